// round 4
// baseline (speedup 1.0000x reference)
#include <cuda_runtime.h>
#include <math.h>

// Problem dims
#define B_ 8
#define N_ 1024
#define H_ 768
#define I_ 3072
#define NMAT 16                    // B * 2 adjacency matrices
#define NN (1024LL*1024LL)

// ---------------- scratch (static device globals; no allocation APIs) --------
__device__ float g_adj[(size_t)NMAT * 1024 * 1024];   // 64 MB normalized adj
__device__ float g_dinv[NMAT * N_];
__device__ float g_t1[(size_t)B_ * N_ * I_];          // 96 MB  [B*N, I]
__device__ float g_t2[(size_t)B_ * N_ * I_];          // 96 MB  [B*N, I]
__device__ float g_h [(size_t)B_ * N_ * H_];          // 24 MB  [B*N, H]
__device__ float g_g1[(size_t)B_ * N_ * H_];
__device__ float g_g2[(size_t)B_ * N_ * H_];
__device__ float g_S [(size_t)B_ * N_ * H_];
__device__ float g_w1c[H_ * H_];
__device__ float g_w2c[H_ * H_];

// ---------------- reductions ------------------------------------------------
__inline__ __device__ float warpReduceSum(float v) {
    #pragma unroll
    for (int o = 16; o > 0; o >>= 1) v += __shfl_xor_sync(0xFFFFFFFFu, v, o);
    return v;
}

// block of 256 threads
__device__ float blockReduceSum(float v, float* sm) {
    __syncthreads();                   // protect sm reuse across calls
    int lane = threadIdx.x & 31, w = threadIdx.x >> 5;
    v = warpReduceSum(v);
    if (lane == 0) sm[w] = v;
    __syncthreads();
    if (w == 0) {
        float t = (lane < 8) ? sm[lane] : 0.0f;
        t = warpReduceSum(t);
        if (lane == 0) sm[0] = t;
    }
    __syncthreads();
    return sm[0];
}

// ---------------- sym_normalize ---------------------------------------------
__global__ void rowsum_dinv_kernel(const float* __restrict__ A) {
    // one block per (matrix,row); 16*1024 blocks
    long long row = blockIdx.x;
    const float* p = A + row * (long long)N_;
    float s = 0.0f;
    for (int c = threadIdx.x * 4; c < N_; c += blockDim.x * 4) {
        float4 v = *(const float4*)(p + c);
        s += v.x + v.y + v.z + v.w;
    }
    __shared__ float sm[32];
    s = blockReduceSum(s, sm);
    if (threadIdx.x == 0) g_dinv[row] = 1.0f / sqrtf(s);
}

__global__ void normalize_adj_kernel(const float* __restrict__ A) {
    long long i4 = (long long)blockIdx.x * blockDim.x + threadIdx.x;
    long long total4 = (long long)NMAT * NN / 4;
    if (i4 >= total4) return;
    long long e = i4 * 4;
    int  m = (int)(e / NN);
    long long rem = e % NN;
    int  r = (int)(rem / N_);
    int  c = (int)(rem % N_);
    float di = g_dinv[m * N_ + r];
    const float* dj = &g_dinv[m * N_ + c];
    float4 v = *(const float4*)(A + e);
    v.x *= di * dj[0];
    v.y *= di * dj[1];
    v.z *= di * dj[2];
    v.w *= di * dj[3];
    *(float4*)(g_adj + e) = v;
}

// ---------------- GEMM (128x128x8 tile, 8x8 per thread, fused epilogues) ----
#define EPI_NONE  0
#define EPI_RELU  1
#define EPI_BIAS  2
#define EPI_GELUB 3
#define EPI_ACC   4

template<int EPI>
__global__ __launch_bounds__(256) void gemm_k(
    const float* __restrict__ A, const float* __restrict__ Bm,
    float* __restrict__ C, const float* __restrict__ bias,
    int M, int N, int K, long long sA, long long sB, long long sC)
{
    const int BM = 128, BN = 128, BK = 8, TM = 8, TN = 8;
    __shared__ float As[BK][BM];
    __shared__ float Bs[BK][BN];

    long long z = blockIdx.z;
    A  += z * sA;
    Bm += z * sB;
    C  += z * sC;

    int tid = threadIdx.x;
    int tr = tid >> 4, tc = tid & 15;       // 16x16 thread grid
    int aRow = tid >> 1, aK = (tid & 1) * 4;
    int bK = tid >> 5,  bCol = (tid & 31) * 4;

    const float* Ap = A + ((long long)blockIdx.y * BM + aRow) * K + aK;
    const float* Bp = Bm + (long long)bK * N + blockIdx.x * BN + bCol;

    float acc[TM][TN];
    #pragma unroll
    for (int i = 0; i < TM; i++)
        #pragma unroll
        for (int j = 0; j < TN; j++) acc[i][j] = 0.0f;

    for (int k0 = 0; k0 < K; k0 += BK) {
        float4 av = *(const float4*)(Ap + k0);
        As[aK + 0][aRow] = av.x;
        As[aK + 1][aRow] = av.y;
        As[aK + 2][aRow] = av.z;
        As[aK + 3][aRow] = av.w;
        *(float4*)&Bs[bK][bCol] = *(const float4*)(Bp + (long long)k0 * N);
        __syncthreads();

        #pragma unroll
        for (int kk = 0; kk < BK; kk++) {
            float ar[TM], br[TN];
            *(float4*)(ar)     = *(const float4*)&As[kk][tr * TM];
            *(float4*)(ar + 4) = *(const float4*)&As[kk][tr * TM + 4];
            *(float4*)(br)     = *(const float4*)&Bs[kk][tc * TN];
            *(float4*)(br + 4) = *(const float4*)&Bs[kk][tc * TN + 4];
            #pragma unroll
            for (int i = 0; i < TM; i++)
                #pragma unroll
                for (int j = 0; j < TN; j++)
                    acc[i][j] = fmaf(ar[i], br[j], acc[i][j]);
        }
        __syncthreads();
    }

    int crow = blockIdx.y * BM + tr * TM;
    int ccol = blockIdx.x * BN + tc * TN;

    float bb[TN];
    if (EPI == EPI_BIAS || EPI == EPI_GELUB) {
        #pragma unroll
        for (int j = 0; j < TN; j++) bb[j] = bias[ccol + j];
    }

    #pragma unroll
    for (int i = 0; i < TM; i++) {
        float* Cr = C + (long long)(crow + i) * N + ccol;
        #pragma unroll
        for (int j0 = 0; j0 < TN; j0 += 4) {
            float t[4];
            #pragma unroll
            for (int u = 0; u < 4; u++) {
                float x = acc[i][j0 + u];
                if (EPI == EPI_RELU)  x = fmaxf(x, 0.0f);
                else if (EPI == EPI_BIAS)  x += bb[j0 + u];
                else if (EPI == EPI_GELUB) {
                    x += bb[j0 + u];
                    x = 0.5f * x * (1.0f + erff(x * 0.70710678118654752f));
                }
                t[u] = x;
            }
            if (EPI == EPI_ACC) {
                float4 o = *(const float4*)(Cr + j0);
                t[0] += o.x; t[1] += o.y; t[2] += o.z; t[3] += o.w;
            }
            float4 v = make_float4(t[0], t[1], t[2], t[3]);
            *(float4*)(Cr + j0) = v;
        }
    }
}

// ---------------- layernorm(nodes + h) --------------------------------------
__global__ void ln_kernel(const float* __restrict__ nodes, const float* __restrict__ h,
                          const float* __restrict__ g, const float* __restrict__ b,
                          float* __restrict__ out)
{
    long long row = blockIdx.x;           // B*N blocks, 256 threads, H=768=3*256
    const float* np = nodes + row * H_;
    const float* hp = h + row * H_;
    float* op = out + row * H_;
    int t = threadIdx.x;

    float x[3];
    float s = 0.0f;
    #pragma unroll
    for (int i = 0; i < 3; i++) {
        int c = t + i * 256;
        x[i] = np[c] + hp[c];
        s += x[i];
    }
    __shared__ float sm[32];
    s = blockReduceSum(s, sm);
    float mu = s * (1.0f / H_);
    float v = 0.0f;
    #pragma unroll
    for (int i = 0; i < 3; i++) {
        float d = x[i] - mu;
        v += d * d;
    }
    v = blockReduceSum(v, sm);
    float rs = rsqrtf(v * (1.0f / H_) + 1e-12f);
    #pragma unroll
    for (int i = 0; i < 3; i++) {
        int c = t + i * 256;
        op[c] = (x[i] - mu) * rs * g[c] + b[c];
    }
}

// ---------------- gate weight folding ---------------------------------------
__global__ void combine_w_kernel(const float* __restrict__ gw) {
    int i = blockIdx.x * blockDim.x + threadIdx.x;   // over H*H
    if (i >= H_ * H_) return;
    int r = i / H_, c = i % H_;
    float w0 = gw[i];                                 // rows [0,H)
    float w1 = gw[(H_     + r) * H_ + c];             // rows [H,2H)
    float w2 = gw[(2 * H_ + r) * H_ + c];             // rows [2H,3H)
    float w3 = gw[(3 * H_ + r) * H_ + c];             // rows [3H,4H)
    g_w1c[i] = w0 + w2 + w3;
    g_w2c[i] = w1 + w2 - w3;
}

// ---------------- final gated blend -----------------------------------------
__global__ void gate_blend_kernel(const float* __restrict__ S, const float* __restrict__ gb,
                                  const float* __restrict__ g1, const float* __restrict__ g2,
                                  float* __restrict__ out, long long total)
{
    long long i = (long long)blockIdx.x * blockDim.x + threadIdx.x;
    if (i >= total) return;
    int c = (int)(i % H_);
    float s = S[i] + gb[c];
    float gate = 1.0f / (1.0f + expf(-s));
    out[i] = gate * g1[i] + (1.0f - gate) * g2[i];
}

// ---------------- launcher ---------------------------------------------------
extern "C" void kernel_launch(void* const* d_in, const int* in_sizes, int n_in,
                              void* d_out, int out_size)
{
    (void)in_sizes; (void)n_in; (void)out_size;
    const float* nodes   = (const float*)d_in[0];
    const float* graphs  = (const float*)d_in[1];
    const float* gcn1_w1 = (const float*)d_in[2];
    const float* gcn1_w2 = (const float*)d_in[3];
    const float* gcn2_w1 = (const float*)d_in[4];
    const float* gcn2_w2 = (const float*)d_in[5];
    const float* exp1_w  = (const float*)d_in[6];
    const float* exp1_b  = (const float*)d_in[7];
    const float* col1_w  = (const float*)d_in[8];
    const float* col1_b  = (const float*)d_in[9];
    const float* exp2_w  = (const float*)d_in[10];
    const float* exp2_b  = (const float*)d_in[11];
    const float* col2_w  = (const float*)d_in[12];
    const float* col2_b  = (const float*)d_in[13];
    const float* gate_w  = (const float*)d_in[14];
    const float* gate_b  = (const float*)d_in[15];
    const float* ln1_g   = (const float*)d_in[16];
    const float* ln1_b   = (const float*)d_in[17];
    const float* ln2_g   = (const float*)d_in[18];
    const float* ln2_b   = (const float*)d_in[19];
    float* out = (float*)d_out;

    float *adj, *t1, *t2, *h, *g1, *g2, *S, *w1c, *w2c;
    cudaGetSymbolAddress((void**)&adj, g_adj);
    cudaGetSymbolAddress((void**)&t1,  g_t1);
    cudaGetSymbolAddress((void**)&t2,  g_t2);
    cudaGetSymbolAddress((void**)&h,   g_h);
    cudaGetSymbolAddress((void**)&g1,  g_g1);
    cudaGetSymbolAddress((void**)&g2,  g_g2);
    cudaGetSymbolAddress((void**)&S,   g_S);
    cudaGetSymbolAddress((void**)&w1c, g_w1c);
    cudaGetSymbolAddress((void**)&w2c, g_w2c);

    const long long MN  = (long long)B_ * N_;   // 8192 rows
    const long long sNI = (long long)N_ * I_;
    const long long sNH = (long long)N_ * H_;

    // 1) normalize both adjacency stacks (16 matrices)
    rowsum_dinv_kernel<<<NMAT * N_, 256>>>(graphs);
    long long total4 = (long long)NMAT * NN / 4;
    normalize_adj_kernel<<<(unsigned)((total4 + 255) / 256), 256>>>(graphs);

    // ---- GCN 1 (adj index 0 within each batch pair; stride 2*NN) ----
    gemm_k<EPI_NONE><<<dim3(I_ / 128, MN / 128, 1), 256>>>(nodes, gcn1_w1, t1, nullptr, (int)MN, I_, H_, 0, 0, 0);
    gemm_k<EPI_RELU><<<dim3(I_ / 128, N_ / 128, B_), 256>>>(adj, t1, t2, nullptr, N_, I_, N_, 2 * NN, sNI, sNI);
    gemm_k<EPI_NONE><<<dim3(H_ / 128, MN / 128, 1), 256>>>(t2, gcn1_w2, h, nullptr, (int)MN, H_, I_, 0, 0, 0);
    gemm_k<EPI_RELU><<<dim3(H_ / 128, N_ / 128, B_), 256>>>(adj, h, g1, nullptr, N_, H_, N_, 2 * NN, sNH, sNH);
    // ---- FFN 1 + LN 1 ----
    gemm_k<EPI_GELUB><<<dim3(I_ / 128, MN / 128, 1), 256>>>(g1, exp1_w, t1, exp1_b, (int)MN, I_, H_, 0, 0, 0);
    gemm_k<EPI_BIAS><<<dim3(H_ / 128, MN / 128, 1), 256>>>(t1, col1_w, h, col1_b, (int)MN, H_, I_, 0, 0, 0);
    ln_kernel<<<(unsigned)MN, 256>>>(nodes, h, ln1_g, ln1_b, g1);

    // ---- GCN 2 (adj offset NN) ----
    gemm_k<EPI_NONE><<<dim3(I_ / 128, MN / 128, 1), 256>>>(nodes, gcn2_w1, t1, nullptr, (int)MN, I_, H_, 0, 0, 0);
    gemm_k<EPI_RELU><<<dim3(I_ / 128, N_ / 128, B_), 256>>>(adj + NN, t1, t2, nullptr, N_, I_, N_, 2 * NN, sNI, sNI);
    gemm_k<EPI_NONE><<<dim3(H_ / 128, MN / 128, 1), 256>>>(t2, gcn2_w2, h, nullptr, (int)MN, H_, I_, 0, 0, 0);
    gemm_k<EPI_RELU><<<dim3(H_ / 128, N_ / 128, B_), 256>>>(adj + NN, h, g2, nullptr, N_, H_, N_, 2 * NN, sNH, sNH);
    // ---- FFN 2 + LN 2 ----
    gemm_k<EPI_GELUB><<<dim3(I_ / 128, MN / 128, 1), 256>>>(g2, exp2_w, t1, exp2_b, (int)MN, I_, H_, 0, 0, 0);
    gemm_k<EPI_BIAS><<<dim3(H_ / 128, MN / 128, 1), 256>>>(t1, col2_w, h, col2_b, (int)MN, H_, I_, 0, 0, 0);
    ln_kernel<<<(unsigned)MN, 256>>>(nodes, h, ln2_g, ln2_b, g2);

    // ---- folded gate: sigmoid(g1@W1c + g2@W2c + b) ----
    combine_w_kernel<<<(H_ * H_ + 255) / 256, 256>>>(gate_w);
    gemm_k<EPI_NONE><<<dim3(H_ / 128, MN / 128, 1), 256>>>(g1, w1c, S, nullptr, (int)MN, H_, H_, 0, 0, 0);
    gemm_k<EPI_ACC><<<dim3(H_ / 128, MN / 128, 1), 256>>>(g2, w2c, S, nullptr, (int)MN, H_, H_, 0, 0, 0);

    long long total = MN * H_;
    gate_blend_kernel<<<(unsigned)((total + 255) / 256), 256>>>(S, gate_b, g1, g2, out, total);
}

// round 5
// speedup vs baseline: 3.1588x; 3.1588x over previous
#include <cuda_runtime.h>
#include <math.h>
#include <stdint.h>

// Problem dims
#define B_ 8
#define N_ 1024
#define H_ 768
#define I_ 3072
#define NMAT 16                    // B * 2 adjacency matrices
#define NN (1024LL*1024LL)

// ---------------- scratch (static device globals; no allocation APIs) --------
__device__ float g_adj[(size_t)NMAT * 1024 * 1024];   // 64 MB normalized adj
__device__ float g_dinv[NMAT * N_];
__device__ float g_t1[(size_t)B_ * N_ * I_];          // 96 MB  [B*N, I]
__device__ float g_t2[(size_t)B_ * N_ * I_];          // 96 MB  [B*N, I]
__device__ float g_h [(size_t)B_ * N_ * H_];          // 24 MB  [B*N, H]
__device__ float g_g1[(size_t)B_ * N_ * H_];
__device__ float g_g2[(size_t)B_ * N_ * H_];
__device__ float g_S [(size_t)B_ * N_ * H_];
__device__ float g_w1c[H_ * H_];
__device__ float g_w2c[H_ * H_];

// ---------------- reductions ------------------------------------------------
__inline__ __device__ float warpReduceSum(float v) {
    #pragma unroll
    for (int o = 16; o > 0; o >>= 1) v += __shfl_xor_sync(0xFFFFFFFFu, v, o);
    return v;
}

// block of 256 threads
__device__ float blockReduceSum(float v, float* sm) {
    __syncthreads();                   // protect sm reuse across calls
    int lane = threadIdx.x & 31, w = threadIdx.x >> 5;
    v = warpReduceSum(v);
    if (lane == 0) sm[w] = v;
    __syncthreads();
    if (w == 0) {
        float t = (lane < 8) ? sm[lane] : 0.0f;
        t = warpReduceSum(t);
        if (lane == 0) sm[0] = t;
    }
    __syncthreads();
    return sm[0];
}

// ---------------- sym_normalize ---------------------------------------------
__global__ void rowsum_dinv_kernel(const float* __restrict__ A) {
    long long row = blockIdx.x;
    const float* p = A + row * (long long)N_;
    float s = 0.0f;
    for (int c = threadIdx.x * 4; c < N_; c += blockDim.x * 4) {
        float4 v = *(const float4*)(p + c);
        s += v.x + v.y + v.z + v.w;
    }
    __shared__ float sm[32];
    s = blockReduceSum(s, sm);
    if (threadIdx.x == 0) g_dinv[row] = 1.0f / sqrtf(s);
}

__global__ void normalize_adj_kernel(const float* __restrict__ A) {
    long long i4 = (long long)blockIdx.x * blockDim.x + threadIdx.x;
    long long total4 = (long long)NMAT * NN / 4;
    if (i4 >= total4) return;
    long long e = i4 * 4;
    int  m = (int)(e / NN);
    long long rem = e % NN;
    int  r = (int)(rem / N_);
    int  c = (int)(rem % N_);
    float di = g_dinv[m * N_ + r];
    const float* dj = &g_dinv[m * N_ + c];
    float4 v = *(const float4*)(A + e);
    v.x *= di * dj[0];
    v.y *= di * dj[1];
    v.z *= di * dj[2];
    v.w *= di * dj[3];
    *(float4*)(g_adj + e) = v;
}

// ---------------- TF32 tensor-core GEMM -------------------------------------
// 128x128 CTA tile, BK=16, 8 warps (2x4), each warp 64x32 via m16n8k8 frags.
#define EPI_NONE  0
#define EPI_RELU  1
#define EPI_BIAS  2
#define EPI_GELUB 3
#define EPI_ACC   4

__device__ __forceinline__ float to_tf32(float x) {
    asm("cvt.rna.tf32.f32 %0, %0;" : "+f"(x));
    return x;
}

__device__ __forceinline__ void mma_tf32(float c[4], uint32_t a0, uint32_t a1,
                                         uint32_t a2, uint32_t a3,
                                         uint32_t b0, uint32_t b1) {
    asm volatile(
        "mma.sync.aligned.m16n8k8.row.col.f32.tf32.tf32.f32 "
        "{%0,%1,%2,%3}, {%4,%5,%6,%7}, {%8,%9}, {%0,%1,%2,%3};\n"
        : "+f"(c[0]), "+f"(c[1]), "+f"(c[2]), "+f"(c[3])
        : "r"(a0), "r"(a1), "r"(a2), "r"(a3), "r"(b0), "r"(b1));
}

template<int EPI>
__global__ __launch_bounds__(256) void gemm_tc(
    const float* __restrict__ A, const float* __restrict__ Bm,
    float* __restrict__ C, const float* __restrict__ bias,
    int M, int N, int K, long long sA, long long sB, long long sC)
{
    // A tile: m-major [128][16], padded to 20 floats (80B rows -> ldmatrix conflict-free)
    // B tile: k-major [16][128], padded to 136 floats (frag LDS banks = 8*tg+g, conflict-free)
    __shared__ __align__(16) float As[2][128][20];
    __shared__ __align__(16) float Bs[2][16][136];

    long long z = blockIdx.z;
    A  += z * sA;
    Bm += z * sB;
    C  += z * sC;

    const int tid  = threadIdx.x;
    const int w    = tid >> 5;
    const int lane = tid & 31;
    const int wm   = w & 1;          // 2 m-chunks of 64
    const int wn   = w >> 1;         // 4 n-chunks of 32
    const int g    = lane >> 2;      // groupID
    const int tg   = lane & 3;       // thread-in-group

    // global load assignments
    const int aRow = tid >> 1;
    const int aK   = (tid & 1) * 8;
    const int bK   = tid >> 4;
    const int bN   = (tid & 15) * 4;

    const float* Ap = A  + ((long long)blockIdx.y * 128 + aRow) * K + aK;
    const float* Bp = Bm + (long long)bK * N + blockIdx.x * 128 + bN;

    float c[4][4][4];
    #pragma unroll
    for (int mi = 0; mi < 4; mi++)
        #pragma unroll
        for (int ni = 0; ni < 4; ni++)
            #pragma unroll
            for (int u = 0; u < 4; u++) c[mi][ni][u] = 0.0f;

    const int S = K / 16;

    // ldmatrix per-lane addressing components (within a k8 step)
    const int lm_row = lane & 15;               // 16 rows of the m16 frag
    const int lm_koff = ((lane >> 4) & 1) * 4;  // k chunk 0-3 or 4-7

    // ---- preload stage 0 ----
    float4 av0 = *(const float4*)(Ap);
    float4 av1 = *(const float4*)(Ap + 4);
    float4 bv0 = *(const float4*)(Bp);
    float4 bv1 = *(const float4*)(Bp + 64);
    {
        float* as = &As[0][aRow][aK];
        as[0] = to_tf32(av0.x); as[1] = to_tf32(av0.y);
        as[2] = to_tf32(av0.z); as[3] = to_tf32(av0.w);
        as[4] = to_tf32(av1.x); as[5] = to_tf32(av1.y);
        as[6] = to_tf32(av1.z); as[7] = to_tf32(av1.w);
        float* bs = &Bs[0][bK][bN];
        bs[0] = to_tf32(bv0.x); bs[1] = to_tf32(bv0.y);
        bs[2] = to_tf32(bv0.z); bs[3] = to_tf32(bv0.w);
        bs[64] = to_tf32(bv1.x); bs[65] = to_tf32(bv1.y);
        bs[66] = to_tf32(bv1.z); bs[67] = to_tf32(bv1.w);
    }
    __syncthreads();

    for (int s = 0; s < S; s++) {
        const int buf = s & 1;
        // prefetch next stage into registers
        if (s + 1 < S) {
            const float* Ap2 = Ap + (s + 1) * 16;
            const float* Bp2 = Bp + (long long)(s + 1) * 16 * N;
            av0 = *(const float4*)(Ap2);
            av1 = *(const float4*)(Ap2 + 4);
            bv0 = *(const float4*)(Bp2);
            bv1 = *(const float4*)(Bp2 + 64);
        }

        // compute on current buffer
        #pragma unroll
        for (int kk = 0; kk < 2; kk++) {
            uint32_t a[4][4];
            uint32_t b[4][2];
            const int koff = kk * 8 + lm_koff;
            #pragma unroll
            for (int mi = 0; mi < 4; mi++) {
                unsigned addr = (unsigned)__cvta_generic_to_shared(
                    &As[buf][wm * 64 + mi * 16 + lm_row][koff]);
                asm volatile(
                    "ldmatrix.sync.aligned.m8n8.x4.shared.b16 {%0,%1,%2,%3}, [%4];"
                    : "=r"(a[mi][0]), "=r"(a[mi][1]), "=r"(a[mi][2]), "=r"(a[mi][3])
                    : "r"(addr));
            }
            #pragma unroll
            for (int ni = 0; ni < 4; ni++) {
                const int nb = wn * 32 + ni * 8 + g;
                b[ni][0] = __float_as_uint(Bs[buf][kk * 8 + tg    ][nb]);
                b[ni][1] = __float_as_uint(Bs[buf][kk * 8 + tg + 4][nb]);
            }
            #pragma unroll
            for (int mi = 0; mi < 4; mi++)
                #pragma unroll
                for (int ni = 0; ni < 4; ni++)
                    mma_tf32(c[mi][ni], a[mi][0], a[mi][1], a[mi][2], a[mi][3],
                             b[ni][0], b[ni][1]);
        }

        // stage next buffer
        if (s + 1 < S) {
            const int nb = buf ^ 1;
            float* as = &As[nb][aRow][aK];
            as[0] = to_tf32(av0.x); as[1] = to_tf32(av0.y);
            as[2] = to_tf32(av0.z); as[3] = to_tf32(av0.w);
            as[4] = to_tf32(av1.x); as[5] = to_tf32(av1.y);
            as[6] = to_tf32(av1.z); as[7] = to_tf32(av1.w);
            float* bs = &Bs[nb][bK][bN];
            bs[0] = to_tf32(bv0.x); bs[1] = to_tf32(bv0.y);
            bs[2] = to_tf32(bv0.z); bs[3] = to_tf32(bv0.w);
            bs[64] = to_tf32(bv1.x); bs[65] = to_tf32(bv1.y);
            bs[66] = to_tf32(bv1.z); bs[67] = to_tf32(bv1.w);
        }
        __syncthreads();
    }

    // ---- epilogue ----
    #pragma unroll
    for (int mi = 0; mi < 4; mi++) {
        #pragma unroll
        for (int ni = 0; ni < 4; ni++) {
            const int row0 = blockIdx.y * 128 + wm * 64 + mi * 16 + g;
            const int col  = blockIdx.x * 128 + wn * 32 + ni * 8 + 2 * tg;
            float v[4];
            v[0] = c[mi][ni][0]; v[1] = c[mi][ni][1];
            v[2] = c[mi][ni][2]; v[3] = c[mi][ni][3];

            if (EPI == EPI_BIAS || EPI == EPI_GELUB) {
                float b0 = bias[col], b1 = bias[col + 1];
                v[0] += b0; v[1] += b1; v[2] += b0; v[3] += b1;
            }
            if (EPI == EPI_RELU) {
                #pragma unroll
                for (int u = 0; u < 4; u++) v[u] = fmaxf(v[u], 0.0f);
            }
            if (EPI == EPI_GELUB) {
                #pragma unroll
                for (int u = 0; u < 4; u++)
                    v[u] = 0.5f * v[u] * (1.0f + erff(v[u] * 0.70710678118654752f));
            }

            float* C0 = C + (long long)row0 * N + col;
            float* C1 = C + (long long)(row0 + 8) * N + col;
            if (EPI == EPI_ACC) {
                float2 o0 = *(const float2*)C0;
                float2 o1 = *(const float2*)C1;
                v[0] += o0.x; v[1] += o0.y; v[2] += o1.x; v[3] += o1.y;
            }
            *(float2*)C0 = make_float2(v[0], v[1]);
            *(float2*)C1 = make_float2(v[2], v[3]);
        }
    }
}

// ---------------- layernorm(nodes + h) --------------------------------------
__global__ void ln_kernel(const float* __restrict__ nodes, const float* __restrict__ h,
                          const float* __restrict__ g, const float* __restrict__ b,
                          float* __restrict__ out)
{
    long long row = blockIdx.x;
    const float* np = nodes + row * H_;
    const float* hp = h + row * H_;
    float* op = out + row * H_;
    int t = threadIdx.x;

    float x[3];
    float s = 0.0f;
    #pragma unroll
    for (int i = 0; i < 3; i++) {
        int c = t + i * 256;
        x[i] = np[c] + hp[c];
        s += x[i];
    }
    __shared__ float sm[32];
    s = blockReduceSum(s, sm);
    float mu = s * (1.0f / H_);
    float v = 0.0f;
    #pragma unroll
    for (int i = 0; i < 3; i++) {
        float d = x[i] - mu;
        v += d * d;
    }
    v = blockReduceSum(v, sm);
    float rs = rsqrtf(v * (1.0f / H_) + 1e-12f);
    #pragma unroll
    for (int i = 0; i < 3; i++) {
        int c = t + i * 256;
        op[c] = (x[i] - mu) * rs * g[c] + b[c];
    }
}

// ---------------- gate weight folding ---------------------------------------
__global__ void combine_w_kernel(const float* __restrict__ gw) {
    int i = blockIdx.x * blockDim.x + threadIdx.x;   // over H*H
    if (i >= H_ * H_) return;
    int r = i / H_, c = i % H_;
    float w0 = gw[i];
    float w1 = gw[(H_     + r) * H_ + c];
    float w2 = gw[(2 * H_ + r) * H_ + c];
    float w3 = gw[(3 * H_ + r) * H_ + c];
    g_w1c[i] = w0 + w2 + w3;
    g_w2c[i] = w1 + w2 - w3;
}

// ---------------- final gated blend -----------------------------------------
__global__ void gate_blend_kernel(const float* __restrict__ S, const float* __restrict__ gb,
                                  const float* __restrict__ g1, const float* __restrict__ g2,
                                  float* __restrict__ out, long long total)
{
    long long i = (long long)blockIdx.x * blockDim.x + threadIdx.x;
    if (i >= total) return;
    int c = (int)(i % H_);
    float s = S[i] + gb[c];
    float gate = 1.0f / (1.0f + expf(-s));
    out[i] = gate * g1[i] + (1.0f - gate) * g2[i];
}

// ---------------- launcher ---------------------------------------------------
extern "C" void kernel_launch(void* const* d_in, const int* in_sizes, int n_in,
                              void* d_out, int out_size)
{
    (void)in_sizes; (void)n_in; (void)out_size;
    const float* nodes   = (const float*)d_in[0];
    const float* graphs  = (const float*)d_in[1];
    const float* gcn1_w1 = (const float*)d_in[2];
    const float* gcn1_w2 = (const float*)d_in[3];
    const float* gcn2_w1 = (const float*)d_in[4];
    const float* gcn2_w2 = (const float*)d_in[5];
    const float* exp1_w  = (const float*)d_in[6];
    const float* exp1_b  = (const float*)d_in[7];
    const float* col1_w  = (const float*)d_in[8];
    const float* col1_b  = (const float*)d_in[9];
    const float* exp2_w  = (const float*)d_in[10];
    const float* exp2_b  = (const float*)d_in[11];
    const float* col2_w  = (const float*)d_in[12];
    const float* col2_b  = (const float*)d_in[13];
    const float* gate_w  = (const float*)d_in[14];
    const float* gate_b  = (const float*)d_in[15];
    const float* ln1_g   = (const float*)d_in[16];
    const float* ln1_b   = (const float*)d_in[17];
    const float* ln2_g   = (const float*)d_in[18];
    const float* ln2_b   = (const float*)d_in[19];
    float* out = (float*)d_out;

    float *adj, *t1, *t2, *h, *g1, *g2, *S, *w1c, *w2c;
    cudaGetSymbolAddress((void**)&adj, g_adj);
    cudaGetSymbolAddress((void**)&t1,  g_t1);
    cudaGetSymbolAddress((void**)&t2,  g_t2);
    cudaGetSymbolAddress((void**)&h,   g_h);
    cudaGetSymbolAddress((void**)&g1,  g_g1);
    cudaGetSymbolAddress((void**)&g2,  g_g2);
    cudaGetSymbolAddress((void**)&S,   g_S);
    cudaGetSymbolAddress((void**)&w1c, g_w1c);
    cudaGetSymbolAddress((void**)&w2c, g_w2c);

    const long long MN  = (long long)B_ * N_;   // 8192 rows
    const long long sNI = (long long)N_ * I_;
    const long long sNH = (long long)N_ * H_;

    // 1) normalize both adjacency stacks (16 matrices)
    rowsum_dinv_kernel<<<NMAT * N_, 256>>>(graphs);
    long long total4 = (long long)NMAT * NN / 4;
    normalize_adj_kernel<<<(unsigned)((total4 + 255) / 256), 256>>>(graphs);

    // ---- GCN 1 ----
    gemm_tc<EPI_NONE><<<dim3(I_ / 128, MN / 128, 1), 256>>>(nodes, gcn1_w1, t1, nullptr, (int)MN, I_, H_, 0, 0, 0);
    gemm_tc<EPI_RELU><<<dim3(I_ / 128, N_ / 128, B_), 256>>>(adj, t1, t2, nullptr, N_, I_, N_, 2 * NN, sNI, sNI);
    gemm_tc<EPI_NONE><<<dim3(H_ / 128, MN / 128, 1), 256>>>(t2, gcn1_w2, h, nullptr, (int)MN, H_, I_, 0, 0, 0);
    gemm_tc<EPI_RELU><<<dim3(H_ / 128, N_ / 128, B_), 256>>>(adj, h, g1, nullptr, N_, H_, N_, 2 * NN, sNH, sNH);
    // ---- FFN 1 + LN 1 ----
    gemm_tc<EPI_GELUB><<<dim3(I_ / 128, MN / 128, 1), 256>>>(g1, exp1_w, t1, exp1_b, (int)MN, I_, H_, 0, 0, 0);
    gemm_tc<EPI_BIAS><<<dim3(H_ / 128, MN / 128, 1), 256>>>(t1, col1_w, h, col1_b, (int)MN, H_, I_, 0, 0, 0);
    ln_kernel<<<(unsigned)MN, 256>>>(nodes, h, ln1_g, ln1_b, g1);

    // ---- GCN 2 ----
    gemm_tc<EPI_NONE><<<dim3(I_ / 128, MN / 128, 1), 256>>>(nodes, gcn2_w1, t1, nullptr, (int)MN, I_, H_, 0, 0, 0);
    gemm_tc<EPI_RELU><<<dim3(I_ / 128, N_ / 128, B_), 256>>>(adj + NN, t1, t2, nullptr, N_, I_, N_, 2 * NN, sNI, sNI);
    gemm_tc<EPI_NONE><<<dim3(H_ / 128, MN / 128, 1), 256>>>(t2, gcn2_w2, h, nullptr, (int)MN, H_, I_, 0, 0, 0);
    gemm_tc<EPI_RELU><<<dim3(H_ / 128, N_ / 128, B_), 256>>>(adj + NN, h, g2, nullptr, N_, H_, N_, 2 * NN, sNH, sNH);
    // ---- FFN 2 + LN 2 ----
    gemm_tc<EPI_GELUB><<<dim3(I_ / 128, MN / 128, 1), 256>>>(g2, exp2_w, t1, exp2_b, (int)MN, I_, H_, 0, 0, 0);
    gemm_tc<EPI_BIAS><<<dim3(H_ / 128, MN / 128, 1), 256>>>(t1, col2_w, h, col2_b, (int)MN, H_, I_, 0, 0, 0);
    ln_kernel<<<(unsigned)MN, 256>>>(nodes, h, ln2_g, ln2_b, g2);

    // ---- folded gate: sigmoid(g1@W1c + g2@W2c + b) ----
    combine_w_kernel<<<(H_ * H_ + 255) / 256, 256>>>(gate_w);
    gemm_tc<EPI_NONE><<<dim3(H_ / 128, MN / 128, 1), 256>>>(g1, w1c, S, nullptr, (int)MN, H_, H_, 0, 0, 0);
    gemm_tc<EPI_ACC><<<dim3(H_ / 128, MN / 128, 1), 256>>>(g2, w2c, S, nullptr, (int)MN, H_, H_, 0, 0, 0);

    long long total = MN * H_;
    gate_blend_kernel<<<(unsigned)((total + 255) / 256), 256>>>(S, gate_b, g1, g2, out, total);
}

// round 7
// speedup vs baseline: 5.9680x; 1.8893x over previous
#include <cuda_runtime.h>
#include <cuda_bf16.h>
#include <math.h>
#include <stdint.h>

// Problem dims
#define B_ 8
#define N_ 1024
#define H_ 768
#define I_ 3072
#define NMAT 16
#define NN (1024LL*1024LL)

typedef __nv_bfloat16 bf16;

// ---------------- scratch (static device globals) ----------------------------
__device__ bf16  g_adj16[(size_t)NMAT * 1024 * 1024];    // normalized adj, bf16
__device__ float g_dinv[NMAT * N_];
__device__ bf16  g_nodes16[(size_t)B_ * N_ * H_];
// bf16 weights
__device__ bf16  g_wA[H_ * I_];   // gcn1_w1
__device__ bf16  g_wB[I_ * H_];   // gcn1_w2
__device__ bf16  g_wC[H_ * I_];   // gcn2_w1
__device__ bf16  g_wD[I_ * H_];   // gcn2_w2
__device__ bf16  g_wE[H_ * I_];   // exp1_w
__device__ bf16  g_wF[I_ * H_];   // col1_w
__device__ bf16  g_wG[H_ * I_];   // exp2_w
__device__ bf16  g_wH[I_ * H_];   // col2_w
__device__ bf16  g_w1c16[H_ * H_];
__device__ bf16  g_w2c16[H_ * H_];
// bf16 activations
__device__ bf16  g_t1_16[(size_t)B_ * N_ * I_];
__device__ bf16  g_t2_16[(size_t)B_ * N_ * I_];
__device__ bf16  g_h16 [(size_t)B_ * N_ * H_];
__device__ bf16  g_gc16[(size_t)B_ * N_ * H_];    // GCN branch output (reused)
__device__ bf16  g_ln1_16[(size_t)B_ * N_ * H_];
__device__ bf16  g_ln2_16[(size_t)B_ * N_ * H_];
// fp32 activations (elementwise-sensitive)
__device__ float g_hf  [(size_t)B_ * N_ * H_];    // pre-LN FFN output
__device__ float g_ln1f[(size_t)B_ * N_ * H_];
__device__ float g_ln2f[(size_t)B_ * N_ * H_];
__device__ float g_S   [(size_t)B_ * N_ * H_];

// ---------------- reductions ------------------------------------------------
__inline__ __device__ float warpReduceSum(float v) {
    #pragma unroll
    for (int o = 16; o > 0; o >>= 1) v += __shfl_xor_sync(0xFFFFFFFFu, v, o);
    return v;
}
__device__ float blockReduceSum(float v, float* sm) {
    __syncthreads();
    int lane = threadIdx.x & 31, w = threadIdx.x >> 5;
    v = warpReduceSum(v);
    if (lane == 0) sm[w] = v;
    __syncthreads();
    if (w == 0) {
        float t = (lane < 8) ? sm[lane] : 0.0f;
        t = warpReduceSum(t);
        if (lane == 0) sm[0] = t;
    }
    __syncthreads();
    return sm[0];
}

// ---------------- fp32 -> bf16 conversions -----------------------------------
__global__ void f2bf_kernel(const float* __restrict__ in, bf16* __restrict__ out, long long n4) {
    long long i = (long long)blockIdx.x * blockDim.x + threadIdx.x;
    if (i >= n4) return;
    float4 v = *(const float4*)(in + i * 4);
    bf16 o[4];
    o[0] = __float2bfloat16_rn(v.x); o[1] = __float2bfloat16_rn(v.y);
    o[2] = __float2bfloat16_rn(v.z); o[3] = __float2bfloat16_rn(v.w);
    *(uint2*)(out + i * 4) = *(uint2*)o;
}

// all 8 H*I weight matrices in one launch: blockIdx.y selects the matrix
__global__ void conv_weights_kernel(
    const float* __restrict__ s0, const float* __restrict__ s1,
    const float* __restrict__ s2, const float* __restrict__ s3,
    const float* __restrict__ s4, const float* __restrict__ s5,
    const float* __restrict__ s6, const float* __restrict__ s7)
{
    const float* srcs[8] = {s0, s1, s2, s3, s4, s5, s6, s7};
    bf16* dsts[8] = {g_wA, g_wB, g_wC, g_wD, g_wE, g_wF, g_wG, g_wH};
    const float* in = srcs[blockIdx.y];
    bf16* out = dsts[blockIdx.y];
    long long i = (long long)blockIdx.x * blockDim.x + threadIdx.x;
    long long n4 = (long long)H_ * I_ / 4;
    if (i >= n4) return;
    float4 v = *(const float4*)(in + i * 4);
    bf16 o[4];
    o[0] = __float2bfloat16_rn(v.x); o[1] = __float2bfloat16_rn(v.y);
    o[2] = __float2bfloat16_rn(v.z); o[3] = __float2bfloat16_rn(v.w);
    *(uint2*)(out + i * 4) = *(uint2*)o;
}

// ---------------- sym_normalize ---------------------------------------------
__global__ void rowsum_dinv_kernel(const float* __restrict__ A) {
    long long row = blockIdx.x;
    const float* p = A + row * (long long)N_;
    float s = 0.0f;
    for (int c = threadIdx.x * 4; c < N_; c += blockDim.x * 4) {
        float4 v = *(const float4*)(p + c);
        s += v.x + v.y + v.z + v.w;
    }
    __shared__ float sm[32];
    s = blockReduceSum(s, sm);
    if (threadIdx.x == 0) g_dinv[row] = 1.0f / sqrtf(s);
}

__global__ void normalize_adj_kernel(const float* __restrict__ A) {
    long long i4 = (long long)blockIdx.x * blockDim.x + threadIdx.x;
    long long total4 = (long long)NMAT * NN / 4;
    if (i4 >= total4) return;
    long long e = i4 * 4;
    int  m = (int)(e / NN);
    long long rem = e % NN;
    int  r = (int)(rem / N_);
    int  c = (int)(rem % N_);
    float di = g_dinv[m * N_ + r];
    const float* dj = &g_dinv[m * N_ + c];
    float4 v = *(const float4*)(A + e);
    bf16 o[4];
    o[0] = __float2bfloat16_rn(v.x * di * dj[0]);
    o[1] = __float2bfloat16_rn(v.y * di * dj[1]);
    o[2] = __float2bfloat16_rn(v.z * di * dj[2]);
    o[3] = __float2bfloat16_rn(v.w * di * dj[3]);
    *(uint2*)(g_adj16 + e) = *(uint2*)o;
}

// ---------------- bf16 tensor-core GEMM --------------------------------------
// 128x128 CTA tile, BK=32, 8 warps (2x4), warp 64x32, mma m16n8k16.
// cp.async double-buffered pipeline.
#define EPI_NONE  0
#define EPI_RELU  1
#define EPI_BIAS  2
#define EPI_GELUB 3
#define EPI_ACC   4

__device__ __forceinline__ void cp16(void* sdst, const void* gsrc) {
    unsigned d = (unsigned)__cvta_generic_to_shared(sdst);
    asm volatile("cp.async.cg.shared.global [%0], [%1], 16;\n" :: "r"(d), "l"(gsrc));
}

__device__ __forceinline__ void mma_bf16(float c[4], const uint32_t a[4],
                                         uint32_t b0, uint32_t b1) {
    asm volatile(
        "mma.sync.aligned.m16n8k16.row.col.f32.bf16.bf16.f32 "
        "{%0,%1,%2,%3}, {%4,%5,%6,%7}, {%8,%9}, {%0,%1,%2,%3};\n"
        : "+f"(c[0]), "+f"(c[1]), "+f"(c[2]), "+f"(c[3])
        : "r"(a[0]), "r"(a[1]), "r"(a[2]), "r"(a[3]), "r"(b0), "r"(b1));
}

// OUTBF: 1 -> C is bf16, 0 -> C is float
template<int EPI, int OUTBF>
__global__ __launch_bounds__(256) void gemm_bf(
    const bf16* __restrict__ A, const bf16* __restrict__ Bm,
    void* __restrict__ Cv, const float* __restrict__ bias,
    int M, int N, int K, long long sA, long long sB, long long sC)
{
    // A tile m-major [128][32] pad->40 bf16 (80B rows, 16B-aligned, conflict-free)
    // B tile k-major [32][128] pad->136 bf16 (272B rows)
    __shared__ __align__(16) bf16 As[2][128][40];
    __shared__ __align__(16) bf16 Bs[2][32][136];

    long long z = blockIdx.z;
    A += z * sA;
    Bm += z * sB;

    const int tid  = threadIdx.x;
    const int w    = tid >> 5;
    const int lane = tid & 31;
    const int wm   = w & 1;
    const int wn   = w >> 1;
    const int g    = lane >> 2;
    const int tg   = lane & 3;

    // cp.async assignments: each thread moves 32B of A and 32B of B per stage
    const int aRow  = tid >> 1;
    const int aKoff = (tid & 1) * 16;           // bf16 units
    const int bRow  = tid >> 3;
    const int bNoff = (tid & 7) * 16;           // bf16 units

    const bf16* Ag = A  + ((long long)blockIdx.y * 128 + aRow) * K + aKoff;
    const bf16* Bg = Bm + (long long)bRow * N + blockIdx.x * 128 + bNoff;

    float c[4][4][4];
    #pragma unroll
    for (int mi = 0; mi < 4; mi++)
        #pragma unroll
        for (int ni = 0; ni < 4; ni++)
            #pragma unroll
            for (int u = 0; u < 4; u++) c[mi][ni][u] = 0.0f;

    const int S = K / 32;

    // ldmatrix lane addressing
    const int lm_r = lane & 15;
    const int lm_c = (lane >> 4) * 8;

    // stage 0
    cp16(&As[0][aRow][aKoff], Ag);
    cp16(&As[0][aRow][aKoff + 8], Ag + 8);
    cp16(&Bs[0][bRow][bNoff], Bg);
    cp16(&Bs[0][bRow][bNoff + 8], Bg + 8);
    asm volatile("cp.async.commit_group;\n");

    for (int s = 0; s < S; s++) {
        const int buf = s & 1;
        if (s + 1 < S) {
            const bf16* Ag2 = Ag + (s + 1) * 32;
            const bf16* Bg2 = Bg + (long long)(s + 1) * 32 * N;
            cp16(&As[buf ^ 1][aRow][aKoff], Ag2);
            cp16(&As[buf ^ 1][aRow][aKoff + 8], Ag2 + 8);
            cp16(&Bs[buf ^ 1][bRow][bNoff], Bg2);
            cp16(&Bs[buf ^ 1][bRow][bNoff + 8], Bg2 + 8);
            asm volatile("cp.async.commit_group;\n");
            asm volatile("cp.async.wait_group 1;\n");
        } else {
            asm volatile("cp.async.wait_group 0;\n");
        }
        __syncthreads();

        #pragma unroll
        for (int kk = 0; kk < 2; kk++) {
            uint32_t a[4][4];
            uint32_t b[2][4];
            #pragma unroll
            for (int mi = 0; mi < 4; mi++) {
                unsigned addr = (unsigned)__cvta_generic_to_shared(
                    &As[buf][wm * 64 + mi * 16 + lm_r][kk * 16 + lm_c]);
                asm volatile(
                    "ldmatrix.sync.aligned.m8n8.x4.shared.b16 {%0,%1,%2,%3}, [%4];"
                    : "=r"(a[mi][0]), "=r"(a[mi][1]), "=r"(a[mi][2]), "=r"(a[mi][3])
                    : "r"(addr));
            }
            #pragma unroll
            for (int nb = 0; nb < 2; nb++) {
                unsigned addr = (unsigned)__cvta_generic_to_shared(
                    &Bs[buf][kk * 16 + lm_r][wn * 32 + nb * 16 + lm_c]);
                asm volatile(
                    "ldmatrix.sync.aligned.m8n8.x4.trans.shared.b16 {%0,%1,%2,%3}, [%4];"
                    : "=r"(b[nb][0]), "=r"(b[nb][1]), "=r"(b[nb][2]), "=r"(b[nb][3])
                    : "r"(addr));
            }
            #pragma unroll
            for (int mi = 0; mi < 4; mi++)
                #pragma unroll
                for (int ni = 0; ni < 4; ni++)
                    mma_bf16(c[mi][ni], a[mi],
                             b[ni >> 1][(ni & 1) * 2], b[ni >> 1][(ni & 1) * 2 + 1]);
        }
        __syncthreads();
    }

    // ---- epilogue ----
    #pragma unroll
    for (int mi = 0; mi < 4; mi++) {
        #pragma unroll
        for (int ni = 0; ni < 4; ni++) {
            const int row0 = blockIdx.y * 128 + wm * 64 + mi * 16 + g;
            const int col  = blockIdx.x * 128 + wn * 32 + ni * 8 + 2 * tg;
            float v[4];
            v[0] = c[mi][ni][0]; v[1] = c[mi][ni][1];
            v[2] = c[mi][ni][2]; v[3] = c[mi][ni][3];

            if (EPI == EPI_BIAS || EPI == EPI_GELUB) {
                float b0 = bias[col], b1 = bias[col + 1];
                v[0] += b0; v[1] += b1; v[2] += b0; v[3] += b1;
            }
            if (EPI == EPI_RELU) {
                #pragma unroll
                for (int u = 0; u < 4; u++) v[u] = fmaxf(v[u], 0.0f);
            }
            if (EPI == EPI_GELUB) {
                #pragma unroll
                for (int u = 0; u < 4; u++)
                    v[u] = 0.5f * v[u] * (1.0f + erff(v[u] * 0.70710678118654752f));
            }

            if (OUTBF) {
                bf16* C = (bf16*)Cv + z * sC;
                bf16* C0 = C + (long long)row0 * N + col;
                bf16* C1 = C + (long long)(row0 + 8) * N + col;
                bf16 p0[2] = {__float2bfloat16_rn(v[0]), __float2bfloat16_rn(v[1])};
                bf16 p1[2] = {__float2bfloat16_rn(v[2]), __float2bfloat16_rn(v[3])};
                *(uint32_t*)C0 = *(uint32_t*)p0;
                *(uint32_t*)C1 = *(uint32_t*)p1;
            } else {
                float* C = (float*)Cv + z * sC;
                float* C0 = C + (long long)row0 * N + col;
                float* C1 = C + (long long)(row0 + 8) * N + col;
                if (EPI == EPI_ACC) {
                    float2 o0 = *(const float2*)C0;
                    float2 o1 = *(const float2*)C1;
                    v[0] += o0.x; v[1] += o0.y; v[2] += o1.x; v[3] += o1.y;
                }
                *(float2*)C0 = make_float2(v[0], v[1]);
                *(float2*)C1 = make_float2(v[2], v[3]);
            }
        }
    }
}

// ---------------- layernorm(nodes + h): fp32 out + bf16 out ------------------
__global__ void ln_kernel(const float* __restrict__ nodes, const float* __restrict__ h,
                          const float* __restrict__ g, const float* __restrict__ b,
                          float* __restrict__ outf, bf16* __restrict__ out16)
{
    long long row = blockIdx.x;
    const float* np = nodes + row * H_;
    const float* hp = h + row * H_;
    float* opf = outf + row * H_;
    bf16* op16 = out16 + row * H_;
    int t = threadIdx.x;

    float x[3];
    float s = 0.0f;
    #pragma unroll
    for (int i = 0; i < 3; i++) {
        int c = t + i * 256;
        x[i] = np[c] + hp[c];
        s += x[i];
    }
    __shared__ float sm[32];
    s = blockReduceSum(s, sm);
    float mu = s * (1.0f / H_);
    float v = 0.0f;
    #pragma unroll
    for (int i = 0; i < 3; i++) {
        float d = x[i] - mu;
        v += d * d;
    }
    v = blockReduceSum(v, sm);
    float rs = rsqrtf(v * (1.0f / H_) + 1e-12f);
    #pragma unroll
    for (int i = 0; i < 3; i++) {
        int c = t + i * 256;
        float o = (x[i] - mu) * rs * g[c] + b[c];
        opf[c] = o;
        op16[c] = __float2bfloat16_rn(o);
    }
}

// ---------------- gate weight folding (writes bf16) ---------------------------
__global__ void combine_w_kernel(const float* __restrict__ gw) {
    int i = blockIdx.x * blockDim.x + threadIdx.x;
    if (i >= H_ * H_) return;
    int r = i / H_, c = i % H_;
    float w0 = gw[i];
    float w1 = gw[(H_     + r) * H_ + c];
    float w2 = gw[(2 * H_ + r) * H_ + c];
    float w3 = gw[(3 * H_ + r) * H_ + c];
    g_w1c16[i] = __float2bfloat16_rn(w0 + w2 + w3);
    g_w2c16[i] = __float2bfloat16_rn(w1 + w2 - w3);
}

// ---------------- final gated blend -----------------------------------------
__global__ void gate_blend_kernel(const float* __restrict__ S, const float* __restrict__ gb,
                                  const float* __restrict__ g1, const float* __restrict__ g2,
                                  float* __restrict__ out, long long total)
{
    long long i = (long long)blockIdx.x * blockDim.x + threadIdx.x;
    if (i >= total) return;
    int c = (int)(i % H_);
    float s = S[i] + gb[c];
    float gate = 1.0f / (1.0f + expf(-s));
    out[i] = gate * g1[i] + (1.0f - gate) * g2[i];
}

// ---------------- launcher ---------------------------------------------------
extern "C" void kernel_launch(void* const* d_in, const int* in_sizes, int n_in,
                              void* d_out, int out_size)
{
    (void)in_sizes; (void)n_in; (void)out_size;
    const float* nodes   = (const float*)d_in[0];
    const float* graphs  = (const float*)d_in[1];
    const float* gcn1_w1 = (const float*)d_in[2];
    const float* gcn1_w2 = (const float*)d_in[3];
    const float* gcn2_w1 = (const float*)d_in[4];
    const float* gcn2_w2 = (const float*)d_in[5];
    const float* exp1_w  = (const float*)d_in[6];
    const float* exp1_b  = (const float*)d_in[7];
    const float* col1_w  = (const float*)d_in[8];
    const float* col1_b  = (const float*)d_in[9];
    const float* exp2_w  = (const float*)d_in[10];
    const float* exp2_b  = (const float*)d_in[11];
    const float* col2_w  = (const float*)d_in[12];
    const float* col2_b  = (const float*)d_in[13];
    const float* gate_w  = (const float*)d_in[14];
    const float* gate_b  = (const float*)d_in[15];
    const float* ln1_g   = (const float*)d_in[16];
    const float* ln1_b   = (const float*)d_in[17];
    const float* ln2_g   = (const float*)d_in[18];
    const float* ln2_b   = (const float*)d_in[19];
    float* out = (float*)d_out;

    bf16 *adj16, *nodes16, *wA, *wB, *wC, *wD, *wE, *wF, *wG, *wH, *w1c16, *w2c16;
    bf16 *t1_16, *t2_16, *h16, *gc16, *ln1_16, *ln2_16;
    float *hf, *ln1f, *ln2f, *S;
    cudaGetSymbolAddress((void**)&adj16,   g_adj16);
    cudaGetSymbolAddress((void**)&nodes16, g_nodes16);
    cudaGetSymbolAddress((void**)&wA, g_wA);  cudaGetSymbolAddress((void**)&wB, g_wB);
    cudaGetSymbolAddress((void**)&wC, g_wC);  cudaGetSymbolAddress((void**)&wD, g_wD);
    cudaGetSymbolAddress((void**)&wE, g_wE);  cudaGetSymbolAddress((void**)&wF, g_wF);
    cudaGetSymbolAddress((void**)&wG, g_wG);  cudaGetSymbolAddress((void**)&wH, g_wH);
    cudaGetSymbolAddress((void**)&w1c16, g_w1c16);
    cudaGetSymbolAddress((void**)&w2c16, g_w2c16);
    cudaGetSymbolAddress((void**)&t1_16, g_t1_16);
    cudaGetSymbolAddress((void**)&t2_16, g_t2_16);
    cudaGetSymbolAddress((void**)&h16,   g_h16);
    cudaGetSymbolAddress((void**)&gc16,  g_gc16);
    cudaGetSymbolAddress((void**)&ln1_16, g_ln1_16);
    cudaGetSymbolAddress((void**)&ln2_16, g_ln2_16);
    cudaGetSymbolAddress((void**)&hf,   g_hf);
    cudaGetSymbolAddress((void**)&ln1f, g_ln1f);
    cudaGetSymbolAddress((void**)&ln2f, g_ln2f);
    cudaGetSymbolAddress((void**)&S,    g_S);

    const long long MN  = (long long)B_ * N_;   // 8192
    const long long sNI = (long long)N_ * I_;
    const long long sNH = (long long)N_ * H_;
    const long long HI  = (long long)H_ * I_;

    // ---- conversions + adj normalize ----
    {
        long long n4 = MN * H_ / 4;
        f2bf_kernel<<<(unsigned)((n4 + 255) / 256), 256>>>(nodes, nodes16, n4);
    }
    {
        long long n4 = HI / 4;
        dim3 grid((unsigned)((n4 + 255) / 256), 8);
        conv_weights_kernel<<<grid, 256>>>(gcn1_w1, gcn1_w2, gcn2_w1, gcn2_w2,
                                           exp1_w, col1_w, exp2_w, col2_w);
    }
    combine_w_kernel<<<(H_ * H_ + 255) / 256, 256>>>(gate_w);
    rowsum_dinv_kernel<<<NMAT * N_, 256>>>(graphs);
    long long total4 = (long long)NMAT * NN / 4;
    normalize_adj_kernel<<<(unsigned)((total4 + 255) / 256), 256>>>(graphs);

    // ---- GCN 1 ----
    gemm_bf<EPI_NONE, 1><<<dim3(I_ / 128, MN / 128, 1), 256>>>(nodes16, wA, t1_16, nullptr, (int)MN, I_, H_, 0, 0, 0);
    gemm_bf<EPI_RELU, 1><<<dim3(I_ / 128, N_ / 128, B_), 256>>>(adj16, t1_16, t2_16, nullptr, N_, I_, N_, 2 * NN, sNI, sNI);
    gemm_bf<EPI_NONE, 1><<<dim3(H_ / 128, MN / 128, 1), 256>>>(t2_16, wB, h16, nullptr, (int)MN, H_, I_, 0, 0, 0);
    gemm_bf<EPI_RELU, 1><<<dim3(H_ / 128, N_ / 128, B_), 256>>>(adj16, h16, gc16, nullptr, N_, H_, N_, 2 * NN, sNH, sNH);
    // ---- FFN 1 + LN 1 ----
    gemm_bf<EPI_GELUB, 1><<<dim3(I_ / 128, MN / 128, 1), 256>>>(gc16, wE, t1_16, exp1_b, (int)MN, I_, H_, 0, 0, 0);
    gemm_bf<EPI_BIAS, 0><<<dim3(H_ / 128, MN / 128, 1), 256>>>(t1_16, wF, hf, col1_b, (int)MN, H_, I_, 0, 0, 0);
    ln_kernel<<<(unsigned)MN, 256>>>(nodes, hf, ln1_g, ln1_b, ln1f, ln1_16);

    // ---- GCN 2 ----
    gemm_bf<EPI_NONE, 1><<<dim3(I_ / 128, MN / 128, 1), 256>>>(nodes16, wC, t1_16, nullptr, (int)MN, I_, H_, 0, 0, 0);
    gemm_bf<EPI_RELU, 1><<<dim3(I_ / 128, N_ / 128, B_), 256>>>(adj16 + NN, t1_16, t2_16, nullptr, N_, I_, N_, 2 * NN, sNI, sNI);
    gemm_bf<EPI_NONE, 1><<<dim3(H_ / 128, MN / 128, 1), 256>>>(t2_16, wD, h16, nullptr, (int)MN, H_, I_, 0, 0, 0);
    gemm_bf<EPI_RELU, 1><<<dim3(H_ / 128, N_ / 128, B_), 256>>>(adj16 + NN, h16, gc16, nullptr, N_, H_, N_, 2 * NN, sNH, sNH);
    // ---- FFN 2 + LN 2 ----
    gemm_bf<EPI_GELUB, 1><<<dim3(I_ / 128, MN / 128, 1), 256>>>(gc16, wG, t1_16, exp2_b, (int)MN, I_, H_, 0, 0, 0);
    gemm_bf<EPI_BIAS, 0><<<dim3(H_ / 128, MN / 128, 1), 256>>>(t1_16, wH, hf, col2_b, (int)MN, H_, I_, 0, 0, 0);
    ln_kernel<<<(unsigned)MN, 256>>>(nodes, hf, ln2_g, ln2_b, ln2f, ln2_16);

    // ---- folded gate: sigmoid(g1@W1c + g2@W2c + b) ----
    gemm_bf<EPI_NONE, 0><<<dim3(H_ / 128, MN / 128, 1), 256>>>(ln1_16, w1c16, S, nullptr, (int)MN, H_, H_, 0, 0, 0);
    gemm_bf<EPI_ACC, 0><<<dim3(H_ / 128, MN / 128, 1), 256>>>(ln2_16, w2c16, S, nullptr, (int)MN, H_, H_, 0, 0, 0);

    long long total = MN * H_;
    gate_blend_kernel<<<(unsigned)((total + 255) / 256), 256>>>(S, gate_b, ln1f, ln2f, out, total);
}

// round 9
// speedup vs baseline: 6.2291x; 1.0438x over previous
#include <cuda_runtime.h>
#include <cuda_bf16.h>
#include <math.h>
#include <stdint.h>

// Problem dims
#define B_ 8
#define N_ 1024
#define H_ 768
#define I_ 3072
#define NMAT 16
#define NN (1024LL*1024LL)

typedef __nv_bfloat16 bf16;

// ---------------- scratch (static device globals) ----------------------------
__device__ bf16  g_adj16[(size_t)NMAT * 1024 * 1024];
__device__ float g_dinv[NMAT * N_];
__device__ bf16  g_nodes16[(size_t)B_ * N_ * H_];
// bf16 weights (k-major [K][N], natural layout)
__device__ bf16  g_wA[H_ * I_];
__device__ bf16  g_wB[I_ * H_];
__device__ bf16  g_wC[H_ * I_];
__device__ bf16  g_wD[I_ * H_];
__device__ bf16  g_wE[H_ * I_];
__device__ bf16  g_wF[I_ * H_];
__device__ bf16  g_wG[H_ * I_];
__device__ bf16  g_wH[I_ * H_];
__device__ bf16  g_wGate[2 * H_ * H_];            // [1536][768] folded gate weight
// bf16 activations
__device__ bf16  g_t1_16[(size_t)B_ * N_ * I_];
__device__ bf16  g_t2_16[(size_t)B_ * N_ * I_];
__device__ bf16  g_h16 [(size_t)B_ * N_ * H_];
__device__ bf16  g_gc16[(size_t)B_ * N_ * H_];
__device__ bf16  g_cat16[(size_t)B_ * N_ * 2 * H_]; // [8192][1536] = [ln1 | ln2]
// fp32 activations (elementwise-sensitive)
__device__ float g_hf  [(size_t)B_ * N_ * H_];
__device__ float g_ln1f[(size_t)B_ * N_ * H_];
__device__ float g_ln2f[(size_t)B_ * N_ * H_];

// ---------------- reductions ------------------------------------------------
__inline__ __device__ float warpReduceSum(float v) {
    #pragma unroll
    for (int o = 16; o > 0; o >>= 1) v += __shfl_xor_sync(0xFFFFFFFFu, v, o);
    return v;
}
__device__ float blockReduceSum(float v, float* sm) {
    __syncthreads();
    int lane = threadIdx.x & 31, w = threadIdx.x >> 5;
    v = warpReduceSum(v);
    if (lane == 0) sm[w] = v;
    __syncthreads();
    if (w == 0) {
        float t = (lane < 8) ? sm[lane] : 0.0f;
        t = warpReduceSum(t);
        if (lane == 0) sm[0] = t;
    }
    __syncthreads();
    return sm[0];
}

// ---------------- fp32 -> bf16 conversions -----------------------------------
__global__ void f2bf_kernel(const float* __restrict__ in, bf16* __restrict__ out, long long n4) {
    long long i = (long long)blockIdx.x * blockDim.x + threadIdx.x;
    if (i >= n4) return;
    float4 v = *(const float4*)(in + i * 4);
    bf16 o[4];
    o[0] = __float2bfloat16_rn(v.x); o[1] = __float2bfloat16_rn(v.y);
    o[2] = __float2bfloat16_rn(v.z); o[3] = __float2bfloat16_rn(v.w);
    *(uint2*)(out + i * 4) = *(uint2*)o;
}

__global__ void conv_weights_kernel(
    const float* __restrict__ s0, const float* __restrict__ s1,
    const float* __restrict__ s2, const float* __restrict__ s3,
    const float* __restrict__ s4, const float* __restrict__ s5,
    const float* __restrict__ s6, const float* __restrict__ s7)
{
    const float* srcs[8] = {s0, s1, s2, s3, s4, s5, s6, s7};
    bf16* dsts[8] = {g_wA, g_wB, g_wC, g_wD, g_wE, g_wF, g_wG, g_wH};
    const float* in = srcs[blockIdx.y];
    bf16* out = dsts[blockIdx.y];
    long long i = (long long)blockIdx.x * blockDim.x + threadIdx.x;
    long long n4 = (long long)H_ * I_ / 4;
    if (i >= n4) return;
    float4 v = *(const float4*)(in + i * 4);
    bf16 o[4];
    o[0] = __float2bfloat16_rn(v.x); o[1] = __float2bfloat16_rn(v.y);
    o[2] = __float2bfloat16_rn(v.z); o[3] = __float2bfloat16_rn(v.w);
    *(uint2*)(out + i * 4) = *(uint2*)o;
}

// ---------------- sym_normalize ---------------------------------------------
__global__ void rowsum_dinv_kernel(const float* __restrict__ A) {
    long long row = blockIdx.x;
    const float* p = A + row * (long long)N_;
    float s = 0.0f;
    for (int c = threadIdx.x * 4; c < N_; c += blockDim.x * 4) {
        float4 v = *(const float4*)(p + c);
        s += v.x + v.y + v.z + v.w;
    }
    __shared__ float sm[32];
    s = blockReduceSum(s, sm);
    if (threadIdx.x == 0) g_dinv[row] = 1.0f / sqrtf(s);
}

__global__ void normalize_adj_kernel(const float* __restrict__ A) {
    long long i4 = (long long)blockIdx.x * blockDim.x + threadIdx.x;
    long long total4 = (long long)NMAT * NN / 4;
    if (i4 >= total4) return;
    long long e = i4 * 4;
    int  m = (int)(e / NN);
    long long rem = e % NN;
    int  r = (int)(rem / N_);
    int  c = (int)(rem % N_);
    float di = g_dinv[m * N_ + r];
    const float* dj = &g_dinv[m * N_ + c];
    float4 v = *(const float4*)(A + e);
    bf16 o[4];
    o[0] = __float2bfloat16_rn(v.x * di * dj[0]);
    o[1] = __float2bfloat16_rn(v.y * di * dj[1]);
    o[2] = __float2bfloat16_rn(v.z * di * dj[2]);
    o[3] = __float2bfloat16_rn(v.w * di * dj[3]);
    *(uint2*)(g_adj16 + e) = *(uint2*)o;
}

// folded gate weight, k-major [1536][768]: rows [0,768)=W1c, [768,1536)=W2c
__global__ void combine_w_kernel(const float* __restrict__ gw) {
    int i = blockIdx.x * blockDim.x + threadIdx.x;
    if (i >= H_ * H_) return;
    int r = i / H_, c = i % H_;
    float w0 = gw[i];
    float w1 = gw[(H_     + r) * H_ + c];
    float w2 = gw[(2 * H_ + r) * H_ + c];
    float w3 = gw[(3 * H_ + r) * H_ + c];
    g_wGate[r * H_ + c]          = __float2bfloat16_rn(w0 + w2 + w3);
    g_wGate[(H_ + r) * H_ + c]   = __float2bfloat16_rn(w1 + w2 - w3);
}

// ---------------- bf16 tensor-core GEMM (mma.sync m16n8k16) -------------------
// 128x128 CTA tile, BK=32, 8 warps (2x4), warp 64x32.
// 4-stage cp.async pipeline, ONE __syncthreads per iteration.
#define EPI_NONE  0
#define EPI_RELU  1
#define EPI_BIAS  2
#define EPI_GELUB 3
#define EPI_GATE  5

// dynamic smem layout (bf16 units):
//   As(st): base st*5120,         [128][40]
//   Bs(st): base 20480 + st*4352, [32][136]
#define SMEM_GEMM_BYTES ((4 * (128 * 40 + 32 * 136)) * 2)   // 75776

__device__ __forceinline__ void cp16(uint32_t sdst, const void* gsrc) {
    asm volatile("cp.async.cg.shared.global [%0], [%1], 16;\n" :: "r"(sdst), "l"(gsrc));
}

__device__ __forceinline__ void mma_bf16(float c[4], const uint32_t a[4],
                                         uint32_t b0, uint32_t b1) {
    asm volatile(
        "mma.sync.aligned.m16n8k16.row.col.f32.bf16.bf16.f32 "
        "{%0,%1,%2,%3}, {%4,%5,%6,%7}, {%8,%9}, {%0,%1,%2,%3};\n"
        : "+f"(c[0]), "+f"(c[1]), "+f"(c[2]), "+f"(c[3])
        : "r"(a[0]), "r"(a[1]), "r"(a[2]), "r"(a[3]), "r"(b0), "r"(b1));
}

// OUTBF: 1 -> C is bf16, 0 -> C is float
template<int EPI, int OUTBF>
__global__ __launch_bounds__(256, 2) void gemm_bf(
    const bf16* __restrict__ A, const bf16* __restrict__ Bm,
    void* __restrict__ Cv, const float* __restrict__ bias,
    const float* __restrict__ e1, const float* __restrict__ e2,
    int N, int K, long long sA, long long sB, long long sC)
{
    extern __shared__ __align__(16) bf16 sm[];
    const uint32_t sbase = (uint32_t)__cvta_generic_to_shared(sm);

    long long z = blockIdx.z;
    A  += z * sA;
    Bm += z * sB;

    const int tid  = threadIdx.x;
    const int w    = tid >> 5;
    const int lane = tid & 31;
    const int wm   = w & 1;
    const int wn   = w >> 1;
    const int g    = lane >> 2;
    const int tg   = lane & 3;

    // cp.async assignments
    const int aRow  = tid >> 1;
    const int aKoff = (tid & 1) * 16;
    const int bRow  = tid >> 3;
    const int bNoff = (tid & 7) * 16;

    const bf16* Ag = A  + ((long long)blockIdx.y * 128 + aRow) * K + aKoff;
    const bf16* Bg = Bm + (long long)bRow * N + blockIdx.x * 128 + bNoff;

    float c[4][4][4];
    #pragma unroll
    for (int mi = 0; mi < 4; mi++)
        #pragma unroll
        for (int ni = 0; ni < 4; ni++)
            #pragma unroll
            for (int u = 0; u < 4; u++) c[mi][ni][u] = 0.0f;

    const int S = K / 32;

    const int lm_r = lane & 15;
    const int lm_c = (lane >> 4) * 8;

    // stage issue: chunk -> buffer st
    auto stage = [&](int chunk, int st) {
        const bf16* Ap = Ag + chunk * 32;
        const bf16* Bp = Bg + (long long)chunk * 32 * N;
        uint32_t asb = sbase + (st * 5120 + aRow * 40 + aKoff) * 2;
        uint32_t bsb = sbase + (20480 + st * 4352 + bRow * 136 + bNoff) * 2;
        cp16(asb, Ap);
        cp16(asb + 16, Ap + 8);
        cp16(bsb, Bp);
        cp16(bsb + 16, Bp + 8);
        asm volatile("cp.async.commit_group;\n");
    };

    stage(0, 0);
    stage(1, 1);
    stage(2, 2);

    for (int s = 0; s < S; s++) {
        if (s <= S - 3)      asm volatile("cp.async.wait_group 2;\n");
        else if (s == S - 2) asm volatile("cp.async.wait_group 1;\n");
        else                 asm volatile("cp.async.wait_group 0;\n");
        __syncthreads();
        if (s + 3 < S) stage(s + 3, (s + 3) & 3);

        const int buf = s & 3;
        const uint32_t asBase = sbase + (buf * 5120) * 2;
        const uint32_t bsBase = sbase + (20480 + buf * 4352) * 2;

        #pragma unroll
        for (int kk = 0; kk < 2; kk++) {
            uint32_t a[4][4];
            uint32_t b[2][4];
            #pragma unroll
            for (int mi = 0; mi < 4; mi++) {
                uint32_t addr = asBase +
                    ((wm * 64 + mi * 16 + lm_r) * 40 + kk * 16 + lm_c) * 2;
                asm volatile(
                    "ldmatrix.sync.aligned.m8n8.x4.shared.b16 {%0,%1,%2,%3}, [%4];"
                    : "=r"(a[mi][0]), "=r"(a[mi][1]), "=r"(a[mi][2]), "=r"(a[mi][3])
                    : "r"(addr));
            }
            #pragma unroll
            for (int nb = 0; nb < 2; nb++) {
                uint32_t addr = bsBase +
                    ((kk * 16 + lm_r) * 136 + wn * 32 + nb * 16 + lm_c) * 2;
                asm volatile(
                    "ldmatrix.sync.aligned.m8n8.x4.trans.shared.b16 {%0,%1,%2,%3}, [%4];"
                    : "=r"(b[nb][0]), "=r"(b[nb][1]), "=r"(b[nb][2]), "=r"(b[nb][3])
                    : "r"(addr));
            }
            #pragma unroll
            for (int mi = 0; mi < 4; mi++)
                #pragma unroll
                for (int ni = 0; ni < 4; ni++)
                    mma_bf16(c[mi][ni], a[mi],
                             b[ni >> 1][(ni & 1) * 2], b[ni >> 1][(ni & 1) * 2 + 1]);
        }
    }

    // ---- epilogue ----
    #pragma unroll
    for (int mi = 0; mi < 4; mi++) {
        #pragma unroll
        for (int ni = 0; ni < 4; ni++) {
            const int row0 = blockIdx.y * 128 + wm * 64 + mi * 16 + g;
            const int col  = blockIdx.x * 128 + wn * 32 + ni * 8 + 2 * tg;
            float v[4];
            v[0] = c[mi][ni][0]; v[1] = c[mi][ni][1];
            v[2] = c[mi][ni][2]; v[3] = c[mi][ni][3];

            if (EPI == EPI_BIAS || EPI == EPI_GELUB || EPI == EPI_GATE) {
                float b0 = bias[col], b1 = bias[col + 1];
                v[0] += b0; v[1] += b1; v[2] += b0; v[3] += b1;
            }
            if (EPI == EPI_RELU) {
                #pragma unroll
                for (int u = 0; u < 4; u++) v[u] = fmaxf(v[u], 0.0f);
            }
            if (EPI == EPI_GELUB) {
                #pragma unroll
                for (int u = 0; u < 4; u++)
                    v[u] = 0.5f * v[u] * (1.0f + erff(v[u] * 0.70710678118654752f));
            }
            if (EPI == EPI_GATE) {
                // v = gate score; out = sigmoid(v)*e1 + (1-sigmoid(v))*e2
                long long i0 = (long long)row0 * N + col;
                long long i1 = (long long)(row0 + 8) * N + col;
                float2 p0 = *(const float2*)(e1 + i0);
                float2 p1 = *(const float2*)(e1 + i1);
                float2 q0 = *(const float2*)(e2 + i0);
                float2 q1 = *(const float2*)(e2 + i1);
                float gt;
                gt = 1.0f / (1.0f + expf(-v[0])); v[0] = gt * p0.x + (1.0f - gt) * q0.x;
                gt = 1.0f / (1.0f + expf(-v[1])); v[1] = gt * p0.y + (1.0f - gt) * q0.y;
                gt = 1.0f / (1.0f + expf(-v[2])); v[2] = gt * p1.x + (1.0f - gt) * q1.x;
                gt = 1.0f / (1.0f + expf(-v[3])); v[3] = gt * p1.y + (1.0f - gt) * q1.y;
            }

            if (OUTBF) {
                bf16* C = (bf16*)Cv + z * sC;
                bf16* C0 = C + (long long)row0 * N + col;
                bf16* C1 = C + (long long)(row0 + 8) * N + col;
                bf16 p0[2] = {__float2bfloat16_rn(v[0]), __float2bfloat16_rn(v[1])};
                bf16 p1[2] = {__float2bfloat16_rn(v[2]), __float2bfloat16_rn(v[3])};
                *(uint32_t*)C0 = *(uint32_t*)p0;
                *(uint32_t*)C1 = *(uint32_t*)p1;
            } else {
                float* C = (float*)Cv + z * sC;
                float* C0 = C + (long long)row0 * N + col;
                float* C1 = C + (long long)(row0 + 8) * N + col;
                *(float2*)C0 = make_float2(v[0], v[1]);
                *(float2*)C1 = make_float2(v[2], v[3]);
            }
        }
    }
}

// ---------------- layernorm(nodes + h): fp32 out + bf16 into concat ----------
__global__ void ln_kernel(const float* __restrict__ nodes, const float* __restrict__ h,
                          const float* __restrict__ g, const float* __restrict__ b,
                          float* __restrict__ outf, bf16* __restrict__ cat, int catOff)
{
    long long row = blockIdx.x;
    const float* np = nodes + row * H_;
    const float* hp = h + row * H_;
    float* opf = outf + row * H_;
    bf16* op16 = cat + row * (2 * H_) + catOff;
    int t = threadIdx.x;

    float x[3];
    float s = 0.0f;
    #pragma unroll
    for (int i = 0; i < 3; i++) {
        int c = t + i * 256;
        x[i] = np[c] + hp[c];
        s += x[i];
    }
    __shared__ float sm[32];
    s = blockReduceSum(s, sm);
    float mu = s * (1.0f / H_);
    float v = 0.0f;
    #pragma unroll
    for (int i = 0; i < 3; i++) {
        float d = x[i] - mu;
        v += d * d;
    }
    v = blockReduceSum(v, sm);
    float rs = rsqrtf(v * (1.0f / H_) + 1e-12f);
    #pragma unroll
    for (int i = 0; i < 3; i++) {
        int c = t + i * 256;
        float o = (x[i] - mu) * rs * g[c] + b[c];
        opf[c] = o;
        op16[c] = __float2bfloat16_rn(o);
    }
}

// ---------------- launcher ---------------------------------------------------
extern "C" void kernel_launch(void* const* d_in, const int* in_sizes, int n_in,
                              void* d_out, int out_size)
{
    (void)in_sizes; (void)n_in; (void)out_size;
    const float* nodes   = (const float*)d_in[0];
    const float* graphs  = (const float*)d_in[1];
    const float* gcn1_w1 = (const float*)d_in[2];
    const float* gcn1_w2 = (const float*)d_in[3];
    const float* gcn2_w1 = (const float*)d_in[4];
    const float* gcn2_w2 = (const float*)d_in[5];
    const float* exp1_w  = (const float*)d_in[6];
    const float* exp1_b  = (const float*)d_in[7];
    const float* col1_w  = (const float*)d_in[8];
    const float* col1_b  = (const float*)d_in[9];
    const float* exp2_w  = (const float*)d_in[10];
    const float* exp2_b  = (const float*)d_in[11];
    const float* col2_w  = (const float*)d_in[12];
    const float* col2_b  = (const float*)d_in[13];
    const float* gate_w  = (const float*)d_in[14];
    const float* gate_b  = (const float*)d_in[15];
    const float* ln1_g   = (const float*)d_in[16];
    const float* ln1_b   = (const float*)d_in[17];
    const float* ln2_g   = (const float*)d_in[18];
    const float* ln2_b   = (const float*)d_in[19];
    float* out = (float*)d_out;

    bf16 *adj16, *nodes16, *wA, *wB, *wC, *wD, *wE, *wF, *wG, *wH, *wGate;
    bf16 *t1_16, *t2_16, *h16, *gc16, *cat16;
    float *hf, *ln1f, *ln2f;
    cudaGetSymbolAddress((void**)&adj16,   g_adj16);
    cudaGetSymbolAddress((void**)&nodes16, g_nodes16);
    cudaGetSymbolAddress((void**)&wA, g_wA);  cudaGetSymbolAddress((void**)&wB, g_wB);
    cudaGetSymbolAddress((void**)&wC, g_wC);  cudaGetSymbolAddress((void**)&wD, g_wD);
    cudaGetSymbolAddress((void**)&wE, g_wE);  cudaGetSymbolAddress((void**)&wF, g_wF);
    cudaGetSymbolAddress((void**)&wG, g_wG);  cudaGetSymbolAddress((void**)&wH, g_wH);
    cudaGetSymbolAddress((void**)&wGate, g_wGate);
    cudaGetSymbolAddress((void**)&t1_16, g_t1_16);
    cudaGetSymbolAddress((void**)&t2_16, g_t2_16);
    cudaGetSymbolAddress((void**)&h16,   g_h16);
    cudaGetSymbolAddress((void**)&gc16,  g_gc16);
    cudaGetSymbolAddress((void**)&cat16, g_cat16);
    cudaGetSymbolAddress((void**)&hf,   g_hf);
    cudaGetSymbolAddress((void**)&ln1f, g_ln1f);
    cudaGetSymbolAddress((void**)&ln2f, g_ln2f);

    // opt in to 75.8KB dynamic smem for every GEMM instantiation
    const int SMB = SMEM_GEMM_BYTES;
    cudaFuncSetAttribute(gemm_bf<EPI_NONE, 1>, cudaFuncAttributeMaxDynamicSharedMemorySize, SMB);
    cudaFuncSetAttribute(gemm_bf<EPI_RELU, 1>, cudaFuncAttributeMaxDynamicSharedMemorySize, SMB);
    cudaFuncSetAttribute(gemm_bf<EPI_GELUB,1>, cudaFuncAttributeMaxDynamicSharedMemorySize, SMB);
    cudaFuncSetAttribute(gemm_bf<EPI_BIAS, 0>, cudaFuncAttributeMaxDynamicSharedMemorySize, SMB);
    cudaFuncSetAttribute(gemm_bf<EPI_GATE, 0>, cudaFuncAttributeMaxDynamicSharedMemorySize, SMB);

    const long long MN  = (long long)B_ * N_;   // 8192
    const long long sNI = (long long)N_ * I_;
    const long long sNH = (long long)N_ * H_;
    const long long HI  = (long long)H_ * I_;

    // ---- prologue ----
    {
        long long n4 = MN * H_ / 4;
        f2bf_kernel<<<(unsigned)((n4 + 255) / 256), 256>>>(nodes, nodes16, n4);
    }
    {
        long long n4 = HI / 4;
        dim3 grid((unsigned)((n4 + 255) / 256), 8);
        conv_weights_kernel<<<grid, 256>>>(gcn1_w1, gcn1_w2, gcn2_w1, gcn2_w2,
                                           exp1_w, col1_w, exp2_w, col2_w);
    }
    combine_w_kernel<<<(H_ * H_ + 255) / 256, 256>>>(gate_w);
    rowsum_dinv_kernel<<<NMAT * N_, 256>>>(graphs);
    long long total4 = (long long)NMAT * NN / 4;
    normalize_adj_kernel<<<(unsigned)((total4 + 255) / 256), 256>>>(graphs);

    // ---- GCN 1 ----
    gemm_bf<EPI_NONE, 1><<<dim3(I_/128, MN/128, 1), 256, SMB>>>(nodes16, wA, t1_16, nullptr, nullptr, nullptr, I_, H_, 0, 0, 0);
    gemm_bf<EPI_RELU, 1><<<dim3(I_/128, N_/128, B_), 256, SMB>>>(adj16, t1_16, t2_16, nullptr, nullptr, nullptr, I_, N_, 2*NN, sNI, sNI);
    gemm_bf<EPI_NONE, 1><<<dim3(H_/128, MN/128, 1), 256, SMB>>>(t2_16, wB, h16, nullptr, nullptr, nullptr, H_, I_, 0, 0, 0);
    gemm_bf<EPI_RELU, 1><<<dim3(H_/128, N_/128, B_), 256, SMB>>>(adj16, h16, gc16, nullptr, nullptr, nullptr, H_, N_, 2*NN, sNH, sNH);
    // ---- FFN 1 + LN 1 ----
    gemm_bf<EPI_GELUB, 1><<<dim3(I_/128, MN/128, 1), 256, SMB>>>(gc16, wE, t1_16, exp1_b, nullptr, nullptr, I_, H_, 0, 0, 0);
    gemm_bf<EPI_BIAS, 0><<<dim3(H_/128, MN/128, 1), 256, SMB>>>(t1_16, wF, hf, col1_b, nullptr, nullptr, H_, I_, 0, 0, 0);
    ln_kernel<<<(unsigned)MN, 256>>>(nodes, hf, ln1_g, ln1_b, ln1f, cat16, 0);

    // ---- GCN 2 ----
    gemm_bf<EPI_NONE, 1><<<dim3(I_/128, MN/128, 1), 256, SMB>>>(nodes16, wC, t1_16, nullptr, nullptr, nullptr, I_, H_, 0, 0, 0);
    gemm_bf<EPI_RELU, 1><<<dim3(I_/128, N_/128, B_), 256, SMB>>>(adj16 + NN, t1_16, t2_16, nullptr, nullptr, nullptr, I_, N_, 2*NN, sNI, sNI);
    gemm_bf<EPI_NONE, 1><<<dim3(H_/128, MN/128, 1), 256, SMB>>>(t2_16, wD, h16, nullptr, nullptr, nullptr, H_, I_, 0, 0, 0);
    gemm_bf<EPI_RELU, 1><<<dim3(H_/128, N_/128, B_), 256, SMB>>>(adj16 + NN, h16, gc16, nullptr, nullptr, nullptr, H_, N_, 2*NN, sNH, sNH);
    // ---- FFN 2 + LN 2 ----
    gemm_bf<EPI_GELUB, 1><<<dim3(I_/128, MN/128, 1), 256, SMB>>>(gc16, wG, t1_16, exp2_b, nullptr, nullptr, I_, H_, 0, 0, 0);
    gemm_bf<EPI_BIAS, 0><<<dim3(H_/128, MN/128, 1), 256, SMB>>>(t1_16, wH, hf, col2_b, nullptr, nullptr, H_, I_, 0, 0, 0);
    ln_kernel<<<(unsigned)MN, 256>>>(nodes, hf, ln2_g, ln2_b, ln2f, cat16, H_);

    // ---- fused gate: out = sigmoid(cat @ Wgate + gb) blended with ln1f/ln2f ----
    gemm_bf<EPI_GATE, 0><<<dim3(H_/128, MN/128, 1), 256, SMB>>>(cat16, wGate, out, gate_b, ln1f, ln2f, H_, 2 * H_, 0, 0, 0);
}

// round 12
// speedup vs baseline: 7.5958x; 1.2194x over previous
#include <cuda_runtime.h>
#include <cuda_bf16.h>
#include <math.h>
#include <stdint.h>

// Problem dims
#define B_ 8
#define N_ 1024
#define H_ 768
#define I_ 3072
#define NMAT 16
#define NN (1024LL*1024LL)
#define HI_ ((long long)H_ * I_)

typedef __nv_bfloat16 bf16;

// ---------------- scratch (static device globals) ----------------------------
// adj stored [k][b][N][N]  (k = graph index 0/1, b = batch)
__device__ bf16  g_adj16[(size_t)NMAT * 1024 * 1024];
__device__ float g_dinv[NMAT * N_];
__device__ bf16  g_nodes16[(size_t)B_ * N_ * H_];
// packed weights: slot 0 = GCN/FFN 1, slot 1 = GCN/FFN 2  (k-major [K][N])
__device__ bf16  g_w1[2 * H_ * I_];    // gcn?_w1
__device__ bf16  g_w2[2 * I_ * H_];    // gcn?_w2
__device__ bf16  g_we[2 * H_ * I_];    // exp?_w
__device__ bf16  g_wc[2 * I_ * H_];    // col?_w
__device__ bf16  g_wGate[2 * H_ * H_]; // folded gate weight [1536][768]
// activations, z = k*8 + b  layout [16][N][*]
__device__ bf16  g_h16 [(size_t)NMAT * N_ * H_];    // adjX, then t2pre
__device__ bf16  g_gc16[(size_t)NMAT * N_ * H_];    // GCN output
__device__ bf16  g_t1_16[(size_t)NMAT * N_ * I_];   // x1, then FFN expand
__device__ float g_hf  [(size_t)NMAT * N_ * H_];    // pre-LN FFN out (fp32)
__device__ bf16  g_cat16[(size_t)B_ * N_ * 2 * H_]; // [8192][1536] = [ln1 | ln2]
__device__ float g_ln1f[(size_t)B_ * N_ * H_];
__device__ float g_ln2f[(size_t)B_ * N_ * H_];

// ---------------- reductions ------------------------------------------------
__inline__ __device__ float warpReduceSum(float v) {
    #pragma unroll
    for (int o = 16; o > 0; o >>= 1) v += __shfl_xor_sync(0xFFFFFFFFu, v, o);
    return v;
}
__device__ float blockReduceSum(float v, float* sm) {
    __syncthreads();
    int lane = threadIdx.x & 31, w = threadIdx.x >> 5;
    v = warpReduceSum(v);
    if (lane == 0) sm[w] = v;
    __syncthreads();
    if (w == 0) {
        float t = (lane < 8) ? sm[lane] : 0.0f;
        t = warpReduceSum(t);
        if (lane == 0) sm[0] = t;
    }
    __syncthreads();
    return sm[0];
}

// ---------------- fp32 -> bf16 conversions -----------------------------------
__global__ void f2bf_kernel(const float* __restrict__ in, bf16* __restrict__ out, long long n4) {
    long long i = (long long)blockIdx.x * blockDim.x + threadIdx.x;
    if (i >= n4) return;
    float4 v = *(const float4*)(in + i * 4);
    bf16 o[4];
    o[0] = __float2bfloat16_rn(v.x); o[1] = __float2bfloat16_rn(v.y);
    o[2] = __float2bfloat16_rn(v.z); o[3] = __float2bfloat16_rn(v.w);
    *(uint2*)(out + i * 4) = *(uint2*)o;
}

// 8 H*I-sized weight conversions into packed slots.
// dsts: {w1[0], w1[1], w2[0], w2[1], we[0], we[1], wc[0], wc[1]}
// srcs must match: {gcn1_w1, gcn2_w1, gcn1_w2, gcn2_w2, exp1_w, exp2_w, col1_w, col2_w}
__global__ void conv_weights_kernel(
    const float* __restrict__ s0, const float* __restrict__ s1,
    const float* __restrict__ s2, const float* __restrict__ s3,
    const float* __restrict__ s4, const float* __restrict__ s5,
    const float* __restrict__ s6, const float* __restrict__ s7)
{
    // args: s0=gcn1_w1, s1=gcn1_w2, s2=gcn2_w1, s3=gcn2_w2,
    //       s4=exp1_w,  s5=col1_w,  s6=exp2_w,  s7=col2_w
    const float* srcs[8] = {s0, s2, s1, s3, s4, s6, s5, s7};
    bf16* dsts[8] = {g_w1, g_w1 + HI_, g_w2, g_w2 + HI_,
                     g_we, g_we + HI_, g_wc, g_wc + HI_};
    const float* in = srcs[blockIdx.y];
    bf16* out = dsts[blockIdx.y];
    long long i = (long long)blockIdx.x * blockDim.x + threadIdx.x;
    long long n4 = HI_ / 4;
    if (i >= n4) return;
    float4 v = *(const float4*)(in + i * 4);
    bf16 o[4];
    o[0] = __float2bfloat16_rn(v.x); o[1] = __float2bfloat16_rn(v.y);
    o[2] = __float2bfloat16_rn(v.z); o[3] = __float2bfloat16_rn(v.w);
    *(uint2*)(out + i * 4) = *(uint2*)o;
}

// ---------------- sym_normalize ---------------------------------------------
__global__ void rowsum_dinv_kernel(const float* __restrict__ A) {
    long long row = blockIdx.x;          // input order: m = b*2+k
    const float* p = A + row * (long long)N_;
    float s = 0.0f;
    for (int c = threadIdx.x * 4; c < N_; c += blockDim.x * 4) {
        float4 v = *(const float4*)(p + c);
        s += v.x + v.y + v.z + v.w;
    }
    __shared__ float sm[32];
    s = blockReduceSum(s, sm);
    if (threadIdx.x == 0) g_dinv[row] = 1.0f / sqrtf(s);
}

// reads graphs in [b][k] order, writes g_adj16 in [k][b] order
__global__ void normalize_adj_kernel(const float* __restrict__ A) {
    long long i4 = (long long)blockIdx.x * blockDim.x + threadIdx.x;
    long long total4 = (long long)NMAT * NN / 4;
    if (i4 >= total4) return;
    long long e = i4 * 4;
    int  m = (int)(e / NN);             // input matrix index: b*2+k
    long long rem = e % NN;
    int  r = (int)(rem / N_);
    int  c = (int)(rem % N_);
    float di = g_dinv[m * N_ + r];
    const float* dj = &g_dinv[m * N_ + c];
    float4 v = *(const float4*)(A + e);
    bf16 o[4];
    o[0] = __float2bfloat16_rn(v.x * di * dj[0]);
    o[1] = __float2bfloat16_rn(v.y * di * dj[1]);
    o[2] = __float2bfloat16_rn(v.z * di * dj[2]);
    o[3] = __float2bfloat16_rn(v.w * di * dj[3]);
    int mo = (m & 1) * 8 + (m >> 1);    // output: k*8 + b
    *(uint2*)(g_adj16 + mo * NN + rem) = *(uint2*)o;
}

// folded gate weight, k-major [1536][768]
__global__ void combine_w_kernel(const float* __restrict__ gw) {
    int i = blockIdx.x * blockDim.x + threadIdx.x;
    if (i >= H_ * H_) return;
    int r = i / H_, c = i % H_;
    float w0 = gw[i];
    float w1 = gw[(H_     + r) * H_ + c];
    float w2 = gw[(2 * H_ + r) * H_ + c];
    float w3 = gw[(3 * H_ + r) * H_ + c];
    g_wGate[r * H_ + c]        = __float2bfloat16_rn(w0 + w2 + w3);
    g_wGate[(H_ + r) * H_ + c] = __float2bfloat16_rn(w1 + w2 - w3);
}

// ---------------- bf16 tensor-core GEMM (mma.sync m16n8k16) -------------------
// 128x128 CTA tile, BK=32, 8 warps (2x4), 4-stage cp.async, 1 sync/iter.
// Per-z operand offsets: ptr += z*s1 + (z>>3)*s2   (z = k*8 + b batching)
#define EPI_NONE  0
#define EPI_RELU  1
#define EPI_BIAS  2
#define EPI_GELUB 3
#define EPI_GATE  5

#define SMEM_GEMM_BYTES ((4 * (128 * 40 + 32 * 136)) * 2)   // 75776

__device__ __forceinline__ void cp16(uint32_t sdst, const void* gsrc) {
    asm volatile("cp.async.cg.shared.global [%0], [%1], 16;\n" :: "r"(sdst), "l"(gsrc));
}

__device__ __forceinline__ void mma_bf16(float c[4], const uint32_t a[4],
                                         uint32_t b0, uint32_t b1) {
    asm volatile(
        "mma.sync.aligned.m16n8k16.row.col.f32.bf16.bf16.f32 "
        "{%0,%1,%2,%3}, {%4,%5,%6,%7}, {%8,%9}, {%0,%1,%2,%3};\n"
        : "+f"(c[0]), "+f"(c[1]), "+f"(c[2]), "+f"(c[3])
        : "r"(a[0]), "r"(a[1]), "r"(a[2]), "r"(a[3]), "r"(b0), "r"(b1));
}

template<int EPI, int OUTBF>
__global__ __launch_bounds__(256, 2) void gemm_bf(
    const bf16* __restrict__ A, const bf16* __restrict__ Bm,
    void* __restrict__ Cv,
    const float* __restrict__ bias_a, const float* __restrict__ bias_b,
    const float* __restrict__ e1, const float* __restrict__ e2,
    int N, int K,
    long long sA1, long long sA2, long long sB1, long long sB2,
    long long sC1, long long sC2)
{
    extern __shared__ __align__(16) bf16 sm[];
    const uint32_t sbase = (uint32_t)__cvta_generic_to_shared(sm);

    const long long z  = blockIdx.z;
    const long long hi = z >> 3;
    A  += z * sA1 + hi * sA2;
    Bm += z * sB1 + hi * sB2;
    const long long cOff = z * sC1 + hi * sC2;
    const float* bias = (hi == 0) ? bias_a : bias_b;

    const int tid  = threadIdx.x;
    const int w    = tid >> 5;
    const int lane = tid & 31;
    const int wm   = w & 1;
    const int wn   = w >> 1;
    const int g    = lane >> 2;
    const int tg   = lane & 3;

    const int aRow  = tid >> 1;
    const int aKoff = (tid & 1) * 16;
    const int bRow  = tid >> 3;
    const int bNoff = (tid & 7) * 16;

    const bf16* Ag = A  + ((long long)blockIdx.y * 128 + aRow) * K + aKoff;
    const bf16* Bg = Bm + (long long)bRow * N + blockIdx.x * 128 + bNoff;

    float c[4][4][4];
    #pragma unroll
    for (int mi = 0; mi < 4; mi++)
        #pragma unroll
        for (int ni = 0; ni < 4; ni++)
            #pragma unroll
            for (int u = 0; u < 4; u++) c[mi][ni][u] = 0.0f;

    const int S = K / 32;
    const int lm_r = lane & 15;
    const int lm_c = (lane >> 4) * 8;

    auto stage = [&](int chunk, int st) {
        const bf16* Ap = Ag + chunk * 32;
        const bf16* Bp = Bg + (long long)chunk * 32 * N;
        uint32_t asb = sbase + (st * 5120 + aRow * 40 + aKoff) * 2;
        uint32_t bsb = sbase + (20480 + st * 4352 + bRow * 136 + bNoff) * 2;
        cp16(asb, Ap);
        cp16(asb + 16, Ap + 8);
        cp16(bsb, Bp);
        cp16(bsb + 16, Bp + 8);
        asm volatile("cp.async.commit_group;\n");
    };

    stage(0, 0);
    stage(1, 1);
    stage(2, 2);

    for (int s = 0; s < S; s++) {
        if (s <= S - 3)      asm volatile("cp.async.wait_group 2;\n");
        else if (s == S - 2) asm volatile("cp.async.wait_group 1;\n");
        else                 asm volatile("cp.async.wait_group 0;\n");
        __syncthreads();
        if (s + 3 < S) stage(s + 3, (s + 3) & 3);

        const int buf = s & 3;
        const uint32_t asBase = sbase + (buf * 5120) * 2;
        const uint32_t bsBase = sbase + (20480 + buf * 4352) * 2;

        #pragma unroll
        for (int kk = 0; kk < 2; kk++) {
            uint32_t a[4][4];
            uint32_t b[2][4];
            #pragma unroll
            for (int mi = 0; mi < 4; mi++) {
                uint32_t addr = asBase +
                    ((wm * 64 + mi * 16 + lm_r) * 40 + kk * 16 + lm_c) * 2;
                asm volatile(
                    "ldmatrix.sync.aligned.m8n8.x4.shared.b16 {%0,%1,%2,%3}, [%4];"
                    : "=r"(a[mi][0]), "=r"(a[mi][1]), "=r"(a[mi][2]), "=r"(a[mi][3])
                    : "r"(addr));
            }
            #pragma unroll
            for (int nb = 0; nb < 2; nb++) {
                uint32_t addr = bsBase +
                    ((kk * 16 + lm_r) * 136 + wn * 32 + nb * 16 + lm_c) * 2;
                asm volatile(
                    "ldmatrix.sync.aligned.m8n8.x4.trans.shared.b16 {%0,%1,%2,%3}, [%4];"
                    : "=r"(b[nb][0]), "=r"(b[nb][1]), "=r"(b[nb][2]), "=r"(b[nb][3])
                    : "r"(addr));
            }
            #pragma unroll
            for (int mi = 0; mi < 4; mi++)
                #pragma unroll
                for (int ni = 0; ni < 4; ni++)
                    mma_bf16(c[mi][ni], a[mi],
                             b[ni >> 1][(ni & 1) * 2], b[ni >> 1][(ni & 1) * 2 + 1]);
        }
    }

    // ---- epilogue ----
    #pragma unroll
    for (int mi = 0; mi < 4; mi++) {
        #pragma unroll
        for (int ni = 0; ni < 4; ni++) {
            const int row0 = blockIdx.y * 128 + wm * 64 + mi * 16 + g;
            const int col  = blockIdx.x * 128 + wn * 32 + ni * 8 + 2 * tg;
            float v[4];
            v[0] = c[mi][ni][0]; v[1] = c[mi][ni][1];
            v[2] = c[mi][ni][2]; v[3] = c[mi][ni][3];

            if (EPI == EPI_BIAS || EPI == EPI_GELUB || EPI == EPI_GATE) {
                float b0 = bias[col], b1 = bias[col + 1];
                v[0] += b0; v[1] += b1; v[2] += b0; v[3] += b1;
            }
            if (EPI == EPI_RELU) {
                #pragma unroll
                for (int u = 0; u < 4; u++) v[u] = fmaxf(v[u], 0.0f);
            }
            if (EPI == EPI_GELUB) {
                #pragma unroll
                for (int u = 0; u < 4; u++)
                    v[u] = 0.5f * v[u] * (1.0f + erff(v[u] * 0.70710678118654752f));
            }
            if (EPI == EPI_GATE) {
                long long i0 = (long long)row0 * N + col;
                long long i1 = (long long)(row0 + 8) * N + col;
                float2 p0 = *(const float2*)(e1 + i0);
                float2 p1 = *(const float2*)(e1 + i1);
                float2 q0 = *(const float2*)(e2 + i0);
                float2 q1 = *(const float2*)(e2 + i1);
                float gt;
                gt = 1.0f / (1.0f + expf(-v[0])); v[0] = gt * p0.x + (1.0f - gt) * q0.x;
                gt = 1.0f / (1.0f + expf(-v[1])); v[1] = gt * p0.y + (1.0f - gt) * q0.y;
                gt = 1.0f / (1.0f + expf(-v[2])); v[2] = gt * p1.x + (1.0f - gt) * q1.x;
                gt = 1.0f / (1.0f + expf(-v[3])); v[3] = gt * p1.y + (1.0f - gt) * q1.y;
            }

            if (OUTBF) {
                bf16* C = (bf16*)Cv + cOff;
                bf16* C0 = C + (long long)row0 * N + col;
                bf16* C1 = C + (long long)(row0 + 8) * N + col;
                bf16 p0[2] = {__float2bfloat16_rn(v[0]), __float2bfloat16_rn(v[1])};
                bf16 p1[2] = {__float2bfloat16_rn(v[2]), __float2bfloat16_rn(v[3])};
                *(uint32_t*)C0 = *(uint32_t*)p0;
                *(uint32_t*)C1 = *(uint32_t*)p1;
            } else {
                float* C = (float*)Cv + cOff;
                float* C0 = C + (long long)row0 * N + col;
                float* C1 = C + (long long)(row0 + 8) * N + col;
                *(float2*)C0 = make_float2(v[0], v[1]);
                *(float2*)C1 = make_float2(v[2], v[3]);
            }
        }
    }
}

// ---------------- merged layernorm: y=0 -> LN1, y=1 -> LN2 --------------------
__global__ void ln_kernel(const float* __restrict__ nodes, const float* __restrict__ hf,
                          const float* __restrict__ g1v, const float* __restrict__ b1v,
                          const float* __restrict__ g2v, const float* __restrict__ b2v,
                          float* __restrict__ ln1f, float* __restrict__ ln2f,
                          bf16* __restrict__ cat)
{
    const int k = blockIdx.y;
    long long row = blockIdx.x;                  // batch-major row in [0, 8192)
    long long b = row >> 10;
    int n = (int)(row & 1023);
    const float* np = nodes + row * H_;
    const float* hp = hf + (((long long)k * 8 + b) * 1024 + n) * H_;
    float* opf = (k ? ln2f : ln1f) + row * H_;
    bf16* op16 = cat + row * (2 * H_) + k * H_;
    const float* g = k ? g2v : g1v;
    const float* bb = k ? b2v : b1v;
    int t = threadIdx.x;

    float x[3];
    float s = 0.0f;
    #pragma unroll
    for (int i = 0; i < 3; i++) {
        int c = t + i * 256;
        x[i] = np[c] + hp[c];
        s += x[i];
    }
    __shared__ float sm[32];
    s = blockReduceSum(s, sm);
    float mu = s * (1.0f / H_);
    float v = 0.0f;
    #pragma unroll
    for (int i = 0; i < 3; i++) {
        float d = x[i] - mu;
        v += d * d;
    }
    v = blockReduceSum(v, sm);
    float rs = rsqrtf(v * (1.0f / H_) + 1e-12f);
    #pragma unroll
    for (int i = 0; i < 3; i++) {
        int c = t + i * 256;
        float o = (x[i] - mu) * rs * g[c] + bb[c];
        opf[c] = o;
        op16[c] = __float2bfloat16_rn(o);
    }
}

// ---------------- launcher ---------------------------------------------------
extern "C" void kernel_launch(void* const* d_in, const int* in_sizes, int n_in,
                              void* d_out, int out_size)
{
    (void)in_sizes; (void)n_in; (void)out_size;
    const float* nodes   = (const float*)d_in[0];
    const float* graphs  = (const float*)d_in[1];
    const float* gcn1_w1 = (const float*)d_in[2];
    const float* gcn1_w2 = (const float*)d_in[3];
    const float* gcn2_w1 = (const float*)d_in[4];
    const float* gcn2_w2 = (const float*)d_in[5];
    const float* exp1_w  = (const float*)d_in[6];
    const float* exp1_b  = (const float*)d_in[7];
    const float* col1_w  = (const float*)d_in[8];
    const float* col1_b  = (const float*)d_in[9];
    const float* exp2_w  = (const float*)d_in[10];
    const float* exp2_b  = (const float*)d_in[11];
    const float* col2_w  = (const float*)d_in[12];
    const float* col2_b  = (const float*)d_in[13];
    const float* gate_w  = (const float*)d_in[14];
    const float* gate_b  = (const float*)d_in[15];
    const float* ln1_g   = (const float*)d_in[16];
    const float* ln1_b   = (const float*)d_in[17];
    const float* ln2_g   = (const float*)d_in[18];
    const float* ln2_b   = (const float*)d_in[19];
    float* out = (float*)d_out;

    bf16 *adj16, *nodes16, *w1, *w2, *we, *wc, *wGate;
    bf16 *t1_16, *h16, *gc16, *cat16;
    float *hf, *ln1f, *ln2f;
    cudaGetSymbolAddress((void**)&adj16,   g_adj16);
    cudaGetSymbolAddress((void**)&nodes16, g_nodes16);
    cudaGetSymbolAddress((void**)&w1, g_w1);
    cudaGetSymbolAddress((void**)&w2, g_w2);
    cudaGetSymbolAddress((void**)&we, g_we);
    cudaGetSymbolAddress((void**)&wc, g_wc);
    cudaGetSymbolAddress((void**)&wGate, g_wGate);
    cudaGetSymbolAddress((void**)&t1_16, g_t1_16);
    cudaGetSymbolAddress((void**)&h16,   g_h16);
    cudaGetSymbolAddress((void**)&gc16,  g_gc16);
    cudaGetSymbolAddress((void**)&cat16, g_cat16);
    cudaGetSymbolAddress((void**)&hf,   g_hf);
    cudaGetSymbolAddress((void**)&ln1f, g_ln1f);
    cudaGetSymbolAddress((void**)&ln2f, g_ln2f);

    const int SMB = SMEM_GEMM_BYTES;
    cudaFuncSetAttribute(gemm_bf<EPI_NONE, 1>, cudaFuncAttributeMaxDynamicSharedMemorySize, SMB);
    cudaFuncSetAttribute(gemm_bf<EPI_RELU, 1>, cudaFuncAttributeMaxDynamicSharedMemorySize, SMB);
    cudaFuncSetAttribute(gemm_bf<EPI_GELUB,1>, cudaFuncAttributeMaxDynamicSharedMemorySize, SMB);
    cudaFuncSetAttribute(gemm_bf<EPI_BIAS, 0>, cudaFuncAttributeMaxDynamicSharedMemorySize, SMB);
    cudaFuncSetAttribute(gemm_bf<EPI_GATE, 0>, cudaFuncAttributeMaxDynamicSharedMemorySize, SMB);

    const long long MN  = (long long)B_ * N_;     // 8192
    const long long sNH = (long long)N_ * H_;     // per-z [N][H] stride
    const long long sNI = (long long)N_ * I_;     // per-z [N][I] stride
    const long long IH  = (long long)I_ * H_;

    // ---- prologue ----
    {
        long long n4 = MN * H_ / 4;
        f2bf_kernel<<<(unsigned)((n4 + 255) / 256), 256>>>(nodes, nodes16, n4);
    }
    {
        long long n4 = HI_ / 4;
        dim3 grid((unsigned)((n4 + 255) / 256), 8);
        conv_weights_kernel<<<grid, 256>>>(gcn1_w1, gcn1_w2, gcn2_w1, gcn2_w2,
                                           exp1_w, col1_w, exp2_w, col2_w);
    }
    combine_w_kernel<<<(H_ * H_ + 255) / 256, 256>>>(gate_w);
    rowsum_dinv_kernel<<<NMAT * N_, 256>>>(graphs);
    long long total4 = (long long)NMAT * NN / 4;
    normalize_adj_kernel<<<(unsigned)((total4 + 255) / 256), 256>>>(graphs);

    // ---- batched dual-GCN chain (z = k*8 + b over 16 slices) ----
    // 1) adjX = adj @ nodes          [z][1024][768]
    gemm_bf<EPI_NONE, 1><<<dim3(H_/128, N_/128, NMAT), 256, SMB>>>(
        adj16, nodes16, h16, nullptr, nullptr, nullptr, nullptr,
        H_, N_, NN, 0, sNH, -8 * sNH, sNH, 0);
    // 2) x1 = relu(adjX @ W1)        [z][1024][3072]
    gemm_bf<EPI_RELU, 1><<<dim3(I_/128, N_/128, NMAT), 256, SMB>>>(
        h16, w1, t1_16, nullptr, nullptr, nullptr, nullptr,
        I_, H_, sNH, 0, 0, HI_, sNI, 0);
    // 3) t2p = x1 @ W2               [z][1024][768]
    gemm_bf<EPI_NONE, 1><<<dim3(H_/128, N_/128, NMAT), 256, SMB>>>(
        t1_16, w2, h16, nullptr, nullptr, nullptr, nullptr,
        H_, I_, sNI, 0, 0, IH, sNH, 0);
    // 4) gc = relu(adj @ t2p)        [z][1024][768]
    gemm_bf<EPI_RELU, 1><<<dim3(H_/128, N_/128, NMAT), 256, SMB>>>(
        adj16, h16, gc16, nullptr, nullptr, nullptr, nullptr,
        H_, N_, NN, 0, sNH, 0, sNH, 0);
    // 5) t3 = gelu(gc @ We + be)     [z][1024][3072]
    gemm_bf<EPI_GELUB, 1><<<dim3(I_/128, N_/128, NMAT), 256, SMB>>>(
        gc16, we, t1_16, exp1_b, exp2_b, nullptr, nullptr,
        I_, H_, sNH, 0, 0, HI_, sNI, 0);
    // 6) hf = t3 @ Wc + bc           [z][1024][768] fp32
    gemm_bf<EPI_BIAS, 0><<<dim3(H_/128, N_/128, NMAT), 256, SMB>>>(
        t1_16, wc, hf, col1_b, col2_b, nullptr, nullptr,
        H_, I_, sNI, 0, 0, IH, sNH, 0);

    // 7) both LayerNorms (residual vs nodes), fp32 + bf16-concat outputs
    ln_kernel<<<dim3((unsigned)MN, 2), 256>>>(nodes, hf, ln1_g, ln1_b, ln2_g, ln2_b,
                                              ln1f, ln2f, cat16);

    // 8) fused gate: out = sigmoid(cat @ Wgate + gb) blended with ln1f/ln2f
    gemm_bf<EPI_GATE, 0><<<dim3(H_/128, (unsigned)(MN/128), 1), 256, SMB>>>(
        cat16, wGate, out, gate_b, nullptr, ln1f, ln2f,
        H_, 2 * H_, 0, 0, 0, 0, 0, 0);
}

// round 13
// speedup vs baseline: 7.6518x; 1.0074x over previous
#include <cuda_runtime.h>
#include <cuda_bf16.h>
#include <math.h>
#include <stdint.h>

// Problem dims
#define B_ 8
#define N_ 1024
#define H_ 768
#define I_ 3072
#define NMAT 16
#define NN (1024LL*1024LL)
#define HI_ ((long long)H_ * I_)

typedef __nv_bfloat16 bf16;

// ---------------- scratch (static device globals) ----------------------------
// adj stored [k][b][N][N]  (k = graph index 0/1, b = batch)
__device__ bf16  g_adj16[(size_t)NMAT * 1024 * 1024];
__device__ float g_dinv[NMAT * N_];
__device__ bf16  g_nodes16[(size_t)B_ * N_ * H_];
// fp8 transposed weights [slot][N][K]
__device__ uint8_t g_w1f8[(size_t)2 * I_ * H_];   // [2][3072][768]
__device__ uint8_t g_w2f8[(size_t)2 * H_ * I_];   // [2][768][3072]
__device__ uint8_t g_wef8[(size_t)2 * I_ * H_];
__device__ uint8_t g_wcf8[(size_t)2 * H_ * I_];
__device__ bf16  g_wGate[2 * H_ * H_];            // folded gate weight [1536][768] bf16
// activations, z = k*8 + b
__device__ bf16  g_h16 [(size_t)NMAT * N_ * H_];    // t2p (bf16)
__device__ uint8_t g_act8[(size_t)NMAT * N_ * H_];  // adjX fp8, then gc fp8
__device__ uint8_t g_big8[(size_t)NMAT * N_ * I_];  // x1 fp8, then t3 fp8
__device__ float g_hf  [(size_t)NMAT * N_ * H_];    // pre-LN FFN out (fp32)
__device__ bf16  g_cat16[(size_t)B_ * N_ * 2 * H_]; // [8192][1536] = [ln1 | ln2]
__device__ float g_ln1f[(size_t)B_ * N_ * H_];
__device__ float g_ln2f[(size_t)B_ * N_ * H_];

// fp8 scales (powers of two)
#define S_ADJX 32.0f
#define S_W    64.0f
#define S_X1   64.0f
#define S_GC   256.0f
#define S_T3   1024.0f

// ---------------- reductions ------------------------------------------------
__inline__ __device__ float warpReduceSum(float v) {
    #pragma unroll
    for (int o = 16; o > 0; o >>= 1) v += __shfl_xor_sync(0xFFFFFFFFu, v, o);
    return v;
}
__device__ float blockReduceSum(float v, float* sm) {
    __syncthreads();
    int lane = threadIdx.x & 31, w = threadIdx.x >> 5;
    v = warpReduceSum(v);
    if (lane == 0) sm[w] = v;
    __syncthreads();
    if (w == 0) {
        float t = (lane < 8) ? sm[lane] : 0.0f;
        t = warpReduceSum(t);
        if (lane == 0) sm[0] = t;
    }
    __syncthreads();
    return sm[0];
}

// ---------------- fp8 pack helper --------------------------------------------
__device__ __forceinline__ uint16_t pack_e4m3x2(float lo, float hi) {
    uint16_t p;
    asm("cvt.rn.satfinite.e4m3x2.f32 %0, %1, %2;" : "=h"(p) : "f"(hi), "f"(lo));
    return p;
}

// ---------------- prologue kernels -------------------------------------------
__global__ void f2bf_kernel(const float* __restrict__ in, bf16* __restrict__ out, long long n4) {
    long long i = (long long)blockIdx.x * blockDim.x + threadIdx.x;
    if (i >= n4) return;
    float4 v = *(const float4*)(in + i * 4);
    bf16 o[4];
    o[0] = __float2bfloat16_rn(v.x); o[1] = __float2bfloat16_rn(v.y);
    o[2] = __float2bfloat16_rn(v.z); o[3] = __float2bfloat16_rn(v.w);
    *(uint2*)(out + i * 4) = *(uint2*)o;
}

// fp32 [R][C] -> fp8 [C][R] * S_W
__global__ void transpose_f8(const float* __restrict__ in, uint8_t* __restrict__ out,
                             int R, int C) {
    __shared__ float tile[32][33];
    int bx = blockIdx.x * 32, by = blockIdx.y * 32;
    int x = threadIdx.x, y = threadIdx.y;
    #pragma unroll
    for (int j = 0; j < 32; j += 8)
        tile[y + j][x] = in[(long long)(by + y + j) * C + bx + x];
    __syncthreads();
    #pragma unroll
    for (int j = 0; j < 32; j += 8) {
        uint16_t p = pack_e4m3x2(tile[x][y + j] * S_W, 0.0f);
        out[(long long)(bx + y + j) * R + by + x] = (uint8_t)(p & 0xFF);
    }
}

// warp-per-row rowsum
__global__ void rowsum_dinv_kernel(const float* __restrict__ A) {
    int w = threadIdx.x >> 5, lane = threadIdx.x & 31;
    long long row = (long long)blockIdx.x * 8 + w;
    const float* p = A + row * (long long)N_;
    float s = 0.0f;
    #pragma unroll
    for (int i = 0; i < 8; i++) {
        float4 v = *(const float4*)(p + (lane + i * 32) * 4);
        s += v.x + v.y + v.z + v.w;
    }
    s = warpReduceSum(s);
    if (lane == 0) g_dinv[row] = 1.0f / sqrtf(s);
}

// reads graphs in [b][k] order, writes g_adj16 in [k][b] order
__global__ void normalize_adj_kernel(const float* __restrict__ A) {
    long long i4 = (long long)blockIdx.x * blockDim.x + threadIdx.x;
    long long total4 = (long long)NMAT * NN / 4;
    if (i4 >= total4) return;
    long long e = i4 * 4;
    int  m = (int)(e / NN);
    long long rem = e % NN;
    int  r = (int)(rem / N_);
    int  c = (int)(rem % N_);
    float di = g_dinv[m * N_ + r];
    const float* dj = &g_dinv[m * N_ + c];
    float4 v = *(const float4*)(A + e);
    bf16 o[4];
    o[0] = __float2bfloat16_rn(v.x * di * dj[0]);
    o[1] = __float2bfloat16_rn(v.y * di * dj[1]);
    o[2] = __float2bfloat16_rn(v.z * di * dj[2]);
    o[3] = __float2bfloat16_rn(v.w * di * dj[3]);
    int mo = (m & 1) * 8 + (m >> 1);    // output: k*8 + b
    *(uint2*)(g_adj16 + mo * NN + rem) = *(uint2*)o;
}

// folded gate weight, k-major [1536][768] bf16
__global__ void combine_w_kernel(const float* __restrict__ gw) {
    int i = blockIdx.x * blockDim.x + threadIdx.x;
    if (i >= H_ * H_) return;
    int r = i / H_, c = i % H_;
    float w0 = gw[i];
    float w1 = gw[(H_     + r) * H_ + c];
    float w2 = gw[(2 * H_ + r) * H_ + c];
    float w3 = gw[(3 * H_ + r) * H_ + c];
    g_wGate[r * H_ + c]        = __float2bfloat16_rn(w0 + w2 + w3);
    g_wGate[(H_ + r) * H_ + c] = __float2bfloat16_rn(w1 + w2 - w3);
}

// ---------------- epilogue codes ---------------------------------------------
#define EPI_NONE  0
#define EPI_RELU  1
#define EPI_BIAS  2
#define EPI_GELUB 3
#define EPI_GATE  5
// OUTM: 0=f32, 1=bf16, 2=fp8*outscale

__device__ __forceinline__ void cp16(uint32_t sdst, const void* gsrc) {
    asm volatile("cp.async.cg.shared.global [%0], [%1], 16;\n" :: "r"(sdst), "l"(gsrc));
}

__device__ __forceinline__ void mma_bf16(float c[4], const uint32_t a[4],
                                         uint32_t b0, uint32_t b1) {
    asm volatile(
        "mma.sync.aligned.m16n8k16.row.col.f32.bf16.bf16.f32 "
        "{%0,%1,%2,%3}, {%4,%5,%6,%7}, {%8,%9}, {%0,%1,%2,%3};\n"
        : "+f"(c[0]), "+f"(c[1]), "+f"(c[2]), "+f"(c[3])
        : "r"(a[0]), "r"(a[1]), "r"(a[2]), "r"(a[3]), "r"(b0), "r"(b1));
}

__device__ __forceinline__ void mma_f8(float c[4], const uint32_t a[4],
                                       uint32_t b0, uint32_t b1) {
    asm volatile(
        "mma.sync.aligned.m16n8k32.row.col.f32.e4m3.e4m3.f32 "
        "{%0,%1,%2,%3}, {%4,%5,%6,%7}, {%8,%9}, {%0,%1,%2,%3};\n"
        : "+f"(c[0]), "+f"(c[1]), "+f"(c[2]), "+f"(c[3])
        : "r"(a[0]), "r"(a[1]), "r"(a[2]), "r"(a[3]), "r"(b0), "r"(b1));
}

// ---------------- bf16 GEMM (adj steps + gate) --------------------------------
#define SMEM_BF_BYTES ((4 * (128 * 40 + 32 * 136)) * 2)   // 75776

template<int EPI, int OUTM>
__global__ __launch_bounds__(256, 2) void gemm_bf(
    const bf16* __restrict__ A, const bf16* __restrict__ Bm,
    void* __restrict__ Cv,
    const float* __restrict__ bias_a, const float* __restrict__ bias_b,
    const float* __restrict__ e1, const float* __restrict__ e2,
    float outscale,
    int N, int K,
    long long sA1, long long sA2, long long sB1, long long sB2,
    long long sC1, long long sC2)
{
    extern __shared__ __align__(16) bf16 smn[];
    const uint32_t sbase = (uint32_t)__cvta_generic_to_shared(smn);

    const long long z  = blockIdx.z;
    const long long hi = z >> 3;
    A  += z * sA1 + hi * sA2;
    Bm += z * sB1 + hi * sB2;
    const long long cOff = z * sC1 + hi * sC2;
    const float* bias = (hi == 0) ? bias_a : bias_b;

    const int tid  = threadIdx.x;
    const int w    = tid >> 5;
    const int lane = tid & 31;
    const int wm   = w & 1;
    const int wn   = w >> 1;
    const int g    = lane >> 2;
    const int tg   = lane & 3;

    const int aRow  = tid >> 1;
    const int aKoff = (tid & 1) * 16;
    const int bRow  = tid >> 3;
    const int bNoff = (tid & 7) * 16;

    const bf16* Ag = A  + ((long long)blockIdx.y * 128 + aRow) * K + aKoff;
    const bf16* Bg = Bm + (long long)bRow * N + blockIdx.x * 128 + bNoff;

    float c[4][4][4];
    #pragma unroll
    for (int mi = 0; mi < 4; mi++)
        #pragma unroll
        for (int ni = 0; ni < 4; ni++)
            #pragma unroll
            for (int u = 0; u < 4; u++) c[mi][ni][u] = 0.0f;

    const int S = K / 32;
    const int lm_r = lane & 15;
    const int lm_c = (lane >> 4) * 8;

    auto stage = [&](int chunk, int st) {
        const bf16* Ap = Ag + chunk * 32;
        const bf16* Bp = Bg + (long long)chunk * 32 * N;
        uint32_t asb = sbase + (st * 5120 + aRow * 40 + aKoff) * 2;
        uint32_t bsb = sbase + (20480 + st * 4352 + bRow * 136 + bNoff) * 2;
        cp16(asb, Ap);
        cp16(asb + 16, Ap + 8);
        cp16(bsb, Bp);
        cp16(bsb + 16, Bp + 8);
        asm volatile("cp.async.commit_group;\n");
    };

    stage(0, 0);
    stage(1, 1);
    stage(2, 2);

    for (int s = 0; s < S; s++) {
        if (s <= S - 3)      asm volatile("cp.async.wait_group 2;\n");
        else if (s == S - 2) asm volatile("cp.async.wait_group 1;\n");
        else                 asm volatile("cp.async.wait_group 0;\n");
        __syncthreads();
        if (s + 3 < S) stage(s + 3, (s + 3) & 3);

        const int buf = s & 3;
        const uint32_t asBase = sbase + (buf * 5120) * 2;
        const uint32_t bsBase = sbase + (20480 + buf * 4352) * 2;

        #pragma unroll
        for (int kk = 0; kk < 2; kk++) {
            uint32_t a[4][4];
            uint32_t b[2][4];
            #pragma unroll
            for (int mi = 0; mi < 4; mi++) {
                uint32_t addr = asBase +
                    ((wm * 64 + mi * 16 + lm_r) * 40 + kk * 16 + lm_c) * 2;
                asm volatile(
                    "ldmatrix.sync.aligned.m8n8.x4.shared.b16 {%0,%1,%2,%3}, [%4];"
                    : "=r"(a[mi][0]), "=r"(a[mi][1]), "=r"(a[mi][2]), "=r"(a[mi][3])
                    : "r"(addr));
            }
            #pragma unroll
            for (int nb = 0; nb < 2; nb++) {
                uint32_t addr = bsBase +
                    ((kk * 16 + lm_r) * 136 + wn * 32 + nb * 16 + lm_c) * 2;
                asm volatile(
                    "ldmatrix.sync.aligned.m8n8.x4.trans.shared.b16 {%0,%1,%2,%3}, [%4];"
                    : "=r"(b[nb][0]), "=r"(b[nb][1]), "=r"(b[nb][2]), "=r"(b[nb][3])
                    : "r"(addr));
            }
            #pragma unroll
            for (int mi = 0; mi < 4; mi++)
                #pragma unroll
                for (int ni = 0; ni < 4; ni++)
                    mma_bf16(c[mi][ni], a[mi],
                             b[ni >> 1][(ni & 1) * 2], b[ni >> 1][(ni & 1) * 2 + 1]);
        }
    }

    #pragma unroll
    for (int mi = 0; mi < 4; mi++) {
        #pragma unroll
        for (int ni = 0; ni < 4; ni++) {
            const int row0 = blockIdx.y * 128 + wm * 64 + mi * 16 + g;
            const int col  = blockIdx.x * 128 + wn * 32 + ni * 8 + 2 * tg;
            float v[4];
            v[0] = c[mi][ni][0]; v[1] = c[mi][ni][1];
            v[2] = c[mi][ni][2]; v[3] = c[mi][ni][3];

            if (EPI == EPI_BIAS || EPI == EPI_GELUB || EPI == EPI_GATE) {
                float b0 = bias[col], b1 = bias[col + 1];
                v[0] += b0; v[1] += b1; v[2] += b0; v[3] += b1;
            }
            if (EPI == EPI_RELU) {
                #pragma unroll
                for (int u = 0; u < 4; u++) v[u] = fmaxf(v[u], 0.0f);
            }
            if (EPI == EPI_GELUB) {
                #pragma unroll
                for (int u = 0; u < 4; u++)
                    v[u] = 0.5f * v[u] * (1.0f + erff(v[u] * 0.70710678118654752f));
            }
            if (EPI == EPI_GATE) {
                long long i0 = (long long)row0 * N + col;
                long long i1 = (long long)(row0 + 8) * N + col;
                float2 p0 = *(const float2*)(e1 + i0);
                float2 p1 = *(const float2*)(e1 + i1);
                float2 q0 = *(const float2*)(e2 + i0);
                float2 q1 = *(const float2*)(e2 + i1);
                float gt;
                gt = 1.0f / (1.0f + expf(-v[0])); v[0] = gt * p0.x + (1.0f - gt) * q0.x;
                gt = 1.0f / (1.0f + expf(-v[1])); v[1] = gt * p0.y + (1.0f - gt) * q0.y;
                gt = 1.0f / (1.0f + expf(-v[2])); v[2] = gt * p1.x + (1.0f - gt) * q1.x;
                gt = 1.0f / (1.0f + expf(-v[3])); v[3] = gt * p1.y + (1.0f - gt) * q1.y;
            }

            if (OUTM == 1) {
                bf16* C = (bf16*)Cv + cOff;
                bf16* C0 = C + (long long)row0 * N + col;
                bf16* C1 = C + (long long)(row0 + 8) * N + col;
                bf16 p0[2] = {__float2bfloat16_rn(v[0]), __float2bfloat16_rn(v[1])};
                bf16 p1[2] = {__float2bfloat16_rn(v[2]), __float2bfloat16_rn(v[3])};
                *(uint32_t*)C0 = *(uint32_t*)p0;
                *(uint32_t*)C1 = *(uint32_t*)p1;
            } else if (OUTM == 2) {
                uint8_t* C = (uint8_t*)Cv + cOff;
                *(uint16_t*)(C + (long long)row0 * N + col) =
                    pack_e4m3x2(v[0] * outscale, v[1] * outscale);
                *(uint16_t*)(C + (long long)(row0 + 8) * N + col) =
                    pack_e4m3x2(v[2] * outscale, v[3] * outscale);
            } else {
                float* C = (float*)Cv + cOff;
                float* C0 = C + (long long)row0 * N + col;
                float* C1 = C + (long long)(row0 + 8) * N + col;
                *(float2*)C0 = make_float2(v[0], v[1]);
                *(float2*)C1 = make_float2(v[2], v[3]);
            }
        }
    }
}

// ---------------- fp8 GEMM (weight steps) -------------------------------------
// A [M][K] fp8, BT [N][K] fp8 (both K-contiguous). 128x128 tile, BK=64 bytes,
// 4-stage cp.async. Tiles: [128 rows][80B] each (64B data + 16B pad).
#define SMEM_F8_BYTES (8 * 128 * 80)   // 81920

template<int EPI, int OUTM>
__global__ __launch_bounds__(256, 2) void gemm_f8(
    const uint8_t* __restrict__ A, const uint8_t* __restrict__ BT,
    void* __restrict__ Cv,
    const float* __restrict__ bias_a, const float* __restrict__ bias_b,
    float unscale, float outscale,
    int N, int K,
    long long sA1, long long sA2, long long sB2,
    long long sC1)
{
    extern __shared__ __align__(16) uint8_t sm8[];
    const uint32_t sbase = (uint32_t)__cvta_generic_to_shared(sm8);

    const long long z  = blockIdx.z;
    const long long hi = z >> 3;
    A  += z * sA1 + hi * sA2;
    BT += hi * sB2;
    const long long cOff = z * sC1;
    const float* bias = (hi == 0) ? bias_a : bias_b;

    const int tid  = threadIdx.x;
    const int w    = tid >> 5;
    const int lane = tid & 31;
    const int wm   = w & 1;
    const int wn   = w >> 1;
    const int g    = lane >> 2;
    const int tg   = lane & 3;

    const int ldRow = tid >> 1;
    const int ldOff = (tid & 1) * 32;
    const uint8_t* Ag = A  + ((long long)blockIdx.y * 128 + ldRow) * K + ldOff;
    const uint8_t* Bg = BT + ((long long)blockIdx.x * 128 + ldRow) * K + ldOff;

    float c[4][4][4];
    #pragma unroll
    for (int mi = 0; mi < 4; mi++)
        #pragma unroll
        for (int ni = 0; ni < 4; ni++)
            #pragma unroll
            for (int u = 0; u < 4; u++) c[mi][ni][u] = 0.0f;

    const int S = K / 64;
    // a-frag addressing: row (lane&15), 16B-half (lane>>4)
    const int a_r = lane & 15;
    const int a_h = (lane >> 4) * 16;
    // b-frag addressing: row (lane&7)+((lane>>4)<<3), 16B-half ((lane>>3)&1)
    const int b_r = (lane & 7) + ((lane >> 4) << 3);
    const int b_h = ((lane >> 3) & 1) * 16;

    auto stage = [&](int chunk, int st) {
        const uint8_t* Ap = Ag + chunk * 64;
        const uint8_t* Bp = Bg + chunk * 64;
        uint32_t asb = sbase + st * 10240 + ldRow * 80 + ldOff;
        uint32_t bsb = sbase + 40960 + st * 10240 + ldRow * 80 + ldOff;
        cp16(asb, Ap);
        cp16(asb + 16, Ap + 16);
        cp16(bsb, Bp);
        cp16(bsb + 16, Bp + 16);
        asm volatile("cp.async.commit_group;\n");
    };

    stage(0, 0);
    stage(1, 1);
    stage(2, 2);

    for (int s = 0; s < S; s++) {
        if (s <= S - 3)      asm volatile("cp.async.wait_group 2;\n");
        else if (s == S - 2) asm volatile("cp.async.wait_group 1;\n");
        else                 asm volatile("cp.async.wait_group 0;\n");
        __syncthreads();
        if (s + 3 < S) stage(s + 3, (s + 3) & 3);

        const int buf = s & 3;
        const uint32_t asBase = sbase + buf * 10240;
        const uint32_t bsBase = sbase + 40960 + buf * 10240;

        #pragma unroll
        for (int kb = 0; kb < 64; kb += 32) {
            uint32_t a[4][4];
            uint32_t b[2][4];
            #pragma unroll
            for (int mi = 0; mi < 4; mi++) {
                uint32_t addr = asBase + (wm * 64 + mi * 16 + a_r) * 80 + kb + a_h;
                asm volatile(
                    "ldmatrix.sync.aligned.m8n8.x4.shared.b16 {%0,%1,%2,%3}, [%4];"
                    : "=r"(a[mi][0]), "=r"(a[mi][1]), "=r"(a[mi][2]), "=r"(a[mi][3])
                    : "r"(addr));
            }
            #pragma unroll
            for (int nb = 0; nb < 2; nb++) {
                uint32_t addr = bsBase + (wn * 32 + nb * 16 + b_r) * 80 + kb + b_h;
                asm volatile(
                    "ldmatrix.sync.aligned.m8n8.x4.shared.b16 {%0,%1,%2,%3}, [%4];"
                    : "=r"(b[nb][0]), "=r"(b[nb][1]), "=r"(b[nb][2]), "=r"(b[nb][3])
                    : "r"(addr));
            }
            #pragma unroll
            for (int mi = 0; mi < 4; mi++)
                #pragma unroll
                for (int ni = 0; ni < 4; ni++)
                    mma_f8(c[mi][ni], a[mi],
                           b[ni >> 1][(ni & 1) * 2], b[ni >> 1][(ni & 1) * 2 + 1]);
        }
    }

    #pragma unroll
    for (int mi = 0; mi < 4; mi++) {
        #pragma unroll
        for (int ni = 0; ni < 4; ni++) {
            const int row0 = blockIdx.y * 128 + wm * 64 + mi * 16 + g;
            const int col  = blockIdx.x * 128 + wn * 32 + ni * 8 + 2 * tg;
            float v[4];
            #pragma unroll
            for (int u = 0; u < 4; u++) v[u] = c[mi][ni][u] * unscale;

            if (EPI == EPI_BIAS || EPI == EPI_GELUB) {
                float b0 = bias[col], b1 = bias[col + 1];
                v[0] += b0; v[1] += b1; v[2] += b0; v[3] += b1;
            }
            if (EPI == EPI_RELU) {
                #pragma unroll
                for (int u = 0; u < 4; u++) v[u] = fmaxf(v[u], 0.0f);
            }
            if (EPI == EPI_GELUB) {
                #pragma unroll
                for (int u = 0; u < 4; u++)
                    v[u] = 0.5f * v[u] * (1.0f + erff(v[u] * 0.70710678118654752f));
            }

            if (OUTM == 1) {
                bf16* C = (bf16*)Cv + cOff;
                bf16* C0 = C + (long long)row0 * N + col;
                bf16* C1 = C + (long long)(row0 + 8) * N + col;
                bf16 p0[2] = {__float2bfloat16_rn(v[0]), __float2bfloat16_rn(v[1])};
                bf16 p1[2] = {__float2bfloat16_rn(v[2]), __float2bfloat16_rn(v[3])};
                *(uint32_t*)C0 = *(uint32_t*)p0;
                *(uint32_t*)C1 = *(uint32_t*)p1;
            } else if (OUTM == 2) {
                uint8_t* C = (uint8_t*)Cv + cOff;
                *(uint16_t*)(C + (long long)row0 * N + col) =
                    pack_e4m3x2(v[0] * outscale, v[1] * outscale);
                *(uint16_t*)(C + (long long)(row0 + 8) * N + col) =
                    pack_e4m3x2(v[2] * outscale, v[3] * outscale);
            } else {
                float* C = (float*)Cv + cOff;
                float* C0 = C + (long long)row0 * N + col;
                float* C1 = C + (long long)(row0 + 8) * N + col;
                *(float2*)C0 = make_float2(v[0], v[1]);
                *(float2*)C1 = make_float2(v[2], v[3]);
            }
        }
    }
}

// ---------------- merged layernorm: y=0 -> LN1, y=1 -> LN2 --------------------
__global__ void ln_kernel(const float* __restrict__ nodes, const float* __restrict__ hf,
                          const float* __restrict__ g1v, const float* __restrict__ b1v,
                          const float* __restrict__ g2v, const float* __restrict__ b2v,
                          float* __restrict__ ln1f, float* __restrict__ ln2f,
                          bf16* __restrict__ cat)
{
    const int k = blockIdx.y;
    long long row = blockIdx.x;
    long long b = row >> 10;
    int n = (int)(row & 1023);
    const float* np = nodes + row * H_;
    const float* hp = hf + (((long long)k * 8 + b) * 1024 + n) * H_;
    float* opf = (k ? ln2f : ln1f) + row * H_;
    bf16* op16 = cat + row * (2 * H_) + k * H_;
    const float* g = k ? g2v : g1v;
    const float* bb = k ? b2v : b1v;
    int t = threadIdx.x;

    float x[3];
    float s = 0.0f;
    #pragma unroll
    for (int i = 0; i < 3; i++) {
        int c = t + i * 256;
        x[i] = np[c] + hp[c];
        s += x[i];
    }
    __shared__ float sm[32];
    s = blockReduceSum(s, sm);
    float mu = s * (1.0f / H_);
    float v = 0.0f;
    #pragma unroll
    for (int i = 0; i < 3; i++) {
        float d = x[i] - mu;
        v += d * d;
    }
    v = blockReduceSum(v, sm);
    float rs = rsqrtf(v * (1.0f / H_) + 1e-12f);
    #pragma unroll
    for (int i = 0; i < 3; i++) {
        int c = t + i * 256;
        float o = (x[i] - mu) * rs * g[c] + bb[c];
        opf[c] = o;
        op16[c] = __float2bfloat16_rn(o);
    }
}

// ---------------- launcher ---------------------------------------------------
extern "C" void kernel_launch(void* const* d_in, const int* in_sizes, int n_in,
                              void* d_out, int out_size)
{
    (void)in_sizes; (void)n_in; (void)out_size;
    const float* nodes   = (const float*)d_in[0];
    const float* graphs  = (const float*)d_in[1];
    const float* gcn1_w1 = (const float*)d_in[2];
    const float* gcn1_w2 = (const float*)d_in[3];
    const float* gcn2_w1 = (const float*)d_in[4];
    const float* gcn2_w2 = (const float*)d_in[5];
    const float* exp1_w  = (const float*)d_in[6];
    const float* exp1_b  = (const float*)d_in[7];
    const float* col1_w  = (const float*)d_in[8];
    const float* col1_b  = (const float*)d_in[9];
    const float* exp2_w  = (const float*)d_in[10];
    const float* exp2_b  = (const float*)d_in[11];
    const float* col2_w  = (const float*)d_in[12];
    const float* col2_b  = (const float*)d_in[13];
    const float* gate_w  = (const float*)d_in[14];
    const float* gate_b  = (const float*)d_in[15];
    const float* ln1_g   = (const float*)d_in[16];
    const float* ln1_b   = (const float*)d_in[17];
    const float* ln2_g   = (const float*)d_in[18];
    const float* ln2_b   = (const float*)d_in[19];
    float* out = (float*)d_out;

    bf16 *adj16, *nodes16, *wGate, *h16, *cat16;
    uint8_t *w1f8, *w2f8, *wef8, *wcf8, *act8, *big8;
    float *hf, *ln1f, *ln2f;
    cudaGetSymbolAddress((void**)&adj16,   g_adj16);
    cudaGetSymbolAddress((void**)&nodes16, g_nodes16);
    cudaGetSymbolAddress((void**)&wGate, g_wGate);
    cudaGetSymbolAddress((void**)&w1f8, g_w1f8);
    cudaGetSymbolAddress((void**)&w2f8, g_w2f8);
    cudaGetSymbolAddress((void**)&wef8, g_wef8);
    cudaGetSymbolAddress((void**)&wcf8, g_wcf8);
    cudaGetSymbolAddress((void**)&act8, g_act8);
    cudaGetSymbolAddress((void**)&big8, g_big8);
    cudaGetSymbolAddress((void**)&h16,   g_h16);
    cudaGetSymbolAddress((void**)&cat16, g_cat16);
    cudaGetSymbolAddress((void**)&hf,   g_hf);
    cudaGetSymbolAddress((void**)&ln1f, g_ln1f);
    cudaGetSymbolAddress((void**)&ln2f, g_ln2f);

    const int SMB  = SMEM_BF_BYTES;
    const int SMB8 = SMEM_F8_BYTES;
    cudaFuncSetAttribute(gemm_bf<EPI_NONE, 2>, cudaFuncAttributeMaxDynamicSharedMemorySize, SMB);
    cudaFuncSetAttribute(gemm_bf<EPI_RELU, 2>, cudaFuncAttributeMaxDynamicSharedMemorySize, SMB);
    cudaFuncSetAttribute(gemm_bf<EPI_GATE, 0>, cudaFuncAttributeMaxDynamicSharedMemorySize, SMB);
    cudaFuncSetAttribute(gemm_f8<EPI_RELU, 2>, cudaFuncAttributeMaxDynamicSharedMemorySize, SMB8);
    cudaFuncSetAttribute(gemm_f8<EPI_NONE, 1>, cudaFuncAttributeMaxDynamicSharedMemorySize, SMB8);
    cudaFuncSetAttribute(gemm_f8<EPI_GELUB,2>, cudaFuncAttributeMaxDynamicSharedMemorySize, SMB8);
    cudaFuncSetAttribute(gemm_f8<EPI_BIAS, 0>, cudaFuncAttributeMaxDynamicSharedMemorySize, SMB8);

    const long long MN  = (long long)B_ * N_;     // 8192
    const long long sNH = (long long)N_ * H_;
    const long long sNI = (long long)N_ * I_;
    const long long IH  = (long long)I_ * H_;

    // ---- prologue ----
    {
        long long n4 = MN * H_ / 4;
        f2bf_kernel<<<(unsigned)((n4 + 255) / 256), 256>>>(nodes, nodes16, n4);
    }
    dim3 tb(32, 8);
    // [768][3072] -> [3072][768]
    transpose_f8<<<dim3(I_ / 32, H_ / 32), tb>>>(gcn1_w1, w1f8,      H_, I_);
    transpose_f8<<<dim3(I_ / 32, H_ / 32), tb>>>(gcn2_w1, w1f8 + IH, H_, I_);
    transpose_f8<<<dim3(I_ / 32, H_ / 32), tb>>>(exp1_w,  wef8,      H_, I_);
    transpose_f8<<<dim3(I_ / 32, H_ / 32), tb>>>(exp2_w,  wef8 + IH, H_, I_);
    // [3072][768] -> [768][3072]
    transpose_f8<<<dim3(H_ / 32, I_ / 32), tb>>>(gcn1_w2, w2f8,      I_, H_);
    transpose_f8<<<dim3(H_ / 32, I_ / 32), tb>>>(gcn2_w2, w2f8 + IH, I_, H_);
    transpose_f8<<<dim3(H_ / 32, I_ / 32), tb>>>(col1_w,  wcf8,      I_, H_);
    transpose_f8<<<dim3(H_ / 32, I_ / 32), tb>>>(col2_w,  wcf8 + IH, I_, H_);
    combine_w_kernel<<<(H_ * H_ + 255) / 256, 256>>>(gate_w);
    rowsum_dinv_kernel<<<NMAT * N_ / 8, 256>>>(graphs);
    long long total4 = (long long)NMAT * NN / 4;
    normalize_adj_kernel<<<(unsigned)((total4 + 255) / 256), 256>>>(graphs);

    // ---- batched dual-GCN chain (z = k*8 + b over 16 slices) ----
    // 1) adjX = adj @ nodes -> fp8*32   [z][1024][768]
    gemm_bf<EPI_NONE, 2><<<dim3(H_/128, N_/128, NMAT), 256, SMB>>>(
        adj16, nodes16, act8, nullptr, nullptr, nullptr, nullptr, S_ADJX,
        H_, N_, NN, 0, sNH, -8 * sNH, sNH, 0);
    // 2) x1 = relu(adjX @ W1) fp8 -> fp8*64   [z][1024][3072]
    gemm_f8<EPI_RELU, 2><<<dim3(I_/128, N_/128, NMAT), 256, SMB8>>>(
        act8, w1f8, big8, nullptr, nullptr, 1.0f/(S_ADJX*S_W), S_X1,
        I_, H_, sNH, 0, IH, sNI);
    // 3) t2p = x1 @ W2 fp8 -> bf16   [z][1024][768]
    gemm_f8<EPI_NONE, 1><<<dim3(H_/128, N_/128, NMAT), 256, SMB8>>>(
        big8, w2f8, h16, nullptr, nullptr, 1.0f/(S_X1*S_W), 0.0f,
        H_, I_, sNI, 0, IH, sNH);
    // 4) gc = relu(adj @ t2p) bf16 -> fp8*256   [z][1024][768]
    gemm_bf<EPI_RELU, 2><<<dim3(H_/128, N_/128, NMAT), 256, SMB>>>(
        adj16, h16, act8, nullptr, nullptr, nullptr, nullptr, S_GC,
        H_, N_, NN, 0, sNH, 0, sNH, 0);
    // 5) t3 = gelu(gc @ We + be) fp8 -> fp8*1024   [z][1024][3072]
    gemm_f8<EPI_GELUB, 2><<<dim3(I_/128, N_/128, NMAT), 256, SMB8>>>(
        act8, wef8, big8, exp1_b, exp2_b, 1.0f/(S_GC*S_W), S_T3,
        I_, H_, sNH, 0, IH, sNI);
    // 6) hf = t3 @ Wc + bc fp8 -> f32   [z][1024][768]
    gemm_f8<EPI_BIAS, 0><<<dim3(H_/128, N_/128, NMAT), 256, SMB8>>>(
        big8, wcf8, hf, col1_b, col2_b, 1.0f/(S_T3*S_W), 0.0f,
        H_, I_, sNI, 0, IH, sNH);

    // 7) both LayerNorms
    ln_kernel<<<dim3((unsigned)MN, 2), 256>>>(nodes, hf, ln1_g, ln1_b, ln2_g, ln2_b,
                                              ln1f, ln2f, cat16);

    // 8) fused gate (bf16): out = sigmoid(cat @ Wgate + gb) blended with ln1f/ln2f
    gemm_bf<EPI_GATE, 0><<<dim3(H_/128, (unsigned)(MN/128), 1), 256, SMB>>>(
        cat16, wGate, out, gate_b, nullptr, ln1f, ln2f, 0.0f,
        H_, 2 * H_, 0, 0, 0, 0, 0, 0);
}

// round 14
// speedup vs baseline: 7.9639x; 1.0408x over previous
#include <cuda_runtime.h>
#include <cuda_bf16.h>
#include <cuda_fp16.h>
#include <math.h>
#include <stdint.h>

// Problem dims
#define B_ 8
#define N_ 1024
#define H_ 768
#define I_ 3072
#define NMAT 16
#define NN (1024LL*1024LL)
#define HI_ ((long long)H_ * I_)

typedef __nv_bfloat16 bf16;

// ---------------- scratch (static device globals) ----------------------------
// adj stored [k][b][N][N]  (k = graph index 0/1, b = batch)
__device__ bf16  g_adj16[(size_t)NMAT * 1024 * 1024];
__device__ float g_dinv[NMAT * N_];
__device__ bf16  g_nodes16[(size_t)B_ * N_ * H_];
// fp8 transposed weights [slot][N][K]
__device__ uint8_t g_w1f8[(size_t)2 * I_ * H_];   // [2][3072][768]
__device__ uint8_t g_w2f8[(size_t)2 * H_ * I_];   // [2][768][3072]
__device__ uint8_t g_wef8[(size_t)2 * I_ * H_];
__device__ uint8_t g_wcf8[(size_t)2 * H_ * I_];
__device__ bf16  g_wGate[2 * H_ * H_];            // folded gate weight [1536][768] bf16
// activations, z = k*8 + b
__device__ bf16  g_h16 [(size_t)NMAT * N_ * H_];    // t2p (bf16)
__device__ uint8_t g_act8[(size_t)NMAT * N_ * H_];  // adjX fp8, then gc fp8
__device__ uint8_t g_big8[(size_t)NMAT * N_ * I_];  // x1 fp8, then t3 fp8
__device__ float g_hf  [(size_t)NMAT * N_ * H_];    // pre-LN FFN out (fp32)
__device__ bf16  g_cat16[(size_t)B_ * N_ * 2 * H_]; // [8192][1536] = [ln1 | ln2]
__device__ float g_ln1f[(size_t)B_ * N_ * H_];
__device__ float g_ln2f[(size_t)B_ * N_ * H_];

// fp8 scales (powers of two)
#define S_ADJX 32.0f
#define S_W    64.0f
#define S_X1   64.0f
#define S_GC   256.0f
#define S_T3   1024.0f

// ---------------- reductions ------------------------------------------------
__inline__ __device__ float warpReduceSum(float v) {
    #pragma unroll
    for (int o = 16; o > 0; o >>= 1) v += __shfl_xor_sync(0xFFFFFFFFu, v, o);
    return v;
}
__device__ float blockReduceSum(float v, float* sm) {
    __syncthreads();
    int lane = threadIdx.x & 31, w = threadIdx.x >> 5;
    v = warpReduceSum(v);
    if (lane == 0) sm[w] = v;
    __syncthreads();
    if (w == 0) {
        float t = (lane < 8) ? sm[lane] : 0.0f;
        t = warpReduceSum(t);
        if (lane == 0) sm[0] = t;
    }
    __syncthreads();
    return sm[0];
}

// ---------------- fp8 pack helper --------------------------------------------
__device__ __forceinline__ uint16_t pack_e4m3x2(float lo, float hi) {
    uint16_t p;
    asm("cvt.rn.satfinite.e4m3x2.f32 %0, %1, %2;" : "=h"(p) : "f"(hi), "f"(lo));
    return p;
}

// ---------------- prologue kernels -------------------------------------------
__global__ void f2bf_kernel(const float* __restrict__ in, bf16* __restrict__ out, long long n4) {
    long long i = (long long)blockIdx.x * blockDim.x + threadIdx.x;
    if (i >= n4) return;
    float4 v = *(const float4*)(in + i * 4);
    bf16 o[4];
    o[0] = __float2bfloat16_rn(v.x); o[1] = __float2bfloat16_rn(v.y);
    o[2] = __float2bfloat16_rn(v.z); o[3] = __float2bfloat16_rn(v.w);
    *(uint2*)(out + i * 4) = *(uint2*)o;
}

// ALL 8 weight transposes in one launch. blockIdx.z selects the matrix.
// z 0..3: [768][3072] -> [3072][768]; z 4..7: [3072][768] -> [768][3072].
// Both shapes tile into 2304 32x32 tiles (1D grid.x).
__global__ void transpose_f8_all(
    const float* __restrict__ s0, const float* __restrict__ s1,
    const float* __restrict__ s2, const float* __restrict__ s3,
    const float* __restrict__ s4, const float* __restrict__ s5,
    const float* __restrict__ s6, const float* __restrict__ s7)
{
    __shared__ float tile[32][33];
    const int zi = blockIdx.z;
    const float* srcs[8] = {s0, s1, s2, s3, s4, s5, s6, s7};
    uint8_t* dsts[8] = {g_w1f8, g_w1f8 + HI_, g_wef8, g_wef8 + HI_,
                        g_w2f8, g_w2f8 + HI_, g_wcf8, g_wcf8 + HI_};
    const float* in = srcs[zi];
    uint8_t* out = dsts[zi];
    const int R = (zi < 4) ? H_ : I_;
    const int C = (zi < 4) ? I_ : H_;
    const int tilesX = C / 32;
    int bid = blockIdx.x;
    int bx = (bid % tilesX) * 32, by = (bid / tilesX) * 32;
    int x = threadIdx.x, y = threadIdx.y;
    #pragma unroll
    for (int j = 0; j < 32; j += 8)
        tile[y + j][x] = in[(long long)(by + y + j) * C + bx + x];
    __syncthreads();
    #pragma unroll
    for (int j = 0; j < 32; j += 8) {
        uint16_t p = pack_e4m3x2(tile[x][y + j] * S_W, 0.0f);
        out[(long long)(bx + y + j) * R + by + x] = (uint8_t)(p & 0xFF);
    }
}

// warp-per-row rowsum
__global__ void rowsum_dinv_kernel(const float* __restrict__ A) {
    int w = threadIdx.x >> 5, lane = threadIdx.x & 31;
    long long row = (long long)blockIdx.x * 8 + w;
    const float* p = A + row * (long long)N_;
    float s = 0.0f;
    #pragma unroll
    for (int i = 0; i < 8; i++) {
        float4 v = *(const float4*)(p + (lane + i * 32) * 4);
        s += v.x + v.y + v.z + v.w;
    }
    s = warpReduceSum(s);
    if (lane == 0) g_dinv[row] = 1.0f / sqrtf(s);
}

// reads graphs in [b][k] order, writes g_adj16 in [k][b] order
__global__ void normalize_adj_kernel(const float* __restrict__ A) {
    long long i4 = (long long)blockIdx.x * blockDim.x + threadIdx.x;
    long long total4 = (long long)NMAT * NN / 4;
    if (i4 >= total4) return;
    long long e = i4 * 4;
    int  m = (int)(e / NN);
    long long rem = e % NN;
    int  r = (int)(rem / N_);
    int  c = (int)(rem % N_);
    float di = g_dinv[m * N_ + r];
    const float* dj = &g_dinv[m * N_ + c];
    float4 v = *(const float4*)(A + e);
    bf16 o[4];
    o[0] = __float2bfloat16_rn(v.x * di * dj[0]);
    o[1] = __float2bfloat16_rn(v.y * di * dj[1]);
    o[2] = __float2bfloat16_rn(v.z * di * dj[2]);
    o[3] = __float2bfloat16_rn(v.w * di * dj[3]);
    int mo = (m & 1) * 8 + (m >> 1);    // output: k*8 + b
    *(uint2*)(g_adj16 + mo * NN + rem) = *(uint2*)o;
}

// folded gate weight, k-major [1536][768] bf16
__global__ void combine_w_kernel(const float* __restrict__ gw) {
    int i = blockIdx.x * blockDim.x + threadIdx.x;
    if (i >= H_ * H_) return;
    int r = i / H_, c = i % H_;
    float w0 = gw[i];
    float w1 = gw[(H_     + r) * H_ + c];
    float w2 = gw[(2 * H_ + r) * H_ + c];
    float w3 = gw[(3 * H_ + r) * H_ + c];
    g_wGate[r * H_ + c]        = __float2bfloat16_rn(w0 + w2 + w3);
    g_wGate[(H_ + r) * H_ + c] = __float2bfloat16_rn(w1 + w2 - w3);
}

// ---------------- epilogue codes ---------------------------------------------
#define EPI_NONE  0
#define EPI_RELU  1
#define EPI_BIAS  2
#define EPI_GELUB 3
#define EPI_GATE  5
// OUTM: 0=f32, 1=bf16, 2=fp8*outscale

__device__ __forceinline__ void cp16(uint32_t sdst, const void* gsrc) {
    asm volatile("cp.async.cg.shared.global [%0], [%1], 16;\n" :: "r"(sdst), "l"(gsrc));
}

__device__ __forceinline__ void mma_bf16(float c[4], const uint32_t a[4],
                                         uint32_t b0, uint32_t b1) {
    asm volatile(
        "mma.sync.aligned.m16n8k16.row.col.f32.bf16.bf16.f32 "
        "{%0,%1,%2,%3}, {%4,%5,%6,%7}, {%8,%9}, {%0,%1,%2,%3};\n"
        : "+f"(c[0]), "+f"(c[1]), "+f"(c[2]), "+f"(c[3])
        : "r"(a[0]), "r"(a[1]), "r"(a[2]), "r"(a[3]), "r"(b0), "r"(b1));
}

// fp8 mma with F16 ACCUMULATORS (2-reg C/D): tests whether the legacy tensor
// path runs f16-accum at 2x the f32-accum rate (as on Ada).
__device__ __forceinline__ void mma_f8_h(uint32_t c[2], const uint32_t a[4],
                                         uint32_t b0, uint32_t b1) {
    asm volatile(
        "mma.sync.aligned.m16n8k32.row.col.f16.e4m3.e4m3.f16 "
        "{%0,%1}, {%2,%3,%4,%5}, {%6,%7}, {%0,%1};\n"
        : "+r"(c[0]), "+r"(c[1])
        : "r"(a[0]), "r"(a[1]), "r"(a[2]), "r"(a[3]), "r"(b0), "r"(b1));
}

// ---------------- bf16 GEMM (adj steps + gate) --------------------------------
#define SMEM_BF_BYTES ((4 * (128 * 40 + 32 * 136)) * 2)   // 75776

template<int EPI, int OUTM>
__global__ __launch_bounds__(256, 2) void gemm_bf(
    const bf16* __restrict__ A, const bf16* __restrict__ Bm,
    void* __restrict__ Cv,
    const float* __restrict__ bias_a, const float* __restrict__ bias_b,
    const float* __restrict__ e1, const float* __restrict__ e2,
    float outscale,
    int N, int K,
    long long sA1, long long sA2, long long sB1, long long sB2,
    long long sC1, long long sC2)
{
    extern __shared__ __align__(16) bf16 smn[];
    const uint32_t sbase = (uint32_t)__cvta_generic_to_shared(smn);

    const long long z  = blockIdx.z;
    const long long hi = z >> 3;
    A  += z * sA1 + hi * sA2;
    Bm += z * sB1 + hi * sB2;
    const long long cOff = z * sC1 + hi * sC2;
    const float* bias = (hi == 0) ? bias_a : bias_b;

    const int tid  = threadIdx.x;
    const int w    = tid >> 5;
    const int lane = tid & 31;
    const int wm   = w & 1;
    const int wn   = w >> 1;
    const int g    = lane >> 2;
    const int tg   = lane & 3;

    const int aRow  = tid >> 1;
    const int aKoff = (tid & 1) * 16;
    const int bRow  = tid >> 3;
    const int bNoff = (tid & 7) * 16;

    const bf16* Ag = A  + ((long long)blockIdx.y * 128 + aRow) * K + aKoff;
    const bf16* Bg = Bm + (long long)bRow * N + blockIdx.x * 128 + bNoff;

    float c[4][4][4];
    #pragma unroll
    for (int mi = 0; mi < 4; mi++)
        #pragma unroll
        for (int ni = 0; ni < 4; ni++)
            #pragma unroll
            for (int u = 0; u < 4; u++) c[mi][ni][u] = 0.0f;

    const int S = K / 32;
    const int lm_r = lane & 15;
    const int lm_c = (lane >> 4) * 8;

    auto stage = [&](int chunk, int st) {
        const bf16* Ap = Ag + chunk * 32;
        const bf16* Bp = Bg + (long long)chunk * 32 * N;
        uint32_t asb = sbase + (st * 5120 + aRow * 40 + aKoff) * 2;
        uint32_t bsb = sbase + (20480 + st * 4352 + bRow * 136 + bNoff) * 2;
        cp16(asb, Ap);
        cp16(asb + 16, Ap + 8);
        cp16(bsb, Bp);
        cp16(bsb + 16, Bp + 8);
        asm volatile("cp.async.commit_group;\n");
    };

    stage(0, 0);
    stage(1, 1);
    stage(2, 2);

    for (int s = 0; s < S; s++) {
        if (s <= S - 3)      asm volatile("cp.async.wait_group 2;\n");
        else if (s == S - 2) asm volatile("cp.async.wait_group 1;\n");
        else                 asm volatile("cp.async.wait_group 0;\n");
        __syncthreads();
        if (s + 3 < S) stage(s + 3, (s + 3) & 3);

        const int buf = s & 3;
        const uint32_t asBase = sbase + (buf * 5120) * 2;
        const uint32_t bsBase = sbase + (20480 + buf * 4352) * 2;

        #pragma unroll
        for (int kk = 0; kk < 2; kk++) {
            uint32_t a[4][4];
            uint32_t b[2][4];
            #pragma unroll
            for (int mi = 0; mi < 4; mi++) {
                uint32_t addr = asBase +
                    ((wm * 64 + mi * 16 + lm_r) * 40 + kk * 16 + lm_c) * 2;
                asm volatile(
                    "ldmatrix.sync.aligned.m8n8.x4.shared.b16 {%0,%1,%2,%3}, [%4];"
                    : "=r"(a[mi][0]), "=r"(a[mi][1]), "=r"(a[mi][2]), "=r"(a[mi][3])
                    : "r"(addr));
            }
            #pragma unroll
            for (int nb = 0; nb < 2; nb++) {
                uint32_t addr = bsBase +
                    ((kk * 16 + lm_r) * 136 + wn * 32 + nb * 16 + lm_c) * 2;
                asm volatile(
                    "ldmatrix.sync.aligned.m8n8.x4.trans.shared.b16 {%0,%1,%2,%3}, [%4];"
                    : "=r"(b[nb][0]), "=r"(b[nb][1]), "=r"(b[nb][2]), "=r"(b[nb][3])
                    : "r"(addr));
            }
            #pragma unroll
            for (int mi = 0; mi < 4; mi++)
                #pragma unroll
                for (int ni = 0; ni < 4; ni++)
                    mma_bf16(c[mi][ni], a[mi],
                             b[ni >> 1][(ni & 1) * 2], b[ni >> 1][(ni & 1) * 2 + 1]);
        }
    }

    #pragma unroll
    for (int mi = 0; mi < 4; mi++) {
        #pragma unroll
        for (int ni = 0; ni < 4; ni++) {
            const int row0 = blockIdx.y * 128 + wm * 64 + mi * 16 + g;
            const int col  = blockIdx.x * 128 + wn * 32 + ni * 8 + 2 * tg;
            float v[4];
            v[0] = c[mi][ni][0]; v[1] = c[mi][ni][1];
            v[2] = c[mi][ni][2]; v[3] = c[mi][ni][3];

            if (EPI == EPI_BIAS || EPI == EPI_GELUB || EPI == EPI_GATE) {
                float b0 = bias[col], b1 = bias[col + 1];
                v[0] += b0; v[1] += b1; v[2] += b0; v[3] += b1;
            }
            if (EPI == EPI_RELU) {
                #pragma unroll
                for (int u = 0; u < 4; u++) v[u] = fmaxf(v[u], 0.0f);
            }
            if (EPI == EPI_GELUB) {
                #pragma unroll
                for (int u = 0; u < 4; u++)
                    v[u] = 0.5f * v[u] * (1.0f + erff(v[u] * 0.70710678118654752f));
            }
            if (EPI == EPI_GATE) {
                long long i0 = (long long)row0 * N + col;
                long long i1 = (long long)(row0 + 8) * N + col;
                float2 p0 = *(const float2*)(e1 + i0);
                float2 p1 = *(const float2*)(e1 + i1);
                float2 q0 = *(const float2*)(e2 + i0);
                float2 q1 = *(const float2*)(e2 + i1);
                float gt;
                gt = 1.0f / (1.0f + expf(-v[0])); v[0] = gt * p0.x + (1.0f - gt) * q0.x;
                gt = 1.0f / (1.0f + expf(-v[1])); v[1] = gt * p0.y + (1.0f - gt) * q0.y;
                gt = 1.0f / (1.0f + expf(-v[2])); v[2] = gt * p1.x + (1.0f - gt) * q1.x;
                gt = 1.0f / (1.0f + expf(-v[3])); v[3] = gt * p1.y + (1.0f - gt) * q1.y;
            }

            if (OUTM == 1) {
                bf16* C = (bf16*)Cv + cOff;
                bf16* C0 = C + (long long)row0 * N + col;
                bf16* C1 = C + (long long)(row0 + 8) * N + col;
                bf16 p0[2] = {__float2bfloat16_rn(v[0]), __float2bfloat16_rn(v[1])};
                bf16 p1[2] = {__float2bfloat16_rn(v[2]), __float2bfloat16_rn(v[3])};
                *(uint32_t*)C0 = *(uint32_t*)p0;
                *(uint32_t*)C1 = *(uint32_t*)p1;
            } else if (OUTM == 2) {
                uint8_t* C = (uint8_t*)Cv + cOff;
                *(uint16_t*)(C + (long long)row0 * N + col) =
                    pack_e4m3x2(v[0] * outscale, v[1] * outscale);
                *(uint16_t*)(C + (long long)(row0 + 8) * N + col) =
                    pack_e4m3x2(v[2] * outscale, v[3] * outscale);
            } else {
                float* C = (float*)Cv + cOff;
                float* C0 = C + (long long)row0 * N + col;
                float* C1 = C + (long long)(row0 + 8) * N + col;
                *(float2*)C0 = make_float2(v[0], v[1]);
                *(float2*)C1 = make_float2(v[2], v[3]);
            }
        }
    }
}

// ---------------- fp8 GEMM with f16 accumulators ------------------------------
// A [M][K] fp8, BT [N][K] fp8 (both K-contiguous). 128x128 tile, BK=64 bytes,
// 4-stage cp.async. Tiles: [128 rows][80B] each (64B data + 16B pad).
#define SMEM_F8_BYTES (8 * 128 * 80)   // 81920

template<int EPI, int OUTM>
__global__ __launch_bounds__(256, 2) void gemm_f8(
    const uint8_t* __restrict__ A, const uint8_t* __restrict__ BT,
    void* __restrict__ Cv,
    const float* __restrict__ bias_a, const float* __restrict__ bias_b,
    float unscale, float outscale,
    int N, int K,
    long long sA1, long long sA2, long long sB2,
    long long sC1)
{
    extern __shared__ __align__(16) uint8_t sm8[];
    const uint32_t sbase = (uint32_t)__cvta_generic_to_shared(sm8);

    const long long z  = blockIdx.z;
    const long long hi = z >> 3;
    A  += z * sA1 + hi * sA2;
    BT += hi * sB2;
    const long long cOff = z * sC1;
    const float* bias = (hi == 0) ? bias_a : bias_b;

    const int tid  = threadIdx.x;
    const int w    = tid >> 5;
    const int lane = tid & 31;
    const int wm   = w & 1;
    const int wn   = w >> 1;
    const int g    = lane >> 2;
    const int tg   = lane & 3;

    const int ldRow = tid >> 1;
    const int ldOff = (tid & 1) * 32;
    const uint8_t* Ag = A  + ((long long)blockIdx.y * 128 + ldRow) * K + ldOff;
    const uint8_t* Bg = BT + ((long long)blockIdx.x * 128 + ldRow) * K + ldOff;

    uint32_t c2[4][4][2];
    #pragma unroll
    for (int mi = 0; mi < 4; mi++)
        #pragma unroll
        for (int ni = 0; ni < 4; ni++) { c2[mi][ni][0] = 0u; c2[mi][ni][1] = 0u; }

    const int S = K / 64;
    const int a_r = lane & 15;
    const int a_h = (lane >> 4) * 16;
    const int b_r = (lane & 7) + ((lane >> 4) << 3);
    const int b_h = ((lane >> 3) & 1) * 16;

    auto stage = [&](int chunk, int st) {
        const uint8_t* Ap = Ag + chunk * 64;
        const uint8_t* Bp = Bg + chunk * 64;
        uint32_t asb = sbase + st * 10240 + ldRow * 80 + ldOff;
        uint32_t bsb = sbase + 40960 + st * 10240 + ldRow * 80 + ldOff;
        cp16(asb, Ap);
        cp16(asb + 16, Ap + 16);
        cp16(bsb, Bp);
        cp16(bsb + 16, Bp + 16);
        asm volatile("cp.async.commit_group;\n");
    };

    stage(0, 0);
    stage(1, 1);
    stage(2, 2);

    for (int s = 0; s < S; s++) {
        if (s <= S - 3)      asm volatile("cp.async.wait_group 2;\n");
        else if (s == S - 2) asm volatile("cp.async.wait_group 1;\n");
        else                 asm volatile("cp.async.wait_group 0;\n");
        __syncthreads();
        if (s + 3 < S) stage(s + 3, (s + 3) & 3);

        const int buf = s & 3;
        const uint32_t asBase = sbase + buf * 10240;
        const uint32_t bsBase = sbase + 40960 + buf * 10240;

        #pragma unroll
        for (int kb = 0; kb < 64; kb += 32) {
            uint32_t a[4][4];
            uint32_t b[2][4];
            #pragma unroll
            for (int mi = 0; mi < 4; mi++) {
                uint32_t addr = asBase + (wm * 64 + mi * 16 + a_r) * 80 + kb + a_h;
                asm volatile(
                    "ldmatrix.sync.aligned.m8n8.x4.shared.b16 {%0,%1,%2,%3}, [%4];"
                    : "=r"(a[mi][0]), "=r"(a[mi][1]), "=r"(a[mi][2]), "=r"(a[mi][3])
                    : "r"(addr));
            }
            #pragma unroll
            for (int nb = 0; nb < 2; nb++) {
                uint32_t addr = bsBase + (wn * 32 + nb * 16 + b_r) * 80 + kb + b_h;
                asm volatile(
                    "ldmatrix.sync.aligned.m8n8.x4.shared.b16 {%0,%1,%2,%3}, [%4];"
                    : "=r"(b[nb][0]), "=r"(b[nb][1]), "=r"(b[nb][2]), "=r"(b[nb][3])
                    : "r"(addr));
            }
            #pragma unroll
            for (int mi = 0; mi < 4; mi++)
                #pragma unroll
                for (int ni = 0; ni < 4; ni++)
                    mma_f8_h(c2[mi][ni], a[mi],
                             b[ni >> 1][(ni & 1) * 2], b[ni >> 1][(ni & 1) * 2 + 1]);
        }
    }

    #pragma unroll
    for (int mi = 0; mi < 4; mi++) {
        #pragma unroll
        for (int ni = 0; ni < 4; ni++) {
            const int row0 = blockIdx.y * 128 + wm * 64 + mi * 16 + g;
            const int col  = blockIdx.x * 128 + wn * 32 + ni * 8 + 2 * tg;
            float2 f01 = __half22float2(*(__half2*)&c2[mi][ni][0]);
            float2 f23 = __half22float2(*(__half2*)&c2[mi][ni][1]);
            float v[4];
            v[0] = f01.x * unscale; v[1] = f01.y * unscale;
            v[2] = f23.x * unscale; v[3] = f23.y * unscale;

            if (EPI == EPI_BIAS || EPI == EPI_GELUB) {
                float b0 = bias[col], b1 = bias[col + 1];
                v[0] += b0; v[1] += b1; v[2] += b0; v[3] += b1;
            }
            if (EPI == EPI_RELU) {
                #pragma unroll
                for (int u = 0; u < 4; u++) v[u] = fmaxf(v[u], 0.0f);
            }
            if (EPI == EPI_GELUB) {
                #pragma unroll
                for (int u = 0; u < 4; u++)
                    v[u] = 0.5f * v[u] * (1.0f + erff(v[u] * 0.70710678118654752f));
            }

            if (OUTM == 1) {
                bf16* C = (bf16*)Cv + cOff;
                bf16* C0 = C + (long long)row0 * N + col;
                bf16* C1 = C + (long long)(row0 + 8) * N + col;
                bf16 p0[2] = {__float2bfloat16_rn(v[0]), __float2bfloat16_rn(v[1])};
                bf16 p1[2] = {__float2bfloat16_rn(v[2]), __float2bfloat16_rn(v[3])};
                *(uint32_t*)C0 = *(uint32_t*)p0;
                *(uint32_t*)C1 = *(uint32_t*)p1;
            } else if (OUTM == 2) {
                uint8_t* C = (uint8_t*)Cv + cOff;
                *(uint16_t*)(C + (long long)row0 * N + col) =
                    pack_e4m3x2(v[0] * outscale, v[1] * outscale);
                *(uint16_t*)(C + (long long)(row0 + 8) * N + col) =
                    pack_e4m3x2(v[2] * outscale, v[3] * outscale);
            } else {
                float* C = (float*)Cv + cOff;
                float* C0 = C + (long long)row0 * N + col;
                float* C1 = C + (long long)(row0 + 8) * N + col;
                *(float2*)C0 = make_float2(v[0], v[1]);
                *(float2*)C1 = make_float2(v[2], v[3]);
            }
        }
    }
}

// ---------------- merged layernorm: y=0 -> LN1, y=1 -> LN2 --------------------
__global__ void ln_kernel(const float* __restrict__ nodes, const float* __restrict__ hf,
                          const float* __restrict__ g1v, const float* __restrict__ b1v,
                          const float* __restrict__ g2v, const float* __restrict__ b2v,
                          float* __restrict__ ln1f, float* __restrict__ ln2f,
                          bf16* __restrict__ cat)
{
    const int k = blockIdx.y;
    long long row = blockIdx.x;
    long long b = row >> 10;
    int n = (int)(row & 1023);
    const float* np = nodes + row * H_;
    const float* hp = hf + (((long long)k * 8 + b) * 1024 + n) * H_;
    float* opf = (k ? ln2f : ln1f) + row * H_;
    bf16* op16 = cat + row * (2 * H_) + k * H_;
    const float* g = k ? g2v : g1v;
    const float* bb = k ? b2v : b1v;
    int t = threadIdx.x;

    float x[3];
    float s = 0.0f;
    #pragma unroll
    for (int i = 0; i < 3; i++) {
        int c = t + i * 256;
        x[i] = np[c] + hp[c];
        s += x[i];
    }
    __shared__ float sm[32];
    s = blockReduceSum(s, sm);
    float mu = s * (1.0f / H_);
    float v = 0.0f;
    #pragma unroll
    for (int i = 0; i < 3; i++) {
        float d = x[i] - mu;
        v += d * d;
    }
    v = blockReduceSum(v, sm);
    float rs = rsqrtf(v * (1.0f / H_) + 1e-12f);
    #pragma unroll
    for (int i = 0; i < 3; i++) {
        int c = t + i * 256;
        float o = (x[i] - mu) * rs * g[c] + bb[c];
        opf[c] = o;
        op16[c] = __float2bfloat16_rn(o);
    }
}

// ---------------- launcher ---------------------------------------------------
extern "C" void kernel_launch(void* const* d_in, const int* in_sizes, int n_in,
                              void* d_out, int out_size)
{
    (void)in_sizes; (void)n_in; (void)out_size;
    const float* nodes   = (const float*)d_in[0];
    const float* graphs  = (const float*)d_in[1];
    const float* gcn1_w1 = (const float*)d_in[2];
    const float* gcn1_w2 = (const float*)d_in[3];
    const float* gcn2_w1 = (const float*)d_in[4];
    const float* gcn2_w2 = (const float*)d_in[5];
    const float* exp1_w  = (const float*)d_in[6];
    const float* exp1_b  = (const float*)d_in[7];
    const float* col1_w  = (const float*)d_in[8];
    const float* col1_b  = (const float*)d_in[9];
    const float* exp2_w  = (const float*)d_in[10];
    const float* exp2_b  = (const float*)d_in[11];
    const float* col2_w  = (const float*)d_in[12];
    const float* col2_b  = (const float*)d_in[13];
    const float* gate_w  = (const float*)d_in[14];
    const float* gate_b  = (const float*)d_in[15];
    const float* ln1_g   = (const float*)d_in[16];
    const float* ln1_b   = (const float*)d_in[17];
    const float* ln2_g   = (const float*)d_in[18];
    const float* ln2_b   = (const float*)d_in[19];
    float* out = (float*)d_out;

    bf16 *adj16, *nodes16, *wGate, *h16, *cat16;
    uint8_t *w1f8, *w2f8, *wef8, *wcf8, *act8, *big8;
    float *hf, *ln1f, *ln2f;
    cudaGetSymbolAddress((void**)&adj16,   g_adj16);
    cudaGetSymbolAddress((void**)&nodes16, g_nodes16);
    cudaGetSymbolAddress((void**)&wGate, g_wGate);
    cudaGetSymbolAddress((void**)&w1f8, g_w1f8);
    cudaGetSymbolAddress((void**)&w2f8, g_w2f8);
    cudaGetSymbolAddress((void**)&wef8, g_wef8);
    cudaGetSymbolAddress((void**)&wcf8, g_wcf8);
    cudaGetSymbolAddress((void**)&act8, g_act8);
    cudaGetSymbolAddress((void**)&big8, g_big8);
    cudaGetSymbolAddress((void**)&h16,   g_h16);
    cudaGetSymbolAddress((void**)&cat16, g_cat16);
    cudaGetSymbolAddress((void**)&hf,   g_hf);
    cudaGetSymbolAddress((void**)&ln1f, g_ln1f);
    cudaGetSymbolAddress((void**)&ln2f, g_ln2f);

    const int SMB  = SMEM_BF_BYTES;
    const int SMB8 = SMEM_F8_BYTES;
    cudaFuncSetAttribute(gemm_bf<EPI_NONE, 2>, cudaFuncAttributeMaxDynamicSharedMemorySize, SMB);
    cudaFuncSetAttribute(gemm_bf<EPI_RELU, 2>, cudaFuncAttributeMaxDynamicSharedMemorySize, SMB);
    cudaFuncSetAttribute(gemm_bf<EPI_GATE, 0>, cudaFuncAttributeMaxDynamicSharedMemorySize, SMB);
    cudaFuncSetAttribute(gemm_f8<EPI_RELU, 2>, cudaFuncAttributeMaxDynamicSharedMemorySize, SMB8);
    cudaFuncSetAttribute(gemm_f8<EPI_NONE, 1>, cudaFuncAttributeMaxDynamicSharedMemorySize, SMB8);
    cudaFuncSetAttribute(gemm_f8<EPI_GELUB,2>, cudaFuncAttributeMaxDynamicSharedMemorySize, SMB8);
    cudaFuncSetAttribute(gemm_f8<EPI_BIAS, 0>, cudaFuncAttributeMaxDynamicSharedMemorySize, SMB8);

    const long long MN  = (long long)B_ * N_;     // 8192
    const long long sNH = (long long)N_ * H_;
    const long long sNI = (long long)N_ * I_;
    const long long IH  = (long long)I_ * H_;

    // ---- prologue ----
    {
        long long n4 = MN * H_ / 4;
        f2bf_kernel<<<(unsigned)((n4 + 255) / 256), 256>>>(nodes, nodes16, n4);
    }
    {
        // one launch for all 8 weight transposes (2304 tiles each)
        dim3 tb(32, 8);
        dim3 grid(2304, 1, 8);
        transpose_f8_all<<<grid, tb>>>(gcn1_w1, gcn2_w1, exp1_w, exp2_w,
                                       gcn1_w2, gcn2_w2, col1_w, col2_w);
    }
    combine_w_kernel<<<(H_ * H_ + 255) / 256, 256>>>(gate_w);
    rowsum_dinv_kernel<<<NMAT * N_ / 8, 256>>>(graphs);
    long long total4 = (long long)NMAT * NN / 4;
    normalize_adj_kernel<<<(unsigned)((total4 + 255) / 256), 256>>>(graphs);

    // ---- batched dual-GCN chain (z = k*8 + b over 16 slices) ----
    // 1) adjX = adj @ nodes -> fp8*32   [z][1024][768]
    gemm_bf<EPI_NONE, 2><<<dim3(H_/128, N_/128, NMAT), 256, SMB>>>(
        adj16, nodes16, act8, nullptr, nullptr, nullptr, nullptr, S_ADJX,
        H_, N_, NN, 0, sNH, -8 * sNH, sNH, 0);
    // 2) x1 = relu(adjX @ W1) fp8 -> fp8*64   [z][1024][3072]
    gemm_f8<EPI_RELU, 2><<<dim3(I_/128, N_/128, NMAT), 256, SMB8>>>(
        act8, w1f8, big8, nullptr, nullptr, 1.0f/(S_ADJX*S_W), S_X1,
        I_, H_, sNH, 0, IH, sNI);
    // 3) t2p = x1 @ W2 fp8 -> bf16   [z][1024][768]
    gemm_f8<EPI_NONE, 1><<<dim3(H_/128, N_/128, NMAT), 256, SMB8>>>(
        big8, w2f8, h16, nullptr, nullptr, 1.0f/(S_X1*S_W), 0.0f,
        H_, I_, sNI, 0, IH, sNH);
    // 4) gc = relu(adj @ t2p) bf16 -> fp8*256   [z][1024][768]
    gemm_bf<EPI_RELU, 2><<<dim3(H_/128, N_/128, NMAT), 256, SMB>>>(
        adj16, h16, act8, nullptr, nullptr, nullptr, nullptr, S_GC,
        H_, N_, NN, 0, sNH, 0, sNH, 0);
    // 5) t3 = gelu(gc @ We + be) fp8 -> fp8*1024   [z][1024][3072]
    gemm_f8<EPI_GELUB, 2><<<dim3(I_/128, N_/128, NMAT), 256, SMB8>>>(
        act8, wef8, big8, exp1_b, exp2_b, 1.0f/(S_GC*S_W), S_T3,
        I_, H_, sNH, 0, IH, sNI);
    // 6) hf = t3 @ Wc + bc fp8 -> f32   [z][1024][768]
    gemm_f8<EPI_BIAS, 0><<<dim3(H_/128, N_/128, NMAT), 256, SMB8>>>(
        big8, wcf8, hf, col1_b, col2_b, 1.0f/(S_T3*S_W), 0.0f,
        H_, I_, sNI, 0, IH, sNH);

    // 7) both LayerNorms
    ln_kernel<<<dim3((unsigned)MN, 2), 256>>>(nodes, hf, ln1_g, ln1_b, ln2_g, ln2_b,
                                              ln1f, ln2f, cat16);

    // 8) fused gate (bf16): out = sigmoid(cat @ Wgate + gb) blended with ln1f/ln2f
    gemm_bf<EPI_GATE, 0><<<dim3(H_/128, (unsigned)(MN/128), 1), 256, SMB>>>(
        cat16, wGate, out, gate_b, nullptr, ln1f, ln2f, 0.0f,
        H_, 2 * H_, 0, 0, 0, 0, 0, 0);
}

// round 15
// speedup vs baseline: 8.5004x; 1.0674x over previous
#include <cuda_runtime.h>
#include <cuda_bf16.h>
#include <cuda_fp16.h>
#include <math.h>
#include <stdint.h>

// Problem dims
#define B_ 8
#define N_ 1024
#define H_ 768
#define I_ 3072
#define NMAT 16
#define NN (1024LL*1024LL)
#define HI_ ((long long)H_ * I_)

typedef __nv_bfloat16 bf16;

// ---------------- scratch (static device globals) ----------------------------
__device__ bf16  g_adj16[(size_t)NMAT * 1024 * 1024];   // [k][b][N][N]
__device__ float g_dinv[NMAT * N_];
__device__ bf16  g_nodes16[(size_t)B_ * N_ * H_];
// fp8 transposed weights [slot][N][K]
__device__ uint8_t g_w1f8[(size_t)2 * I_ * H_];
__device__ uint8_t g_w2f8[(size_t)2 * H_ * I_];
__device__ uint8_t g_wef8[(size_t)2 * I_ * H_];
__device__ uint8_t g_wcf8[(size_t)2 * H_ * I_];
__device__ bf16  g_wGate[2 * H_ * H_];
// activations, [k][b] slices
__device__ bf16  g_h16 [(size_t)NMAT * N_ * H_];
__device__ uint8_t g_act8[(size_t)NMAT * N_ * H_];
__device__ uint8_t g_big8[(size_t)NMAT * N_ * I_];
__device__ float g_hf  [(size_t)NMAT * N_ * H_];
__device__ bf16  g_cat16[(size_t)B_ * N_ * 2 * H_];
__device__ float g_ln1f[(size_t)B_ * N_ * H_];
__device__ float g_ln2f[(size_t)B_ * N_ * H_];

// fp8 scales (powers of two)
#define S_ADJX 32.0f
#define S_W    64.0f
#define S_X1   64.0f
#define S_GC   256.0f
#define S_T3   1024.0f

// ---------------- reductions ------------------------------------------------
__inline__ __device__ float warpReduceSum(float v) {
    #pragma unroll
    for (int o = 16; o > 0; o >>= 1) v += __shfl_xor_sync(0xFFFFFFFFu, v, o);
    return v;
}
__device__ float blockReduceSum(float v, float* sm) {
    __syncthreads();
    int lane = threadIdx.x & 31, w = threadIdx.x >> 5;
    v = warpReduceSum(v);
    if (lane == 0) sm[w] = v;
    __syncthreads();
    if (w == 0) {
        float t = (lane < 8) ? sm[lane] : 0.0f;
        t = warpReduceSum(t);
        if (lane == 0) sm[0] = t;
    }
    __syncthreads();
    return sm[0];
}

// ---------------- fp8 pack helper --------------------------------------------
__device__ __forceinline__ uint16_t pack_e4m3x2(float lo, float hi) {
    uint16_t p;
    asm("cvt.rn.satfinite.e4m3x2.f32 %0, %1, %2;" : "=h"(p) : "f"(hi), "f"(lo));
    return p;
}

// ---------------- prologue kernels -------------------------------------------
__global__ void f2bf_kernel(const float* __restrict__ in, bf16* __restrict__ out, long long n4) {
    long long i = (long long)blockIdx.x * blockDim.x + threadIdx.x;
    if (i >= n4) return;
    float4 v = *(const float4*)(in + i * 4);
    bf16 o[4];
    o[0] = __float2bfloat16_rn(v.x); o[1] = __float2bfloat16_rn(v.y);
    o[2] = __float2bfloat16_rn(v.z); o[3] = __float2bfloat16_rn(v.w);
    *(uint2*)(out + i * 4) = *(uint2*)o;
}

// ALL 8 weight transposes in one launch (blockIdx.z selects matrix).
__global__ void transpose_f8_all(
    const float* __restrict__ s0, const float* __restrict__ s1,
    const float* __restrict__ s2, const float* __restrict__ s3,
    const float* __restrict__ s4, const float* __restrict__ s5,
    const float* __restrict__ s6, const float* __restrict__ s7)
{
    __shared__ float tile[32][33];
    const int zi = blockIdx.z;
    const float* srcs[8] = {s0, s1, s2, s3, s4, s5, s6, s7};
    uint8_t* dsts[8] = {g_w1f8, g_w1f8 + HI_, g_wef8, g_wef8 + HI_,
                        g_w2f8, g_w2f8 + HI_, g_wcf8, g_wcf8 + HI_};
    const float* in = srcs[zi];
    uint8_t* out = dsts[zi];
    const int R = (zi < 4) ? H_ : I_;
    const int C = (zi < 4) ? I_ : H_;
    const int tilesX = C / 32;
    int bid = blockIdx.x;
    int bx = (bid % tilesX) * 32, by = (bid / tilesX) * 32;
    int x = threadIdx.x, y = threadIdx.y;
    #pragma unroll
    for (int j = 0; j < 32; j += 8)
        tile[y + j][x] = in[(long long)(by + y + j) * C + bx + x];
    __syncthreads();
    #pragma unroll
    for (int j = 0; j < 32; j += 8) {
        uint16_t p = pack_e4m3x2(tile[x][y + j] * S_W, 0.0f);
        out[(long long)(bx + y + j) * R + by + x] = (uint8_t)(p & 0xFF);
    }
}

__global__ void rowsum_dinv_kernel(const float* __restrict__ A) {
    int w = threadIdx.x >> 5, lane = threadIdx.x & 31;
    long long row = (long long)blockIdx.x * 8 + w;
    const float* p = A + row * (long long)N_;
    float s = 0.0f;
    #pragma unroll
    for (int i = 0; i < 8; i++) {
        float4 v = *(const float4*)(p + (lane + i * 32) * 4);
        s += v.x + v.y + v.z + v.w;
    }
    s = warpReduceSum(s);
    if (lane == 0) g_dinv[row] = 1.0f / sqrtf(s);
}

// reads graphs in [b][k] order, writes g_adj16 in [k][b] order
__global__ void normalize_adj_kernel(const float* __restrict__ A) {
    long long i4 = (long long)blockIdx.x * blockDim.x + threadIdx.x;
    long long total4 = (long long)NMAT * NN / 4;
    if (i4 >= total4) return;
    long long e = i4 * 4;
    int  m = (int)(e / NN);
    long long rem = e % NN;
    int  r = (int)(rem / N_);
    int  c = (int)(rem % N_);
    float di = g_dinv[m * N_ + r];
    const float* dj = &g_dinv[m * N_ + c];
    float4 v = *(const float4*)(A + e);
    bf16 o[4];
    o[0] = __float2bfloat16_rn(v.x * di * dj[0]);
    o[1] = __float2bfloat16_rn(v.y * di * dj[1]);
    o[2] = __float2bfloat16_rn(v.z * di * dj[2]);
    o[3] = __float2bfloat16_rn(v.w * di * dj[3]);
    int mo = (m & 1) * 8 + (m >> 1);
    *(uint2*)(g_adj16 + mo * NN + rem) = *(uint2*)o;
}

// folded gate weight, k-major [1536][768] bf16
__global__ void combine_w_kernel(const float* __restrict__ gw) {
    int i = blockIdx.x * blockDim.x + threadIdx.x;
    if (i >= H_ * H_) return;
    int r = i / H_, c = i % H_;
    float w0 = gw[i];
    float w1 = gw[(H_     + r) * H_ + c];
    float w2 = gw[(2 * H_ + r) * H_ + c];
    float w3 = gw[(3 * H_ + r) * H_ + c];
    g_wGate[r * H_ + c]        = __float2bfloat16_rn(w0 + w2 + w3);
    g_wGate[(H_ + r) * H_ + c] = __float2bfloat16_rn(w1 + w2 - w3);
}

// ---------------- epilogue codes ---------------------------------------------
#define EPI_NONE  0
#define EPI_RELU  1
#define EPI_BIAS  2
#define EPI_GELUB 3
#define EPI_GATE  5
// OUTM: 0=f32, 1=bf16, 2=fp8*outscale

__device__ __forceinline__ void cp16(uint32_t sdst, const void* gsrc) {
    asm volatile("cp.async.cg.shared.global [%0], [%1], 16;\n" :: "r"(sdst), "l"(gsrc));
}

__device__ __forceinline__ void mma_bf16(float c[4], const uint32_t a[4],
                                         uint32_t b0, uint32_t b1) {
    asm volatile(
        "mma.sync.aligned.m16n8k16.row.col.f32.bf16.bf16.f32 "
        "{%0,%1,%2,%3}, {%4,%5,%6,%7}, {%8,%9}, {%0,%1,%2,%3};\n"
        : "+f"(c[0]), "+f"(c[1]), "+f"(c[2]), "+f"(c[3])
        : "r"(a[0]), "r"(a[1]), "r"(a[2]), "r"(a[3]), "r"(b0), "r"(b1));
}

__device__ __forceinline__ void mma_f8_h(uint32_t c[2], const uint32_t a[4],
                                         uint32_t b0, uint32_t b1) {
    asm volatile(
        "mma.sync.aligned.m16n8k32.row.col.f16.e4m3.e4m3.f16 "
        "{%0,%1}, {%2,%3,%4,%5}, {%6,%7}, {%0,%1};\n"
        : "+r"(c[0]), "+r"(c[1])
        : "r"(a[0]), "r"(a[1]), "r"(a[2]), "r"(a[3]), "r"(b0), "r"(b1));
}

// ---------------- bf16 GEMM, MT-row tiles (adj steps + gate) -------------------
// MT in {128, 64}. 8 warps (2 x 4), warp covers (MT/2) x 32.
#define SMEM_BF_BYTES(MT) ((4 * ((MT) * 40 + 32 * 136)) * 2)

template<int EPI, int OUTM, int MT>
__global__ __launch_bounds__(256, 2) void gemm_bf(
    const bf16* __restrict__ A, const bf16* __restrict__ Bm,
    void* __restrict__ Cv,
    const float* __restrict__ bias,
    const float* __restrict__ e1, const float* __restrict__ e2,
    float outscale,
    int N, int K,
    long long sA1, long long sB1, long long sC1)
{
    extern __shared__ __align__(16) bf16 smn[];
    const uint32_t sbase = (uint32_t)__cvta_generic_to_shared(smn);
    constexpr int AS = MT * 40;        // A stage stride (elems)
    constexpr int BBASE = 4 * AS;      // B region base (elems)
    constexpr int MI = MT / 32;        // m-frags per warp

    const long long z = blockIdx.z;
    A  += z * sA1;
    Bm += z * sB1;
    const long long cOff = z * sC1;

    const int tid  = threadIdx.x;
    const int w    = tid >> 5;
    const int lane = tid & 31;
    const int wm   = w & 1;
    const int wn   = w >> 1;
    const int g    = lane >> 2;
    const int tg   = lane & 3;

    const int aRow  = (MT == 128) ? (tid >> 1) : (tid >> 2);
    const int aKoff = (MT == 128) ? (tid & 1) * 16 : (tid & 3) * 8;
    const int bRow  = tid >> 3;
    const int bNoff = (tid & 7) * 16;

    const bf16* Ag = A  + ((long long)blockIdx.y * MT + aRow) * K + aKoff;
    const bf16* Bg = Bm + (long long)bRow * N + blockIdx.x * 128 + bNoff;

    float c[MI][4][4];
    #pragma unroll
    for (int mi = 0; mi < MI; mi++)
        #pragma unroll
        for (int ni = 0; ni < 4; ni++)
            #pragma unroll
            for (int u = 0; u < 4; u++) c[mi][ni][u] = 0.0f;

    const int S = K / 32;
    const int lm_r = lane & 15;
    const int lm_c = (lane >> 4) * 8;

    auto stage = [&](int chunk, int st) {
        const bf16* Ap = Ag + chunk * 32;
        const bf16* Bp = Bg + (long long)chunk * 32 * N;
        uint32_t asb = sbase + (st * AS + aRow * 40 + aKoff) * 2;
        uint32_t bsb = sbase + (BBASE + st * 4352 + bRow * 136 + bNoff) * 2;
        cp16(asb, Ap);
        if (MT == 128) cp16(asb + 16, Ap + 8);
        cp16(bsb, Bp);
        cp16(bsb + 16, Bp + 8);
        asm volatile("cp.async.commit_group;\n");
    };

    stage(0, 0);
    stage(1, 1);
    stage(2, 2);

    for (int s = 0; s < S; s++) {
        if (s <= S - 3)      asm volatile("cp.async.wait_group 2;\n");
        else if (s == S - 2) asm volatile("cp.async.wait_group 1;\n");
        else                 asm volatile("cp.async.wait_group 0;\n");
        __syncthreads();
        if (s + 3 < S) stage(s + 3, (s + 3) & 3);

        const int buf = s & 3;
        const uint32_t asBase = sbase + (buf * AS) * 2;
        const uint32_t bsBase = sbase + (BBASE + buf * 4352) * 2;

        #pragma unroll
        for (int kk = 0; kk < 2; kk++) {
            uint32_t a[MI][4];
            uint32_t b[2][4];
            #pragma unroll
            for (int mi = 0; mi < MI; mi++) {
                uint32_t addr = asBase +
                    ((wm * (MT / 2) + mi * 16 + lm_r) * 40 + kk * 16 + lm_c) * 2;
                asm volatile(
                    "ldmatrix.sync.aligned.m8n8.x4.shared.b16 {%0,%1,%2,%3}, [%4];"
                    : "=r"(a[mi][0]), "=r"(a[mi][1]), "=r"(a[mi][2]), "=r"(a[mi][3])
                    : "r"(addr));
            }
            #pragma unroll
            for (int nb = 0; nb < 2; nb++) {
                uint32_t addr = bsBase +
                    ((kk * 16 + lm_r) * 136 + wn * 32 + nb * 16 + lm_c) * 2;
                asm volatile(
                    "ldmatrix.sync.aligned.m8n8.x4.trans.shared.b16 {%0,%1,%2,%3}, [%4];"
                    : "=r"(b[nb][0]), "=r"(b[nb][1]), "=r"(b[nb][2]), "=r"(b[nb][3])
                    : "r"(addr));
            }
            #pragma unroll
            for (int mi = 0; mi < MI; mi++)
                #pragma unroll
                for (int ni = 0; ni < 4; ni++)
                    mma_bf16(c[mi][ni], a[mi],
                             b[ni >> 1][(ni & 1) * 2], b[ni >> 1][(ni & 1) * 2 + 1]);
        }
    }

    #pragma unroll
    for (int mi = 0; mi < MI; mi++) {
        #pragma unroll
        for (int ni = 0; ni < 4; ni++) {
            const int row0 = blockIdx.y * MT + wm * (MT / 2) + mi * 16 + g;
            const int col  = blockIdx.x * 128 + wn * 32 + ni * 8 + 2 * tg;
            float v[4];
            v[0] = c[mi][ni][0]; v[1] = c[mi][ni][1];
            v[2] = c[mi][ni][2]; v[3] = c[mi][ni][3];

            if (EPI == EPI_BIAS || EPI == EPI_GELUB || EPI == EPI_GATE) {
                float b0 = bias[col], b1 = bias[col + 1];
                v[0] += b0; v[1] += b1; v[2] += b0; v[3] += b1;
            }
            if (EPI == EPI_RELU) {
                #pragma unroll
                for (int u = 0; u < 4; u++) v[u] = fmaxf(v[u], 0.0f);
            }
            if (EPI == EPI_GELUB) {
                #pragma unroll
                for (int u = 0; u < 4; u++)
                    v[u] = 0.5f * v[u] * (1.0f + erff(v[u] * 0.70710678118654752f));
            }
            if (EPI == EPI_GATE) {
                long long i0 = (long long)row0 * N + col;
                long long i1 = (long long)(row0 + 8) * N + col;
                float2 p0 = *(const float2*)(e1 + i0);
                float2 p1 = *(const float2*)(e1 + i1);
                float2 q0 = *(const float2*)(e2 + i0);
                float2 q1 = *(const float2*)(e2 + i1);
                float gt;
                gt = 1.0f / (1.0f + expf(-v[0])); v[0] = gt * p0.x + (1.0f - gt) * q0.x;
                gt = 1.0f / (1.0f + expf(-v[1])); v[1] = gt * p0.y + (1.0f - gt) * q0.y;
                gt = 1.0f / (1.0f + expf(-v[2])); v[2] = gt * p1.x + (1.0f - gt) * q1.x;
                gt = 1.0f / (1.0f + expf(-v[3])); v[3] = gt * p1.y + (1.0f - gt) * q1.y;
            }

            if (OUTM == 1) {
                bf16* C = (bf16*)Cv + cOff;
                bf16* C0 = C + (long long)row0 * N + col;
                bf16* C1 = C + (long long)(row0 + 8) * N + col;
                bf16 p0[2] = {__float2bfloat16_rn(v[0]), __float2bfloat16_rn(v[1])};
                bf16 p1[2] = {__float2bfloat16_rn(v[2]), __float2bfloat16_rn(v[3])};
                *(uint32_t*)C0 = *(uint32_t*)p0;
                *(uint32_t*)C1 = *(uint32_t*)p1;
            } else if (OUTM == 2) {
                uint8_t* C = (uint8_t*)Cv + cOff;
                *(uint16_t*)(C + (long long)row0 * N + col) =
                    pack_e4m3x2(v[0] * outscale, v[1] * outscale);
                *(uint16_t*)(C + (long long)(row0 + 8) * N + col) =
                    pack_e4m3x2(v[2] * outscale, v[3] * outscale);
            } else {
                float* C = (float*)Cv + cOff;
                float* C0 = C + (long long)row0 * N + col;
                float* C1 = C + (long long)(row0 + 8) * N + col;
                *(float2*)C0 = make_float2(v[0], v[1]);
                *(float2*)C1 = make_float2(v[2], v[3]);
            }
        }
    }
}

// ---------------- fp8 GEMM with f16 accumulators ------------------------------
#define SMEM_F8_BYTES (8 * 128 * 80)   // 81920

template<int EPI, int OUTM>
__global__ __launch_bounds__(256, 2) void gemm_f8(
    const uint8_t* __restrict__ A, const uint8_t* __restrict__ BT,
    void* __restrict__ Cv,
    const float* __restrict__ bias,
    float unscale, float outscale,
    int N, int K,
    long long sA1, long long sC1)
{
    extern __shared__ __align__(16) uint8_t sm8[];
    const uint32_t sbase = (uint32_t)__cvta_generic_to_shared(sm8);

    const long long z = blockIdx.z;
    A += z * sA1;
    const long long cOff = z * sC1;

    const int tid  = threadIdx.x;
    const int w    = tid >> 5;
    const int lane = tid & 31;
    const int wm   = w & 1;
    const int wn   = w >> 1;
    const int g    = lane >> 2;
    const int tg   = lane & 3;

    const int ldRow = tid >> 1;
    const int ldOff = (tid & 1) * 32;
    const uint8_t* Ag = A  + ((long long)blockIdx.y * 128 + ldRow) * K + ldOff;
    const uint8_t* Bg = BT + ((long long)blockIdx.x * 128 + ldRow) * K + ldOff;

    uint32_t c2[4][4][2];
    #pragma unroll
    for (int mi = 0; mi < 4; mi++)
        #pragma unroll
        for (int ni = 0; ni < 4; ni++) { c2[mi][ni][0] = 0u; c2[mi][ni][1] = 0u; }

    const int S = K / 64;
    const int a_r = lane & 15;
    const int a_h = (lane >> 4) * 16;
    const int b_r = (lane & 7) + ((lane >> 4) << 3);
    const int b_h = ((lane >> 3) & 1) * 16;

    auto stage = [&](int chunk, int st) {
        const uint8_t* Ap = Ag + chunk * 64;
        const uint8_t* Bp = Bg + chunk * 64;
        uint32_t asb = sbase + st * 10240 + ldRow * 80 + ldOff;
        uint32_t bsb = sbase + 40960 + st * 10240 + ldRow * 80 + ldOff;
        cp16(asb, Ap);
        cp16(asb + 16, Ap + 16);
        cp16(bsb, Bp);
        cp16(bsb + 16, Bp + 16);
        asm volatile("cp.async.commit_group;\n");
    };

    stage(0, 0);
    stage(1, 1);
    stage(2, 2);

    for (int s = 0; s < S; s++) {
        if (s <= S - 3)      asm volatile("cp.async.wait_group 2;\n");
        else if (s == S - 2) asm volatile("cp.async.wait_group 1;\n");
        else                 asm volatile("cp.async.wait_group 0;\n");
        __syncthreads();
        if (s + 3 < S) stage(s + 3, (s + 3) & 3);

        const int buf = s & 3;
        const uint32_t asBase = sbase + buf * 10240;
        const uint32_t bsBase = sbase + 40960 + buf * 10240;

        #pragma unroll
        for (int kb = 0; kb < 64; kb += 32) {
            uint32_t a[4][4];
            uint32_t b[2][4];
            #pragma unroll
            for (int mi = 0; mi < 4; mi++) {
                uint32_t addr = asBase + (wm * 64 + mi * 16 + a_r) * 80 + kb + a_h;
                asm volatile(
                    "ldmatrix.sync.aligned.m8n8.x4.shared.b16 {%0,%1,%2,%3}, [%4];"
                    : "=r"(a[mi][0]), "=r"(a[mi][1]), "=r"(a[mi][2]), "=r"(a[mi][3])
                    : "r"(addr));
            }
            #pragma unroll
            for (int nb = 0; nb < 2; nb++) {
                uint32_t addr = bsBase + (wn * 32 + nb * 16 + b_r) * 80 + kb + b_h;
                asm volatile(
                    "ldmatrix.sync.aligned.m8n8.x4.shared.b16 {%0,%1,%2,%3}, [%4];"
                    : "=r"(b[nb][0]), "=r"(b[nb][1]), "=r"(b[nb][2]), "=r"(b[nb][3])
                    : "r"(addr));
            }
            #pragma unroll
            for (int mi = 0; mi < 4; mi++)
                #pragma unroll
                for (int ni = 0; ni < 4; ni++)
                    mma_f8_h(c2[mi][ni], a[mi],
                             b[ni >> 1][(ni & 1) * 2], b[ni >> 1][(ni & 1) * 2 + 1]);
        }
    }

    #pragma unroll
    for (int mi = 0; mi < 4; mi++) {
        #pragma unroll
        for (int ni = 0; ni < 4; ni++) {
            const int row0 = blockIdx.y * 128 + wm * 64 + mi * 16 + g;
            const int col  = blockIdx.x * 128 + wn * 32 + ni * 8 + 2 * tg;
            float2 f01 = __half22float2(*(__half2*)&c2[mi][ni][0]);
            float2 f23 = __half22float2(*(__half2*)&c2[mi][ni][1]);
            float v[4];
            v[0] = f01.x * unscale; v[1] = f01.y * unscale;
            v[2] = f23.x * unscale; v[3] = f23.y * unscale;

            if (EPI == EPI_BIAS || EPI == EPI_GELUB) {
                float b0 = bias[col], b1 = bias[col + 1];
                v[0] += b0; v[1] += b1; v[2] += b0; v[3] += b1;
            }
            if (EPI == EPI_RELU) {
                #pragma unroll
                for (int u = 0; u < 4; u++) v[u] = fmaxf(v[u], 0.0f);
            }
            if (EPI == EPI_GELUB) {
                #pragma unroll
                for (int u = 0; u < 4; u++)
                    v[u] = 0.5f * v[u] * (1.0f + erff(v[u] * 0.70710678118654752f));
            }

            if (OUTM == 1) {
                bf16* C = (bf16*)Cv + cOff;
                bf16* C0 = C + (long long)row0 * N + col;
                bf16* C1 = C + (long long)(row0 + 8) * N + col;
                bf16 p0[2] = {__float2bfloat16_rn(v[0]), __float2bfloat16_rn(v[1])};
                bf16 p1[2] = {__float2bfloat16_rn(v[2]), __float2bfloat16_rn(v[3])};
                *(uint32_t*)C0 = *(uint32_t*)p0;
                *(uint32_t*)C1 = *(uint32_t*)p1;
            } else if (OUTM == 2) {
                uint8_t* C = (uint8_t*)Cv + cOff;
                *(uint16_t*)(C + (long long)row0 * N + col) =
                    pack_e4m3x2(v[0] * outscale, v[1] * outscale);
                *(uint16_t*)(C + (long long)(row0 + 8) * N + col) =
                    pack_e4m3x2(v[2] * outscale, v[3] * outscale);
            } else {
                float* C = (float*)Cv + cOff;
                float* C0 = C + (long long)row0 * N + col;
                float* C1 = C + (long long)(row0 + 8) * N + col;
                *(float2*)C0 = make_float2(v[0], v[1]);
                *(float2*)C1 = make_float2(v[2], v[3]);
            }
        }
    }
}

// ---------------- merged layernorm: y=0 -> LN1, y=1 -> LN2 --------------------
__global__ void ln_kernel(const float* __restrict__ nodes, const float* __restrict__ hf,
                          const float* __restrict__ g1v, const float* __restrict__ b1v,
                          const float* __restrict__ g2v, const float* __restrict__ b2v,
                          float* __restrict__ ln1f, float* __restrict__ ln2f,
                          bf16* __restrict__ cat)
{
    const int k = blockIdx.y;
    long long row = blockIdx.x;
    long long b = row >> 10;
    int n = (int)(row & 1023);
    const float* np = nodes + row * H_;
    const float* hp = hf + (((long long)k * 8 + b) * 1024 + n) * H_;
    float* opf = (k ? ln2f : ln1f) + row * H_;
    bf16* op16 = cat + row * (2 * H_) + k * H_;
    const float* g = k ? g2v : g1v;
    const float* bb = k ? b2v : b1v;
    int t = threadIdx.x;

    float x[3];
    float s = 0.0f;
    #pragma unroll
    for (int i = 0; i < 3; i++) {
        int c = t + i * 256;
        x[i] = np[c] + hp[c];
        s += x[i];
    }
    __shared__ float sm[32];
    s = blockReduceSum(s, sm);
    float mu = s * (1.0f / H_);
    float v = 0.0f;
    #pragma unroll
    for (int i = 0; i < 3; i++) {
        float d = x[i] - mu;
        v += d * d;
    }
    v = blockReduceSum(v, sm);
    float rs = rsqrtf(v * (1.0f / H_) + 1e-12f);
    #pragma unroll
    for (int i = 0; i < 3; i++) {
        int c = t + i * 256;
        float o = (x[i] - mu) * rs * g[c] + bb[c];
        opf[c] = o;
        op16[c] = __float2bfloat16_rn(o);
    }
}

// ---------------- launcher ---------------------------------------------------
extern "C" void kernel_launch(void* const* d_in, const int* in_sizes, int n_in,
                              void* d_out, int out_size)
{
    (void)in_sizes; (void)n_in; (void)out_size;
    const float* nodes   = (const float*)d_in[0];
    const float* graphs  = (const float*)d_in[1];
    const float* gcn1_w1 = (const float*)d_in[2];
    const float* gcn1_w2 = (const float*)d_in[3];
    const float* gcn2_w1 = (const float*)d_in[4];
    const float* gcn2_w2 = (const float*)d_in[5];
    const float* exp1_w  = (const float*)d_in[6];
    const float* exp1_b  = (const float*)d_in[7];
    const float* col1_w  = (const float*)d_in[8];
    const float* col1_b  = (const float*)d_in[9];
    const float* exp2_w  = (const float*)d_in[10];
    const float* exp2_b  = (const float*)d_in[11];
    const float* col2_w  = (const float*)d_in[12];
    const float* col2_b  = (const float*)d_in[13];
    const float* gate_w  = (const float*)d_in[14];
    const float* gate_b  = (const float*)d_in[15];
    const float* ln1_g   = (const float*)d_in[16];
    const float* ln1_b   = (const float*)d_in[17];
    const float* ln2_g   = (const float*)d_in[18];
    const float* ln2_b   = (const float*)d_in[19];
    float* out = (float*)d_out;

    bf16 *adj16, *nodes16, *wGate, *h16, *cat16;
    uint8_t *w1f8, *w2f8, *wef8, *wcf8, *act8, *big8;
    float *hf, *ln1f, *ln2f;
    cudaGetSymbolAddress((void**)&adj16,   g_adj16);
    cudaGetSymbolAddress((void**)&nodes16, g_nodes16);
    cudaGetSymbolAddress((void**)&wGate, g_wGate);
    cudaGetSymbolAddress((void**)&w1f8, g_w1f8);
    cudaGetSymbolAddress((void**)&w2f8, g_w2f8);
    cudaGetSymbolAddress((void**)&wef8, g_wef8);
    cudaGetSymbolAddress((void**)&wcf8, g_wcf8);
    cudaGetSymbolAddress((void**)&act8, g_act8);
    cudaGetSymbolAddress((void**)&big8, g_big8);
    cudaGetSymbolAddress((void**)&h16,   g_h16);
    cudaGetSymbolAddress((void**)&cat16, g_cat16);
    cudaGetSymbolAddress((void**)&hf,   g_hf);
    cudaGetSymbolAddress((void**)&ln1f, g_ln1f);
    cudaGetSymbolAddress((void**)&ln2f, g_ln2f);

    // streams/events created once; launch DAG is identical on every call
    static cudaStream_t sA = nullptr, sB = nullptr;
    static cudaEvent_t evRoot = nullptr, evA = nullptr, evB = nullptr;
    if (sA == nullptr) {
        cudaStreamCreateWithFlags(&sA, cudaStreamNonBlocking);
        cudaStreamCreateWithFlags(&sB, cudaStreamNonBlocking);
        cudaEventCreateWithFlags(&evRoot, cudaEventDisableTiming);
        cudaEventCreateWithFlags(&evA, cudaEventDisableTiming);
        cudaEventCreateWithFlags(&evB, cudaEventDisableTiming);
    }

    const int SMB128 = SMEM_BF_BYTES(128);
    const int SMB64  = SMEM_BF_BYTES(64);
    const int SMB8   = SMEM_F8_BYTES;
    cudaFuncSetAttribute(gemm_bf<EPI_NONE, 2, 128>, cudaFuncAttributeMaxDynamicSharedMemorySize, SMB128);
    cudaFuncSetAttribute(gemm_bf<EPI_RELU, 2, 128>, cudaFuncAttributeMaxDynamicSharedMemorySize, SMB128);
    cudaFuncSetAttribute(gemm_bf<EPI_GATE, 0, 64>,  cudaFuncAttributeMaxDynamicSharedMemorySize, SMB64);
    cudaFuncSetAttribute(gemm_f8<EPI_RELU, 2>, cudaFuncAttributeMaxDynamicSharedMemorySize, SMB8);
    cudaFuncSetAttribute(gemm_f8<EPI_NONE, 1>, cudaFuncAttributeMaxDynamicSharedMemorySize, SMB8);
    cudaFuncSetAttribute(gemm_f8<EPI_GELUB,2>, cudaFuncAttributeMaxDynamicSharedMemorySize, SMB8);
    cudaFuncSetAttribute(gemm_f8<EPI_BIAS, 0>, cudaFuncAttributeMaxDynamicSharedMemorySize, SMB8);

    const long long MN  = (long long)B_ * N_;     // 8192
    const long long sNH = (long long)N_ * H_;
    const long long sNI = (long long)N_ * I_;
    const long long IH  = (long long)I_ * H_;

    // ---- prologue (default stream) ----
    {
        long long n4 = MN * H_ / 4;
        f2bf_kernel<<<(unsigned)((n4 + 255) / 256), 256>>>(nodes, nodes16, n4);
    }
    {
        dim3 tb(32, 8);
        dim3 grid(2304, 1, 8);
        transpose_f8_all<<<grid, tb>>>(gcn1_w1, gcn2_w1, exp1_w, exp2_w,
                                       gcn1_w2, gcn2_w2, col1_w, col2_w);
    }
    combine_w_kernel<<<(H_ * H_ + 255) / 256, 256>>>(gate_w);
    rowsum_dinv_kernel<<<NMAT * N_ / 8, 256>>>(graphs);
    long long total4 = (long long)NMAT * NN / 4;
    normalize_adj_kernel<<<(unsigned)((total4 + 255) / 256), 256>>>(graphs);

    // ---- fork: two independent GCN/FFN chains on separate streams ----
    cudaEventRecord(evRoot, 0);
    cudaStreamWaitEvent(sA, evRoot, 0);
    cudaStreamWaitEvent(sB, evRoot, 0);

    for (int k = 0; k < 2; k++) {
        cudaStream_t st = k ? sB : sA;
        const long long ko = (long long)k * 8;
        bf16*   adjK  = adj16 + ko * NN;
        uint8_t* actK = act8 + ko * sNH;
        uint8_t* bigK = big8 + ko * sNI;
        bf16*   hK    = h16 + ko * sNH;
        float*  hfK   = hf + ko * sNH;
        const float* expb = k ? exp2_b : exp1_b;
        const float* colb = k ? col2_b : col1_b;

        // 1) adjX = adj @ nodes -> fp8*32
        gemm_bf<EPI_NONE, 2, 128><<<dim3(H_/128, N_/128, 8), 256, SMB128, st>>>(
            adjK, nodes16, actK, nullptr, nullptr, nullptr, S_ADJX,
            H_, N_, NN, sNH, sNH);
        // 2) x1 = relu(adjX @ W1) -> fp8*64
        gemm_f8<EPI_RELU, 2><<<dim3(I_/128, N_/128, 8), 256, SMB8, st>>>(
            actK, w1f8 + k * IH, bigK, nullptr, 1.0f/(S_ADJX*S_W), S_X1,
            I_, H_, sNH, sNI);
        // 3) t2p = x1 @ W2 -> bf16
        gemm_f8<EPI_NONE, 1><<<dim3(H_/128, N_/128, 8), 256, SMB8, st>>>(
            bigK, w2f8 + k * IH, hK, nullptr, 1.0f/(S_X1*S_W), 0.0f,
            H_, I_, sNI, sNH);
        // 4) gc = relu(adj @ t2p) -> fp8*256
        gemm_bf<EPI_RELU, 2, 128><<<dim3(H_/128, N_/128, 8), 256, SMB128, st>>>(
            adjK, hK, actK, nullptr, nullptr, nullptr, S_GC,
            H_, N_, NN, sNH, sNH);
        // 5) t3 = gelu(gc @ We + be) -> fp8*1024
        gemm_f8<EPI_GELUB, 2><<<dim3(I_/128, N_/128, 8), 256, SMB8, st>>>(
            actK, wef8 + k * IH, bigK, expb, 1.0f/(S_GC*S_W), S_T3,
            I_, H_, sNH, sNI);
        // 6) hf = t3 @ Wc + bc -> f32
        gemm_f8<EPI_BIAS, 0><<<dim3(H_/128, N_/128, 8), 256, SMB8, st>>>(
            bigK, wcf8 + k * IH, hfK, colb, 1.0f/(S_T3*S_W), 0.0f,
            H_, I_, sNI, sNH);
    }

    // ---- join ----
    cudaEventRecord(evA, sA);
    cudaEventRecord(evB, sB);
    cudaStreamWaitEvent(0, evA, 0);
    cudaStreamWaitEvent(0, evB, 0);

    // 7) both LayerNorms
    ln_kernel<<<dim3((unsigned)MN, 2), 256>>>(nodes, hf, ln1_g, ln1_b, ln2_g, ln2_b,
                                              ln1f, ln2f, cat16);

    // 8) fused gate (bf16, 64-row tiles): out = sigmoid(cat@Wg + gb) blend
    gemm_bf<EPI_GATE, 0, 64><<<dim3(H_/128, (unsigned)(MN/64), 1), 256, SMB64>>>(
        cat16, wGate, out, gate_b, ln1f, ln2f, 0.0f,
        H_, 2 * H_, 0, 0, 0);
}

// round 17
// speedup vs baseline: 8.5423x; 1.0049x over previous
#include <cuda_runtime.h>
#include <cuda_bf16.h>
#include <cuda_fp16.h>
#include <math.h>
#include <stdint.h>

// Problem dims
#define B_ 8
#define N_ 1024
#define H_ 768
#define I_ 3072
#define NMAT 16
#define NN (1024LL*1024LL)
#define HI_ ((long long)H_ * I_)

typedef __nv_bfloat16 bf16;

// ---------------- scratch (static device globals) ----------------------------
__device__ bf16  g_adj16[(size_t)NMAT * 1024 * 1024];   // [k][b][N][N]
__device__ float g_dinv[NMAT * N_];
__device__ bf16  g_nodes16[(size_t)B_ * N_ * H_];
// fp8 transposed weights [slot][N][K]
__device__ uint8_t g_w1f8[(size_t)2 * I_ * H_];
__device__ uint8_t g_w2f8[(size_t)2 * H_ * I_];
__device__ uint8_t g_wef8[(size_t)2 * I_ * H_];
__device__ uint8_t g_wcf8[(size_t)2 * H_ * I_];
__device__ bf16  g_wGate[2 * H_ * H_];
// activations, [k][b] slices
__device__ bf16  g_h16 [(size_t)NMAT * N_ * H_];
__device__ uint8_t g_act8[(size_t)NMAT * N_ * H_];
__device__ uint8_t g_big8[(size_t)NMAT * N_ * I_];
__device__ float g_hf  [(size_t)NMAT * N_ * H_];
__device__ bf16  g_cat16[(size_t)B_ * N_ * 2 * H_];
__device__ float g_ln1f[(size_t)B_ * N_ * H_];
__device__ float g_ln2f[(size_t)B_ * N_ * H_];

// fp8 scales (powers of two)
#define S_ADJX 32.0f
#define S_W    64.0f
#define S_X1   64.0f
#define S_GC   256.0f
#define S_T3   1024.0f

// ---------------- reductions ------------------------------------------------
__inline__ __device__ float warpReduceSum(float v) {
    #pragma unroll
    for (int o = 16; o > 0; o >>= 1) v += __shfl_xor_sync(0xFFFFFFFFu, v, o);
    return v;
}
__device__ float blockReduceSum(float v, float* sm) {
    __syncthreads();
    int lane = threadIdx.x & 31, w = threadIdx.x >> 5;
    v = warpReduceSum(v);
    if (lane == 0) sm[w] = v;
    __syncthreads();
    if (w == 0) {
        float t = (lane < 8) ? sm[lane] : 0.0f;
        t = warpReduceSum(t);
        if (lane == 0) sm[0] = t;
    }
    __syncthreads();
    return sm[0];
}

// ---------------- fp8 pack helper --------------------------------------------
__device__ __forceinline__ uint16_t pack_e4m3x2(float lo, float hi) {
    uint16_t p;
    asm("cvt.rn.satfinite.e4m3x2.f32 %0, %1, %2;" : "=h"(p) : "f"(hi), "f"(lo));
    return p;
}

// ---------------- prologue kernels -------------------------------------------
__global__ void f2bf_kernel(const float* __restrict__ in, bf16* __restrict__ out, long long n4) {
    long long i = (long long)blockIdx.x * blockDim.x + threadIdx.x;
    if (i >= n4) return;
    float4 v = *(const float4*)(in + i * 4);
    bf16 o[4];
    o[0] = __float2bfloat16_rn(v.x); o[1] = __float2bfloat16_rn(v.y);
    o[2] = __float2bfloat16_rn(v.z); o[3] = __float2bfloat16_rn(v.w);
    *(uint2*)(out + i * 4) = *(uint2*)o;
}

// ALL 8 weight transposes in one launch (blockIdx.z selects matrix).
__global__ void transpose_f8_all(
    const float* __restrict__ s0, const float* __restrict__ s1,
    const float* __restrict__ s2, const float* __restrict__ s3,
    const float* __restrict__ s4, const float* __restrict__ s5,
    const float* __restrict__ s6, const float* __restrict__ s7)
{
    __shared__ float tile[32][33];
    const int zi = blockIdx.z;
    const float* srcs[8] = {s0, s1, s2, s3, s4, s5, s6, s7};
    uint8_t* dsts[8] = {g_w1f8, g_w1f8 + HI_, g_wef8, g_wef8 + HI_,
                        g_w2f8, g_w2f8 + HI_, g_wcf8, g_wcf8 + HI_};
    const float* in = srcs[zi];
    uint8_t* out = dsts[zi];
    const int R = (zi < 4) ? H_ : I_;
    const int C = (zi < 4) ? I_ : H_;
    const int tilesX = C / 32;
    int bid = blockIdx.x;
    int bx = (bid % tilesX) * 32, by = (bid / tilesX) * 32;
    int x = threadIdx.x, y = threadIdx.y;
    #pragma unroll
    for (int j = 0; j < 32; j += 8)
        tile[y + j][x] = in[(long long)(by + y + j) * C + bx + x];
    __syncthreads();
    #pragma unroll
    for (int j = 0; j < 32; j += 8) {
        uint16_t p = pack_e4m3x2(tile[x][y + j] * S_W, 0.0f);
        out[(long long)(bx + y + j) * R + by + x] = (uint8_t)(p & 0xFF);
    }
}

// rowsum for HALF the matrices (graph index kSel). Input m = b*2 + kSel.
__global__ void rowsum_dinv_k(const float* __restrict__ A, int kSel) {
    int w = threadIdx.x >> 5, lane = threadIdx.x & 31;
    long long rowLocal = (long long)blockIdx.x * 8 + w;   // 0 .. 8191
    long long b = rowLocal >> 10;
    long long r = rowLocal & 1023;
    long long m = b * 2 + kSel;
    const float* p = A + (m * N_ + r) * (long long)N_;
    float s = 0.0f;
    #pragma unroll
    for (int i = 0; i < 8; i++) {
        float4 v = *(const float4*)(p + (lane + i * 32) * 4);
        s += v.x + v.y + v.z + v.w;
    }
    s = warpReduceSum(s);
    if (lane == 0) g_dinv[m * N_ + r] = 1.0f / sqrtf(s);
}

// normalize for HALF the matrices. Reads [b][k], writes [k][b].
__global__ void normalize_adj_k(const float* __restrict__ A, int kSel) {
    long long i4 = (long long)blockIdx.x * blockDim.x + threadIdx.x;
    long long total4 = 8 * NN / 4;
    if (i4 >= total4) return;
    long long eL = i4 * 4;
    int  b = (int)(eL / NN);
    long long rem = eL % NN;
    int  r = (int)(rem / N_);
    int  c = (int)(rem % N_);
    int  m = b * 2 + kSel;
    float di = g_dinv[m * N_ + r];
    const float* dj = &g_dinv[m * N_ + c];
    float4 v = *(const float4*)(A + m * NN + rem);
    bf16 o[4];
    o[0] = __float2bfloat16_rn(v.x * di * dj[0]);
    o[1] = __float2bfloat16_rn(v.y * di * dj[1]);
    o[2] = __float2bfloat16_rn(v.z * di * dj[2]);
    o[3] = __float2bfloat16_rn(v.w * di * dj[3]);
    *(uint2*)(g_adj16 + ((long long)kSel * 8 + b) * NN + rem) = *(uint2*)o;
}

// folded gate weight, k-major [1536][768] bf16
__global__ void combine_w_kernel(const float* __restrict__ gw) {
    int i = blockIdx.x * blockDim.x + threadIdx.x;
    if (i >= H_ * H_) return;
    int r = i / H_, c = i % H_;
    float w0 = gw[i];
    float w1 = gw[(H_     + r) * H_ + c];
    float w2 = gw[(2 * H_ + r) * H_ + c];
    float w3 = gw[(3 * H_ + r) * H_ + c];
    g_wGate[r * H_ + c]        = __float2bfloat16_rn(w0 + w2 + w3);
    g_wGate[(H_ + r) * H_ + c] = __float2bfloat16_rn(w1 + w2 - w3);
}

// ---------------- epilogue codes ---------------------------------------------
#define EPI_NONE  0
#define EPI_RELU  1
#define EPI_BIAS  2
#define EPI_GELUB 3
#define EPI_GATE  5
// OUTM: 0=f32, 1=bf16, 2=fp8*outscale

__device__ __forceinline__ void cp16(uint32_t sdst, const void* gsrc) {
    asm volatile("cp.async.cg.shared.global [%0], [%1], 16;\n" :: "r"(sdst), "l"(gsrc));
}

__device__ __forceinline__ void mma_bf16(float c[4], const uint32_t a[4],
                                         uint32_t b0, uint32_t b1) {
    asm volatile(
        "mma.sync.aligned.m16n8k16.row.col.f32.bf16.bf16.f32 "
        "{%0,%1,%2,%3}, {%4,%5,%6,%7}, {%8,%9}, {%0,%1,%2,%3};\n"
        : "+f"(c[0]), "+f"(c[1]), "+f"(c[2]), "+f"(c[3])
        : "r"(a[0]), "r"(a[1]), "r"(a[2]), "r"(a[3]), "r"(b0), "r"(b1));
}

__device__ __forceinline__ void mma_f8_h(uint32_t c[2], const uint32_t a[4],
                                         uint32_t b0, uint32_t b1) {
    asm volatile(
        "mma.sync.aligned.m16n8k32.row.col.f16.e4m3.e4m3.f16 "
        "{%0,%1}, {%2,%3,%4,%5}, {%6,%7}, {%0,%1};\n"
        : "+r"(c[0]), "+r"(c[1])
        : "r"(a[0]), "r"(a[1]), "r"(a[2]), "r"(a[3]), "r"(b0), "r"(b1));
}

// ---------------- bf16 GEMM, MT-row tiles (adj steps + gate) -------------------
#define SMEM_BF_BYTES(MT) ((4 * ((MT) * 40 + 32 * 136)) * 2)

template<int EPI, int OUTM, int MT>
__global__ __launch_bounds__(256, 2) void gemm_bf(
    const bf16* __restrict__ A, const bf16* __restrict__ Bm,
    void* __restrict__ Cv,
    const float* __restrict__ bias,
    const float* __restrict__ e1, const float* __restrict__ e2,
    float outscale,
    int N, int K,
    long long sA1, long long sB1, long long sC1)
{
    extern __shared__ __align__(16) bf16 smn[];
    const uint32_t sbase = (uint32_t)__cvta_generic_to_shared(smn);
    constexpr int AS = MT * 40;
    constexpr int BBASE = 4 * AS;
    constexpr int MI = MT / 32;

    const long long z = blockIdx.z;
    A  += z * sA1;
    Bm += z * sB1;
    const long long cOff = z * sC1;

    const int tid  = threadIdx.x;
    const int w    = tid >> 5;
    const int lane = tid & 31;
    const int wm   = w & 1;
    const int wn   = w >> 1;
    const int g    = lane >> 2;
    const int tg   = lane & 3;

    const int aRow  = (MT == 128) ? (tid >> 1) : (tid >> 2);
    const int aKoff = (MT == 128) ? (tid & 1) * 16 : (tid & 3) * 8;
    const int bRow  = tid >> 3;
    const int bNoff = (tid & 7) * 16;

    const bf16* Ag = A  + ((long long)blockIdx.y * MT + aRow) * K + aKoff;
    const bf16* Bg = Bm + (long long)bRow * N + blockIdx.x * 128 + bNoff;

    float c[MI][4][4];
    #pragma unroll
    for (int mi = 0; mi < MI; mi++)
        #pragma unroll
        for (int ni = 0; ni < 4; ni++)
            #pragma unroll
            for (int u = 0; u < 4; u++) c[mi][ni][u] = 0.0f;

    const int S = K / 32;
    const int lm_r = lane & 15;
    const int lm_c = (lane >> 4) * 8;

    auto stage = [&](int chunk, int st) {
        const bf16* Ap = Ag + chunk * 32;
        const bf16* Bp = Bg + (long long)chunk * 32 * N;
        uint32_t asb = sbase + (st * AS + aRow * 40 + aKoff) * 2;
        uint32_t bsb = sbase + (BBASE + st * 4352 + bRow * 136 + bNoff) * 2;
        cp16(asb, Ap);
        if (MT == 128) cp16(asb + 16, Ap + 8);
        cp16(bsb, Bp);
        cp16(bsb + 16, Bp + 8);
        asm volatile("cp.async.commit_group;\n");
    };

    stage(0, 0);
    stage(1, 1);
    stage(2, 2);

    for (int s = 0; s < S; s++) {
        if (s <= S - 3)      asm volatile("cp.async.wait_group 2;\n");
        else if (s == S - 2) asm volatile("cp.async.wait_group 1;\n");
        else                 asm volatile("cp.async.wait_group 0;\n");
        __syncthreads();
        if (s + 3 < S) stage(s + 3, (s + 3) & 3);

        const int buf = s & 3;
        const uint32_t asBase = sbase + (buf * AS) * 2;
        const uint32_t bsBase = sbase + (BBASE + buf * 4352) * 2;

        #pragma unroll
        for (int kk = 0; kk < 2; kk++) {
            uint32_t a[MI][4];
            uint32_t b[2][4];
            #pragma unroll
            for (int mi = 0; mi < MI; mi++) {
                uint32_t addr = asBase +
                    ((wm * (MT / 2) + mi * 16 + lm_r) * 40 + kk * 16 + lm_c) * 2;
                asm volatile(
                    "ldmatrix.sync.aligned.m8n8.x4.shared.b16 {%0,%1,%2,%3}, [%4];"
                    : "=r"(a[mi][0]), "=r"(a[mi][1]), "=r"(a[mi][2]), "=r"(a[mi][3])
                    : "r"(addr));
            }
            #pragma unroll
            for (int nb = 0; nb < 2; nb++) {
                uint32_t addr = bsBase +
                    ((kk * 16 + lm_r) * 136 + wn * 32 + nb * 16 + lm_c) * 2;
                asm volatile(
                    "ldmatrix.sync.aligned.m8n8.x4.trans.shared.b16 {%0,%1,%2,%3}, [%4];"
                    : "=r"(b[nb][0]), "=r"(b[nb][1]), "=r"(b[nb][2]), "=r"(b[nb][3])
                    : "r"(addr));
            }
            #pragma unroll
            for (int mi = 0; mi < MI; mi++)
                #pragma unroll
                for (int ni = 0; ni < 4; ni++)
                    mma_bf16(c[mi][ni], a[mi],
                             b[ni >> 1][(ni & 1) * 2], b[ni >> 1][(ni & 1) * 2 + 1]);
        }
    }

    #pragma unroll
    for (int mi = 0; mi < MI; mi++) {
        #pragma unroll
        for (int ni = 0; ni < 4; ni++) {
            const int row0 = blockIdx.y * MT + wm * (MT / 2) + mi * 16 + g;
            const int col  = blockIdx.x * 128 + wn * 32 + ni * 8 + 2 * tg;
            float v[4];
            v[0] = c[mi][ni][0]; v[1] = c[mi][ni][1];
            v[2] = c[mi][ni][2]; v[3] = c[mi][ni][3];

            if (EPI == EPI_BIAS || EPI == EPI_GELUB || EPI == EPI_GATE) {
                float b0 = bias[col], b1 = bias[col + 1];
                v[0] += b0; v[1] += b1; v[2] += b0; v[3] += b1;
            }
            if (EPI == EPI_RELU) {
                #pragma unroll
                for (int u = 0; u < 4; u++) v[u] = fmaxf(v[u], 0.0f);
            }
            if (EPI == EPI_GELUB) {
                #pragma unroll
                for (int u = 0; u < 4; u++)
                    v[u] = 0.5f * v[u] * (1.0f + erff(v[u] * 0.70710678118654752f));
            }
            if (EPI == EPI_GATE) {
                long long i0 = (long long)row0 * N + col;
                long long i1 = (long long)(row0 + 8) * N + col;
                float2 p0 = *(const float2*)(e1 + i0);
                float2 p1 = *(const float2*)(e1 + i1);
                float2 q0 = *(const float2*)(e2 + i0);
                float2 q1 = *(const float2*)(e2 + i1);
                float gt;
                gt = 1.0f / (1.0f + expf(-v[0])); v[0] = gt * p0.x + (1.0f - gt) * q0.x;
                gt = 1.0f / (1.0f + expf(-v[1])); v[1] = gt * p0.y + (1.0f - gt) * q0.y;
                gt = 1.0f / (1.0f + expf(-v[2])); v[2] = gt * p1.x + (1.0f - gt) * q1.x;
                gt = 1.0f / (1.0f + expf(-v[3])); v[3] = gt * p1.y + (1.0f - gt) * q1.y;
            }

            if (OUTM == 1) {
                bf16* C = (bf16*)Cv + cOff;
                bf16* C0 = C + (long long)row0 * N + col;
                bf16* C1 = C + (long long)(row0 + 8) * N + col;
                bf16 p0[2] = {__float2bfloat16_rn(v[0]), __float2bfloat16_rn(v[1])};
                bf16 p1[2] = {__float2bfloat16_rn(v[2]), __float2bfloat16_rn(v[3])};
                *(uint32_t*)C0 = *(uint32_t*)p0;
                *(uint32_t*)C1 = *(uint32_t*)p1;
            } else if (OUTM == 2) {
                uint8_t* C = (uint8_t*)Cv + cOff;
                *(uint16_t*)(C + (long long)row0 * N + col) =
                    pack_e4m3x2(v[0] * outscale, v[1] * outscale);
                *(uint16_t*)(C + (long long)(row0 + 8) * N + col) =
                    pack_e4m3x2(v[2] * outscale, v[3] * outscale);
            } else {
                float* C = (float*)Cv + cOff;
                float* C0 = C + (long long)row0 * N + col;
                float* C1 = C + (long long)(row0 + 8) * N + col;
                *(float2*)C0 = make_float2(v[0], v[1]);
                *(float2*)C1 = make_float2(v[2], v[3]);
            }
        }
    }
}

// ---------------- fp8 GEMM with f16 accumulators ------------------------------
#define SMEM_F8_BYTES (8 * 128 * 80)   // 81920

template<int EPI, int OUTM>
__global__ __launch_bounds__(256, 2) void gemm_f8(
    const uint8_t* __restrict__ A, const uint8_t* __restrict__ BT,
    void* __restrict__ Cv,
    const float* __restrict__ bias,
    float unscale, float outscale,
    int N, int K,
    long long sA1, long long sC1)
{
    extern __shared__ __align__(16) uint8_t sm8[];
    const uint32_t sbase = (uint32_t)__cvta_generic_to_shared(sm8);

    const long long z = blockIdx.z;
    A += z * sA1;
    const long long cOff = z * sC1;

    const int tid  = threadIdx.x;
    const int w    = tid >> 5;
    const int lane = tid & 31;
    const int wm   = w & 1;
    const int wn   = w >> 1;
    const int g    = lane >> 2;
    const int tg   = lane & 3;

    const int ldRow = tid >> 1;
    const int ldOff = (tid & 1) * 32;
    const uint8_t* Ag = A  + ((long long)blockIdx.y * 128 + ldRow) * K + ldOff;
    const uint8_t* Bg = BT + ((long long)blockIdx.x * 128 + ldRow) * K + ldOff;

    uint32_t c2[4][4][2];
    #pragma unroll
    for (int mi = 0; mi < 4; mi++)
        #pragma unroll
        for (int ni = 0; ni < 4; ni++) { c2[mi][ni][0] = 0u; c2[mi][ni][1] = 0u; }

    const int S = K / 64;
    const int a_r = lane & 15;
    const int a_h = (lane >> 4) * 16;
    const int b_r = (lane & 7) + ((lane >> 4) << 3);
    const int b_h = ((lane >> 3) & 1) * 16;

    auto stage = [&](int chunk, int st) {
        const uint8_t* Ap = Ag + chunk * 64;
        const uint8_t* Bp = Bg + chunk * 64;
        uint32_t asb = sbase + st * 10240 + ldRow * 80 + ldOff;
        uint32_t bsb = sbase + 40960 + st * 10240 + ldRow * 80 + ldOff;
        cp16(asb, Ap);
        cp16(asb + 16, Ap + 16);
        cp16(bsb, Bp);
        cp16(bsb + 16, Bp + 16);
        asm volatile("cp.async.commit_group;\n");
    };

    stage(0, 0);
    stage(1, 1);
    stage(2, 2);

    for (int s = 0; s < S; s++) {
        if (s <= S - 3)      asm volatile("cp.async.wait_group 2;\n");
        else if (s == S - 2) asm volatile("cp.async.wait_group 1;\n");
        else                 asm volatile("cp.async.wait_group 0;\n");
        __syncthreads();
        if (s + 3 < S) stage(s + 3, (s + 3) & 3);

        const int buf = s & 3;
        const uint32_t asBase = sbase + buf * 10240;
        const uint32_t bsBase = sbase + 40960 + buf * 10240;

        #pragma unroll
        for (int kb = 0; kb < 64; kb += 32) {
            uint32_t a[4][4];
            uint32_t b[2][4];
            #pragma unroll
            for (int mi = 0; mi < 4; mi++) {
                uint32_t addr = asBase + (wm * 64 + mi * 16 + a_r) * 80 + kb + a_h;
                asm volatile(
                    "ldmatrix.sync.aligned.m8n8.x4.shared.b16 {%0,%1,%2,%3}, [%4];"
                    : "=r"(a[mi][0]), "=r"(a[mi][1]), "=r"(a[mi][2]), "=r"(a[mi][3])
                    : "r"(addr));
            }
            #pragma unroll
            for (int nb = 0; nb < 2; nb++) {
                uint32_t addr = bsBase + (wn * 32 + nb * 16 + b_r) * 80 + kb + b_h;
                asm volatile(
                    "ldmatrix.sync.aligned.m8n8.x4.shared.b16 {%0,%1,%2,%3}, [%4];"
                    : "=r"(b[nb][0]), "=r"(b[nb][1]), "=r"(b[nb][2]), "=r"(b[nb][3])
                    : "r"(addr));
            }
            #pragma unroll
            for (int mi = 0; mi < 4; mi++)
                #pragma unroll
                for (int ni = 0; ni < 4; ni++)
                    mma_f8_h(c2[mi][ni], a[mi],
                             b[ni >> 1][(ni & 1) * 2], b[ni >> 1][(ni & 1) * 2 + 1]);
        }
    }

    #pragma unroll
    for (int mi = 0; mi < 4; mi++) {
        #pragma unroll
        for (int ni = 0; ni < 4; ni++) {
            const int row0 = blockIdx.y * 128 + wm * 64 + mi * 16 + g;
            const int col  = blockIdx.x * 128 + wn * 32 + ni * 8 + 2 * tg;
            float2 f01 = __half22float2(*(__half2*)&c2[mi][ni][0]);
            float2 f23 = __half22float2(*(__half2*)&c2[mi][ni][1]);
            float v[4];
            v[0] = f01.x * unscale; v[1] = f01.y * unscale;
            v[2] = f23.x * unscale; v[3] = f23.y * unscale;

            if (EPI == EPI_BIAS || EPI == EPI_GELUB) {
                float b0 = bias[col], b1 = bias[col + 1];
                v[0] += b0; v[1] += b1; v[2] += b0; v[3] += b1;
            }
            if (EPI == EPI_RELU) {
                #pragma unroll
                for (int u = 0; u < 4; u++) v[u] = fmaxf(v[u], 0.0f);
            }
            if (EPI == EPI_GELUB) {
                #pragma unroll
                for (int u = 0; u < 4; u++)
                    v[u] = 0.5f * v[u] * (1.0f + erff(v[u] * 0.70710678118654752f));
            }

            if (OUTM == 1) {
                bf16* C = (bf16*)Cv + cOff;
                bf16* C0 = C + (long long)row0 * N + col;
                bf16* C1 = C + (long long)(row0 + 8) * N + col;
                bf16 p0[2] = {__float2bfloat16_rn(v[0]), __float2bfloat16_rn(v[1])};
                bf16 p1[2] = {__float2bfloat16_rn(v[2]), __float2bfloat16_rn(v[3])};
                *(uint32_t*)C0 = *(uint32_t*)p0;
                *(uint32_t*)C1 = *(uint32_t*)p1;
            } else if (OUTM == 2) {
                uint8_t* C = (uint8_t*)Cv + cOff;
                *(uint16_t*)(C + (long long)row0 * N + col) =
                    pack_e4m3x2(v[0] * outscale, v[1] * outscale);
                *(uint16_t*)(C + (long long)(row0 + 8) * N + col) =
                    pack_e4m3x2(v[2] * outscale, v[3] * outscale);
            } else {
                float* C = (float*)Cv + cOff;
                float* C0 = C + (long long)row0 * N + col;
                float* C1 = C + (long long)(row0 + 8) * N + col;
                *(float2*)C0 = make_float2(v[0], v[1]);
                *(float2*)C1 = make_float2(v[2], v[3]);
            }
        }
    }
}

// ---------------- merged layernorm: y=0 -> LN1, y=1 -> LN2 --------------------
__global__ void ln_kernel(const float* __restrict__ nodes, const float* __restrict__ hf,
                          const float* __restrict__ g1v, const float* __restrict__ b1v,
                          const float* __restrict__ g2v, const float* __restrict__ b2v,
                          float* __restrict__ ln1f, float* __restrict__ ln2f,
                          bf16* __restrict__ cat)
{
    const int k = blockIdx.y;
    long long row = blockIdx.x;
    long long b = row >> 10;
    int n = (int)(row & 1023);
    const float* np = nodes + row * H_;
    const float* hp = hf + (((long long)k * 8 + b) * 1024 + n) * H_;
    float* opf = (k ? ln2f : ln1f) + row * H_;
    bf16* op16 = cat + row * (2 * H_) + k * H_;
    const float* g = k ? g2v : g1v;
    const float* bb = k ? b2v : b1v;
    int t = threadIdx.x;

    float x[3];
    float s = 0.0f;
    #pragma unroll
    for (int i = 0; i < 3; i++) {
        int c = t + i * 256;
        x[i] = np[c] + hp[c];
        s += x[i];
    }
    __shared__ float sm[32];
    s = blockReduceSum(s, sm);
    float mu = s * (1.0f / H_);
    float v = 0.0f;
    #pragma unroll
    for (int i = 0; i < 3; i++) {
        float d = x[i] - mu;
        v += d * d;
    }
    v = blockReduceSum(v, sm);
    float rs = rsqrtf(v * (1.0f / H_) + 1e-12f);
    #pragma unroll
    for (int i = 0; i < 3; i++) {
        int c = t + i * 256;
        float o = (x[i] - mu) * rs * g[c] + bb[c];
        opf[c] = o;
        op16[c] = __float2bfloat16_rn(o);
    }
}

// ---------------- launcher ---------------------------------------------------
extern "C" void kernel_launch(void* const* d_in, const int* in_sizes, int n_in,
                              void* d_out, int out_size)
{
    (void)in_sizes; (void)n_in; (void)out_size;
    const float* nodes   = (const float*)d_in[0];
    const float* graphs  = (const float*)d_in[1];
    const float* gcn1_w1 = (const float*)d_in[2];
    const float* gcn1_w2 = (const float*)d_in[3];
    const float* gcn2_w1 = (const float*)d_in[4];
    const float* gcn2_w2 = (const float*)d_in[5];
    const float* exp1_w  = (const float*)d_in[6];
    const float* exp1_b  = (const float*)d_in[7];
    const float* col1_w  = (const float*)d_in[8];
    const float* col1_b  = (const float*)d_in[9];
    const float* exp2_w  = (const float*)d_in[10];
    const float* exp2_b  = (const float*)d_in[11];
    const float* col2_w  = (const float*)d_in[12];
    const float* col2_b  = (const float*)d_in[13];
    const float* gate_w  = (const float*)d_in[14];
    const float* gate_b  = (const float*)d_in[15];
    const float* ln1_g   = (const float*)d_in[16];
    const float* ln1_b   = (const float*)d_in[17];
    const float* ln2_g   = (const float*)d_in[18];
    const float* ln2_b   = (const float*)d_in[19];
    float* out = (float*)d_out;

    bf16 *adj16, *nodes16, *wGate, *h16, *cat16;
    uint8_t *w1f8, *w2f8, *wef8, *wcf8, *act8, *big8;
    float *hf, *ln1f, *ln2f;
    cudaGetSymbolAddress((void**)&adj16,   g_adj16);
    cudaGetSymbolAddress((void**)&nodes16, g_nodes16);
    cudaGetSymbolAddress((void**)&wGate, g_wGate);
    cudaGetSymbolAddress((void**)&w1f8, g_w1f8);
    cudaGetSymbolAddress((void**)&w2f8, g_w2f8);
    cudaGetSymbolAddress((void**)&wef8, g_wef8);
    cudaGetSymbolAddress((void**)&wcf8, g_wcf8);
    cudaGetSymbolAddress((void**)&act8, g_act8);
    cudaGetSymbolAddress((void**)&big8, g_big8);
    cudaGetSymbolAddress((void**)&h16,   g_h16);
    cudaGetSymbolAddress((void**)&cat16, g_cat16);
    cudaGetSymbolAddress((void**)&hf,   g_hf);
    cudaGetSymbolAddress((void**)&ln1f, g_ln1f);
    cudaGetSymbolAddress((void**)&ln2f, g_ln2f);

    // streams/events created once; launch DAG identical every call
    static cudaStream_t sA = nullptr, sB = nullptr;
    static cudaEvent_t evRoot = nullptr, evF = nullptr, evT = nullptr,
                       evN0 = nullptr, evA = nullptr, evB = nullptr;
    if (sA == nullptr) {
        cudaStreamCreateWithFlags(&sA, cudaStreamNonBlocking);
        cudaStreamCreateWithFlags(&sB, cudaStreamNonBlocking);
        cudaEventCreateWithFlags(&evRoot, cudaEventDisableTiming);
        cudaEventCreateWithFlags(&evF,  cudaEventDisableTiming);
        cudaEventCreateWithFlags(&evT,  cudaEventDisableTiming);
        cudaEventCreateWithFlags(&evN0, cudaEventDisableTiming);
        cudaEventCreateWithFlags(&evA,  cudaEventDisableTiming);
        cudaEventCreateWithFlags(&evB,  cudaEventDisableTiming);
    }

    const int SMB128 = SMEM_BF_BYTES(128);
    const int SMB64  = SMEM_BF_BYTES(64);
    const int SMB8   = SMEM_F8_BYTES;
    cudaFuncSetAttribute(gemm_bf<EPI_NONE, 2, 128>, cudaFuncAttributeMaxDynamicSharedMemorySize, SMB128);
    cudaFuncSetAttribute(gemm_bf<EPI_RELU, 2, 128>, cudaFuncAttributeMaxDynamicSharedMemorySize, SMB128);
    cudaFuncSetAttribute(gemm_bf<EPI_GATE, 0, 64>,  cudaFuncAttributeMaxDynamicSharedMemorySize, SMB64);
    cudaFuncSetAttribute(gemm_f8<EPI_RELU, 2>, cudaFuncAttributeMaxDynamicSharedMemorySize, SMB8);
    cudaFuncSetAttribute(gemm_f8<EPI_NONE, 1>, cudaFuncAttributeMaxDynamicSharedMemorySize, SMB8);
    cudaFuncSetAttribute(gemm_f8<EPI_GELUB,2>, cudaFuncAttributeMaxDynamicSharedMemorySize, SMB8);
    cudaFuncSetAttribute(gemm_f8<EPI_BIAS, 0>, cudaFuncAttributeMaxDynamicSharedMemorySize, SMB8);

    const long long MN  = (long long)B_ * N_;     // 8192
    const long long sNH = (long long)N_ * H_;
    const long long sNI = (long long)N_ * I_;
    const long long IH  = (long long)I_ * H_;

    // ==== fork side streams FIRST (capture-legal: event from captured stream) ====
    cudaEventRecord(evRoot, 0);
    cudaStreamWaitEvent(sB, evRoot, 0);

    // ==== parallel prologue ====
    // stream 0: nodes conversion + k=0 adjacency path (feeds chain A)
    {
        long long n4 = MN * H_ / 4;
        f2bf_kernel<<<(unsigned)((n4 + 255) / 256), 256>>>(nodes, nodes16, n4);
    }
    cudaEventRecord(evF, 0);                 // nodes16 ready
    rowsum_dinv_k<<<1024, 256>>>(graphs, 0);
    {
        long long t4 = 8 * NN / 4;
        normalize_adj_k<<<(unsigned)((t4 + 255) / 256), 256>>>(graphs, 0);
    }
    cudaEventRecord(evN0, 0);                // adj k=0 ready

    // stream B (forked above): weights, then k=1 adjacency, then chain B
    {
        dim3 tb(32, 8);
        dim3 grid(2304, 1, 8);
        transpose_f8_all<<<grid, tb, 0, sB>>>(gcn1_w1, gcn2_w1, exp1_w, exp2_w,
                                              gcn1_w2, gcn2_w2, col1_w, col2_w);
    }
    combine_w_kernel<<<(H_ * H_ + 255) / 256, 256, 0, sB>>>(gate_w);
    cudaEventRecord(evT, sB);                // weights ready
    rowsum_dinv_k<<<1024, 256, 0, sB>>>(graphs, 1);
    {
        long long t4 = 8 * NN / 4;
        normalize_adj_k<<<(unsigned)((t4 + 255) / 256), 256, 0, sB>>>(graphs, 1);
    }
    cudaStreamWaitEvent(sB, evF, 0);         // chain B needs nodes16

    // stream A forks by waiting on k=0 adjacency (event from captured stream 0)
    cudaStreamWaitEvent(sA, evN0, 0);

    for (int k = 0; k < 2; k++) {
        cudaStream_t st = k ? sB : sA;
        const long long ko = (long long)k * 8;
        bf16*   adjK  = adj16 + ko * NN;
        uint8_t* actK = act8 + ko * sNH;
        uint8_t* bigK = big8 + ko * sNI;
        bf16*   hK    = h16 + ko * sNH;
        float*  hfK   = hf + ko * sNH;
        const float* expb = k ? exp2_b : exp1_b;
        const float* colb = k ? col2_b : col1_b;

        // 1) adjX = adj @ nodes -> fp8*32   (no weights needed)
        gemm_bf<EPI_NONE, 2, 128><<<dim3(H_/128, N_/128, 8), 256, SMB128, st>>>(
            adjK, nodes16, actK, nullptr, nullptr, nullptr, S_ADJX,
            H_, N_, NN, sNH, sNH);
        if (k == 0) cudaStreamWaitEvent(st, evT, 0);   // weights from sB
        // 2) x1 = relu(adjX @ W1) -> fp8*64
        gemm_f8<EPI_RELU, 2><<<dim3(I_/128, N_/128, 8), 256, SMB8, st>>>(
            actK, w1f8 + k * IH, bigK, nullptr, 1.0f/(S_ADJX*S_W), S_X1,
            I_, H_, sNH, sNI);
        // 3) t2p = x1 @ W2 -> bf16
        gemm_f8<EPI_NONE, 1><<<dim3(H_/128, N_/128, 8), 256, SMB8, st>>>(
            bigK, w2f8 + k * IH, hK, nullptr, 1.0f/(S_X1*S_W), 0.0f,
            H_, I_, sNI, sNH);
        // 4) gc = relu(adj @ t2p) -> fp8*256
        gemm_bf<EPI_RELU, 2, 128><<<dim3(H_/128, N_/128, 8), 256, SMB128, st>>>(
            adjK, hK, actK, nullptr, nullptr, nullptr, S_GC,
            H_, N_, NN, sNH, sNH);
        // 5) t3 = gelu(gc @ We + be) -> fp8*1024
        gemm_f8<EPI_GELUB, 2><<<dim3(I_/128, N_/128, 8), 256, SMB8, st>>>(
            actK, wef8 + k * IH, bigK, expb, 1.0f/(S_GC*S_W), S_T3,
            I_, H_, sNH, sNI);
        // 6) hf = t3 @ Wc + bc -> f32
        gemm_f8<EPI_BIAS, 0><<<dim3(H_/128, N_/128, 8), 256, SMB8, st>>>(
            bigK, wcf8 + k * IH, hfK, colb, 1.0f/(S_T3*S_W), 0.0f,
            H_, I_, sNI, sNH);
    }

    // ---- join ----
    cudaEventRecord(evA, sA);
    cudaEventRecord(evB, sB);
    cudaStreamWaitEvent(0, evA, 0);
    cudaStreamWaitEvent(0, evB, 0);

    // 7) both LayerNorms
    ln_kernel<<<dim3((unsigned)MN, 2), 256>>>(nodes, hf, ln1_g, ln1_b, ln2_g, ln2_b,
                                              ln1f, ln2f, cat16);

    // 8) fused gate (bf16, 64-row tiles): out = sigmoid(cat@Wg + gb) blend
    gemm_bf<EPI_GATE, 0, 64><<<dim3(H_/128, (unsigned)(MN/64), 1), 256, SMB64>>>(
        cat16, wGate, out, gate_b, ln1f, ln2f, 0.0f,
        H_, 2 * H_, 0, 0, 0);
}